// round 2
// baseline (speedup 1.0000x reference)
#include <cuda_runtime.h>

// Problem constants (fixed instance): B=2, T=4096, D=1024, H=16, hd=64, WIN=512, BS=64
#define DIM   1024
#define HD    64
#define NHEAD 16
#define TLEN  4096
#define BATCH 2
#define MTOT  (BATCH * TLEN)      // 8192 rows
#define NBLK  (TLEN / 64)         // 64 query blocks per (b,h)
#define SCALE 0.125f              // 1/sqrt(64)

// Scratch (device globals: allocation-free rule)
__device__ float g_q[MTOT * DIM];
__device__ float g_k[MTOT * DIM];
__device__ float g_v[MTOT * DIM];
__device__ float g_a[MTOT * DIM];

// ---------------------------------------------------------------------------
// GEMM: C[M,N] = A[M,K] @ W[N,K]^T   with M=8192, N=1024, K=1024 (all fp32)
// Tiles: 128x128, BK=16, 256 threads, 8x8 per-thread microtile.
// Double-buffered smem, k-major layout for conflict-light float4 reads.
// ---------------------------------------------------------------------------
__global__ __launch_bounds__(256) void gemm_nt_kernel(
    const float* __restrict__ A, const float* __restrict__ W, float* __restrict__ C)
{
    __shared__ float As[2][16][128];   // [buf][k][m]
    __shared__ float Ws[2][16][128];   // [buf][k][n]

    const int tid = threadIdx.x;
    const int ty = tid >> 4;        // 0..15 -> rows 8*ty..8*ty+7
    const int tx = tid & 15;        // 0..15 -> cols 8*tx..8*tx+7
    const int bm = blockIdx.y * 128;
    const int bn = blockIdx.x * 128;

    // Load task decomposition (same for A and W): 128 rows x 16 k = 512 float4
    const int m0  = tid >> 2;             // task tid
    const int m1  = (tid + 256) >> 2;     // task tid+256
    const int kq  = (tid & 3) * 4;

    float acc[8][8];
#pragma unroll
    for (int a = 0; a < 8; a++)
#pragma unroll
        for (int b = 0; b < 8; b++) acc[a][b] = 0.f;

    // Preload k0 = 0 into buffer 0
    {
        float4 va0 = *(const float4*)&A[(size_t)(bm + m0) * 1024 + kq];
        float4 va1 = *(const float4*)&A[(size_t)(bm + m1) * 1024 + kq];
        float4 vw0 = *(const float4*)&W[(size_t)(bn + m0) * 1024 + kq];
        float4 vw1 = *(const float4*)&W[(size_t)(bn + m1) * 1024 + kq];
        As[0][kq + 0][m0] = va0.x; As[0][kq + 1][m0] = va0.y;
        As[0][kq + 2][m0] = va0.z; As[0][kq + 3][m0] = va0.w;
        As[0][kq + 0][m1] = va1.x; As[0][kq + 1][m1] = va1.y;
        As[0][kq + 2][m1] = va1.z; As[0][kq + 3][m1] = va1.w;
        Ws[0][kq + 0][m0] = vw0.x; Ws[0][kq + 1][m0] = vw0.y;
        Ws[0][kq + 2][m0] = vw0.z; Ws[0][kq + 3][m0] = vw0.w;
        Ws[0][kq + 0][m1] = vw1.x; Ws[0][kq + 1][m1] = vw1.y;
        Ws[0][kq + 2][m1] = vw1.z; Ws[0][kq + 3][m1] = vw1.w;
    }
    __syncthreads();

    for (int it = 0; it < 64; it++) {
        const int cur = it & 1;
        const int nxt = cur ^ 1;
        const int k1 = (it + 1) * 16;

        // Issue next tile's global loads early (overlap with compute)
        float4 va0, va1, vw0, vw1;
        if (k1 < 1024) {
            va0 = *(const float4*)&A[(size_t)(bm + m0) * 1024 + k1 + kq];
            va1 = *(const float4*)&A[(size_t)(bm + m1) * 1024 + k1 + kq];
            vw0 = *(const float4*)&W[(size_t)(bn + m0) * 1024 + k1 + kq];
            vw1 = *(const float4*)&W[(size_t)(bn + m1) * 1024 + k1 + kq];
        }

        // Compute on current buffer
#pragma unroll
        for (int kk = 0; kk < 16; kk++) {
            float4 a0 = *(float4*)&As[cur][kk][8 * ty];
            float4 a1 = *(float4*)&As[cur][kk][8 * ty + 4];
            float4 b0 = *(float4*)&Ws[cur][kk][8 * tx];
            float4 b1 = *(float4*)&Ws[cur][kk][8 * tx + 4];
            float ar[8] = {a0.x, a0.y, a0.z, a0.w, a1.x, a1.y, a1.z, a1.w};
            float br[8] = {b0.x, b0.y, b0.z, b0.w, b1.x, b1.y, b1.z, b1.w};
#pragma unroll
            for (int a = 0; a < 8; a++)
#pragma unroll
                for (int b = 0; b < 8; b++)
                    acc[a][b] = fmaf(ar[a], br[b], acc[a][b]);
        }

        // Stage next tile into the other buffer
        if (k1 < 1024) {
            As[nxt][kq + 0][m0] = va0.x; As[nxt][kq + 1][m0] = va0.y;
            As[nxt][kq + 2][m0] = va0.z; As[nxt][kq + 3][m0] = va0.w;
            As[nxt][kq + 0][m1] = va1.x; As[nxt][kq + 1][m1] = va1.y;
            As[nxt][kq + 2][m1] = va1.z; As[nxt][kq + 3][m1] = va1.w;
            Ws[nxt][kq + 0][m0] = vw0.x; Ws[nxt][kq + 1][m0] = vw0.y;
            Ws[nxt][kq + 2][m0] = vw0.z; Ws[nxt][kq + 3][m0] = vw0.w;
            Ws[nxt][kq + 0][m1] = vw1.x; Ws[nxt][kq + 1][m1] = vw1.y;
            Ws[nxt][kq + 2][m1] = vw1.z; Ws[nxt][kq + 3][m1] = vw1.w;
            __syncthreads();
        }
    }

    // Write 8x8 microtile
#pragma unroll
    for (int a = 0; a < 8; a++) {
        float4 o0 = make_float4(acc[a][0], acc[a][1], acc[a][2], acc[a][3]);
        float4 o1 = make_float4(acc[a][4], acc[a][5], acc[a][6], acc[a][7]);
        *(float4*)&C[(size_t)(bm + 8 * ty + a) * 1024 + bn + 8 * tx]     = o0;
        *(float4*)&C[(size_t)(bm + 8 * ty + a) * 1024 + bn + 8 * tx + 4] = o1;
    }
}

// ---------------------------------------------------------------------------
// Banded (sliding-window, causal) attention.
// One CTA per (query block n, head h, batch b). 256 threads.
// Key blocks jb = n-8 .. n:
//   jb == n-8 : only (r < c) valid  (window edge)
//   jb == n   : causal (c <= r)
//   otherwise : fully valid
// Online softmax (flash); O in registers (4x4/thread).
// ---------------------------------------------------------------------------
__global__ __launch_bounds__(256) void attn_kernel(
    const float* __restrict__ q, const float* __restrict__ k,
    const float* __restrict__ v, float* __restrict__ o)
{
    extern __shared__ float sm[];
    float* Qs   = sm;                // [64][64] d-major
    float* Ks   = sm + 4096;         // [64][64] d-major
    float* Vs   = sm + 8192;         // [64][64] row-major
    float* Ss   = sm + 12288;        // [64][65]
    float* mrow = Ss + 64 * 65;
    float* lrow = mrow + 64;
    float* cfr  = lrow + 64;

    const int tid = threadIdx.x;
    const int ty = tid >> 4;   // 0..15 -> rows 4*ty..4*ty+3
    const int tx = tid & 15;   // 0..15 -> cols 4*tx..4*tx+3
    const int n = blockIdx.x, h = blockIdx.y, b = blockIdx.z;

    const size_t qbase = ((size_t)b * TLEN + (size_t)n * 64) * DIM + h * HD;

    // Load Q transposed (d-major): 64 rows x 16 float4 = 1024 tasks
#pragma unroll
    for (int it = 0; it < 4; it++) {
        int t  = tid + it * 256;
        int i  = t >> 4;
        int dq = (t & 15) * 4;
        float4 vq = *(const float4*)&q[qbase + (size_t)i * DIM + dq];
        Qs[(dq + 0) * 64 + i] = vq.x; Qs[(dq + 1) * 64 + i] = vq.y;
        Qs[(dq + 2) * 64 + i] = vq.z; Qs[(dq + 3) * 64 + i] = vq.w;
    }
    if (tid < 64) { mrow[tid] = -1e9f; lrow[tid] = 0.f; }

    float acc[4][4];
#pragma unroll
    for (int a = 0; a < 4; a++)
#pragma unroll
        for (int c = 0; c < 4; c++) acc[a][c] = 0.f;

    for (int off = -8; off <= 0; off++) {
        int jb = n + off;
        if (jb < 0) continue;
        const size_t kbase = ((size_t)b * TLEN + (size_t)jb * 64) * DIM + h * HD;

        // Load K (d-major) and V (row-major)
#pragma unroll
        for (int it = 0; it < 4; it++) {
            int t  = tid + it * 256;
            int j  = t >> 4;
            int dq = (t & 15) * 4;
            float4 kv = *(const float4*)&k[kbase + (size_t)j * DIM + dq];
            Ks[(dq + 0) * 64 + j] = kv.x; Ks[(dq + 1) * 64 + j] = kv.y;
            Ks[(dq + 2) * 64 + j] = kv.z; Ks[(dq + 3) * 64 + j] = kv.w;
            float4 vv = *(const float4*)&v[kbase + (size_t)j * DIM + dq];
            *(float4*)&Vs[j * 64 + dq] = vv;
        }
        __syncthreads();

        // S = Q K^T (4x4 microtile)
        float s[4][4];
#pragma unroll
        for (int a = 0; a < 4; a++)
#pragma unroll
            for (int c = 0; c < 4; c++) s[a][c] = 0.f;
#pragma unroll 4
        for (int d = 0; d < 64; d++) {
            float4 qa = *(float4*)&Qs[d * 64 + 4 * ty];
            float4 kb = *(float4*)&Ks[d * 64 + 4 * tx];
            float ar[4] = {qa.x, qa.y, qa.z, qa.w};
            float br[4] = {kb.x, kb.y, kb.z, kb.w};
#pragma unroll
            for (int a = 0; a < 4; a++)
#pragma unroll
                for (int c = 0; c < 4; c++)
                    s[a][c] = fmaf(ar[a], br[c], s[a][c]);
        }
        // Mask + store scaled scores
#pragma unroll
        for (int a = 0; a < 4; a++) {
            int r = 4 * ty + a;
#pragma unroll
            for (int c = 0; c < 4; c++) {
                int cc = 4 * tx + c;
                bool valid = (off == 0) ? (cc <= r)
                           : (off == -8) ? (r < cc)
                           : true;
                Ss[r * 65 + cc] = valid ? s[a][c] * SCALE : -1e9f;
            }
        }
        __syncthreads();

        // Online softmax row pass (1 thread/row; stride 65 = conflict-free)
        if (tid < 64) {
            float mo = mrow[tid];
            float mx = mo;
#pragma unroll 8
            for (int j = 0; j < 64; j++) mx = fmaxf(mx, Ss[tid * 65 + j]);
            float cf = __expf(mo - mx);
            float sum = 0.f;
#pragma unroll 8
            for (int j = 0; j < 64; j++) {
                float p = __expf(Ss[tid * 65 + j] - mx);
                Ss[tid * 65 + j] = p;
                sum += p;
            }
            mrow[tid] = mx;
            cfr[tid]  = cf;
            lrow[tid] = lrow[tid] * cf + sum;
        }
        __syncthreads();

        // Rescale O, then O += P @ V
        float cfa[4];
#pragma unroll
        for (int a = 0; a < 4; a++) cfa[a] = cfr[4 * ty + a];
#pragma unroll
        for (int a = 0; a < 4; a++)
#pragma unroll
            for (int c = 0; c < 4; c++) acc[a][c] *= cfa[a];

#pragma unroll 4
        for (int j = 0; j < 64; j++) {
            float4 vb = *(float4*)&Vs[j * 64 + 4 * tx];
            float br[4] = {vb.x, vb.y, vb.z, vb.w};
            float pr[4];
#pragma unroll
            for (int a = 0; a < 4; a++) pr[a] = Ss[(4 * ty + a) * 65 + j];
#pragma unroll
            for (int a = 0; a < 4; a++)
#pragma unroll
                for (int c = 0; c < 4; c++)
                    acc[a][c] = fmaf(pr[a], br[c], acc[a][c]);
        }
        __syncthreads();
    }

    // Normalize and write out
#pragma unroll
    for (int a = 0; a < 4; a++) {
        float li = 1.f / lrow[4 * ty + a];
        float4 ov = make_float4(acc[a][0] * li, acc[a][1] * li,
                                acc[a][2] * li, acc[a][3] * li);
        *(float4*)&o[qbase + (size_t)(4 * ty + a) * DIM + 4 * tx] = ov;
    }
}

// ---------------------------------------------------------------------------
// Launch
// ---------------------------------------------------------------------------
extern "C" void kernel_launch(void* const* d_in, const int* in_sizes, int n_in,
                              void* d_out, int out_size)
{
    const float* x  = (const float*)d_in[0];
    const float* Wq = (const float*)d_in[1];
    const float* Wk = (const float*)d_in[2];
    const float* Wv = (const float*)d_in[3];
    const float* Wo = (const float*)d_in[4];
    float* out = (float*)d_out;

    float *q, *k, *v, *a;
    cudaGetSymbolAddress((void**)&q, g_q);
    cudaGetSymbolAddress((void**)&k, g_k);
    cudaGetSymbolAddress((void**)&v, g_v);
    cudaGetSymbolAddress((void**)&a, g_a);

    const int ATTN_SMEM = 16640 * 4;  // 66560 B
    cudaFuncSetAttribute(attn_kernel, cudaFuncAttributeMaxDynamicSharedMemorySize, ATTN_SMEM);

    dim3 gblock(256);
    dim3 ggrid(1024 / 128, MTOT / 128);   // (8, 64)

    gemm_nt_kernel<<<ggrid, gblock>>>(x, Wq, q);
    gemm_nt_kernel<<<ggrid, gblock>>>(x, Wk, k);
    gemm_nt_kernel<<<ggrid, gblock>>>(x, Wv, v);

    dim3 agrid(NBLK, NHEAD, BATCH);       // (64, 16, 2)
    attn_kernel<<<agrid, gblock, ATTN_SMEM>>>(q, k, v, a);

    gemm_nt_kernel<<<ggrid, gblock>>>(a, Wo, out);
}

// round 4
// speedup vs baseline: 1.7557x; 1.7557x over previous
#include <cuda_runtime.h>
#include <cuda_bf16.h>
#include <cstdint>

// Problem constants: B=2, T=4096, D=1024, H=16, hd=64, WIN=512, BS=64
#define DIM   1024
#define HD    64
#define NHEAD 16
#define TLEN  4096
#define BATCH 2
#define MTOT  (BATCH * TLEN)      // 8192
#define NBLK  (TLEN / 64)
#define SCALE 0.125f

// ---------------- scratch (device globals; allocation-free rule) ----------------
__device__ float g_q[MTOT * DIM];
__device__ float g_k[MTOT * DIM];
__device__ float g_v[MTOT * DIM];
__device__ float g_a[MTOT * DIM];
__device__ unsigned short g_xhi[MTOT * DIM];
__device__ unsigned short g_xlo[MTOT * DIM];
__device__ unsigned short g_whi[4 * DIM * DIM];
__device__ unsigned short g_wlo[4 * DIM * DIM];

// ---------------- helpers ----------------
__device__ __forceinline__ uint32_t smem_u32(const void* p) {
    uint32_t a;
    asm("{ .reg .u64 t; cvta.to.shared.u64 t, %1; cvt.u32.u64 %0, t; }" : "=r"(a) : "l"(p));
    return a;
}
__device__ __forceinline__ void cp16(uint32_t saddr, const void* g) {
    asm volatile("cp.async.cg.shared.global [%0], [%1], 16;" :: "r"(saddr), "l"(g));
}
#define CP_COMMIT() asm volatile("cp.async.commit_group;" ::: "memory")
#define CP_WAIT0()  asm volatile("cp.async.wait_group 0;" ::: "memory")

__device__ __forceinline__ void ldsm4(uint32_t& r0, uint32_t& r1, uint32_t& r2, uint32_t& r3, uint32_t addr) {
    asm volatile("ldmatrix.sync.aligned.m8n8.x4.shared.b16 {%0,%1,%2,%3}, [%4];"
                 : "=r"(r0), "=r"(r1), "=r"(r2), "=r"(r3) : "r"(addr));
}
__device__ __forceinline__ void mma16816(float* c, const uint32_t* a, const uint32_t* b) {
    asm volatile("mma.sync.aligned.m16n8k16.row.col.f32.bf16.bf16.f32 "
                 "{%0,%1,%2,%3}, {%4,%5,%6,%7}, {%8,%9}, {%0,%1,%2,%3};"
                 : "+f"(c[0]), "+f"(c[1]), "+f"(c[2]), "+f"(c[3])
                 : "r"(a[0]), "r"(a[1]), "r"(a[2]), "r"(a[3]), "r"(b[0]), "r"(b[1]));
}

// ---------------- fp32 -> bf16 hi/lo split ----------------
__global__ __launch_bounds__(256) void split_kernel(
    const float4* __restrict__ src, uint2* __restrict__ hi, uint2* __restrict__ lo, int n4)
{
    int i = blockIdx.x * blockDim.x + threadIdx.x;
    if (i >= n4) return;
    float4 v = src[i];
    float f[4] = {v.x, v.y, v.z, v.w};
    uint32_t hs[4], ls[4];
#pragma unroll
    for (int j = 0; j < 4; ++j) {
        __nv_bfloat16 h = __float2bfloat16(f[j]);
        float r = f[j] - __bfloat162float(h);
        __nv_bfloat16 l = __float2bfloat16(r);
        hs[j] = (uint32_t)*reinterpret_cast<unsigned short*>(&h);
        ls[j] = (uint32_t)*reinterpret_cast<unsigned short*>(&l);
    }
    uint2 H, L;
    H.x = hs[0] | (hs[1] << 16); H.y = hs[2] | (hs[3] << 16);
    L.x = ls[0] | (ls[1] << 16); L.y = ls[2] | (ls[3] << 16);
    hi[i] = H; lo[i] = L;
}

// ---------------- HMMA bf16x3 GEMM: C[M,N] = A @ B^T ----------------
// A: [8192,1024] bf16 hi/lo, B(=W): [1024,1024] bf16 hi/lo, C fp32.
// CTA 128x128, BK=32, 8 warps (2x4), warp tile 64x32. cp.async double buffer.
// smem tile layout: 128 rows x 80 bytes (32 bf16 + 16B pad) -> ldmatrix conflict-free.
#define T_STRIDE 80
#define TILE_BYTES (128 * T_STRIDE)          // 10240
#define STAGE_BYTES (4 * TILE_BYTES)         // 40960: Ahi, Alo, Bhi, Blo
#define GEMM_SMEM (2 * STAGE_BYTES)          // 81920

__device__ __forceinline__ void load_tile_ca(
    const unsigned short* __restrict__ G, int row0, int k0, uint32_t stile, int tid)
{
#pragma unroll
    for (int h = 0; h < 2; ++h) {
        int idx = tid + h * 256;          // 0..511
        int r   = idx >> 2;               // 0..127
        int ch  = idx & 3;                // 16B chunk
        cp16(stile + (uint32_t)(r * T_STRIDE + ch * 16),
             G + (size_t)(row0 + r) * 1024 + k0 + ch * 8);
    }
}

__global__ __launch_bounds__(256, 1) void gemm_hmma_kernel(
    const unsigned short* __restrict__ Ahi, const unsigned short* __restrict__ Alo,
    const unsigned short* __restrict__ Bhi, const unsigned short* __restrict__ Blo,
    float* __restrict__ C)
{
    extern __shared__ char gsm[];
    const uint32_t sbase = smem_u32(gsm);
    const int tid  = threadIdx.x;
    const int wid  = tid >> 5;
    const int lane = tid & 31;
    const int warp_m = wid >> 2;          // 0..1
    const int warp_n = wid & 3;           // 0..3
    const int bm = blockIdx.y * 128;
    const int bn = blockIdx.x * 128;

    float acc[4][4][4];
#pragma unroll
    for (int i = 0; i < 4; ++i)
#pragma unroll
        for (int j = 0; j < 4; ++j)
#pragma unroll
            for (int e = 0; e < 4; ++e) acc[i][j][e] = 0.f;

    // ldmatrix per-lane addresses (byte offsets within a tile)
    // A: lanes 0-15 -> rows 0-15 chunk0; 16-31 -> rows 0-15 chunk1
    const int a_r = lane & 15;
    const int a_c = lane >> 4;
    // B: lanes 0-7: n0-7 k0; 8-15: n0-7 k1; 16-23: n8-15 k0; 24-31: n8-15 k1
    const int b_r = (lane & 7) + ((lane & 16) >> 1);
    const int b_c = (lane >> 3) & 1;

    // prologue: stage 0
    {
        const uint32_t st = sbase;
        load_tile_ca(Ahi, bm, 0, st + 0 * TILE_BYTES, tid);
        load_tile_ca(Alo, bm, 0, st + 1 * TILE_BYTES, tid);
        load_tile_ca(Bhi, bn, 0, st + 2 * TILE_BYTES, tid);
        load_tile_ca(Blo, bn, 0, st + 3 * TILE_BYTES, tid);
        CP_COMMIT();
    }
    CP_WAIT0();
    __syncthreads();

    const int NIT = 1024 / 32;   // 32
    for (int it = 0; it < NIT; ++it) {
        // issue next stage loads
        if (it + 1 < NIT) {
            const uint32_t st = sbase + (uint32_t)((it + 1) & 1) * STAGE_BYTES;
            const int k0 = (it + 1) * 32;
            load_tile_ca(Ahi, bm, k0, st + 0 * TILE_BYTES, tid);
            load_tile_ca(Alo, bm, k0, st + 1 * TILE_BYTES, tid);
            load_tile_ca(Bhi, bn, k0, st + 2 * TILE_BYTES, tid);
            load_tile_ca(Blo, bn, k0, st + 3 * TILE_BYTES, tid);
            CP_COMMIT();
        }

        // compute current stage
        const uint32_t st = sbase + (uint32_t)(it & 1) * STAGE_BYTES;
        const uint32_t sAh = st + 0 * TILE_BYTES;
        const uint32_t sAl = st + 1 * TILE_BYTES;
        const uint32_t sBh = st + 2 * TILE_BYTES;
        const uint32_t sBl = st + 3 * TILE_BYTES;

#pragma unroll
        for (int ks = 0; ks < 2; ++ks) {
            uint32_t ah[4][4], al[4][4], bh[4][2], bl[4][2];
#pragma unroll
            for (int mf = 0; mf < 4; ++mf) {
                const uint32_t off = (uint32_t)((warp_m * 64 + mf * 16 + a_r) * T_STRIDE + ks * 32 + a_c * 16);
                ldsm4(ah[mf][0], ah[mf][1], ah[mf][2], ah[mf][3], sAh + off);
                ldsm4(al[mf][0], al[mf][1], al[mf][2], al[mf][3], sAl + off);
            }
#pragma unroll
            for (int bf = 0; bf < 2; ++bf) {
                const uint32_t off = (uint32_t)((warp_n * 32 + bf * 16 + b_r) * T_STRIDE + ks * 32 + b_c * 16);
                ldsm4(bh[2 * bf][0], bh[2 * bf][1], bh[2 * bf + 1][0], bh[2 * bf + 1][1], sBh + off);
                ldsm4(bl[2 * bf][0], bl[2 * bf][1], bl[2 * bf + 1][0], bl[2 * bf + 1][1], sBl + off);
            }
#pragma unroll
            for (int mf = 0; mf < 4; ++mf)
#pragma unroll
                for (int nf = 0; nf < 4; ++nf)
                    mma16816(acc[mf][nf], ah[mf], bh[nf]);
#pragma unroll
            for (int mf = 0; mf < 4; ++mf)
#pragma unroll
                for (int nf = 0; nf < 4; ++nf)
                    mma16816(acc[mf][nf], ah[mf], bl[nf]);
#pragma unroll
            for (int mf = 0; mf < 4; ++mf)
#pragma unroll
                for (int nf = 0; nf < 4; ++nf)
                    mma16816(acc[mf][nf], al[mf], bh[nf]);
        }

        if (it + 1 < NIT) {
            CP_WAIT0();
            __syncthreads();
        }
    }

    // epilogue: direct global stores (float2 per frag-half)
    const int er = lane >> 2;
    const int ec = (lane & 3) * 2;
#pragma unroll
    for (int mf = 0; mf < 4; ++mf) {
#pragma unroll
        for (int nf = 0; nf < 4; ++nf) {
            const size_t row = (size_t)(bm + warp_m * 64 + mf * 16 + er);
            const int col = bn + warp_n * 32 + nf * 8 + ec;
            *(float2*)&C[row * 1024 + col]        = make_float2(acc[mf][nf][0], acc[mf][nf][1]);
            *(float2*)&C[(row + 8) * 1024 + col]  = make_float2(acc[mf][nf][2], acc[mf][nf][3]);
        }
    }
}

// ---------------- banded sliding-window attention (unchanged, passing) ----------------
__global__ __launch_bounds__(256) void attn_kernel(
    const float* __restrict__ q, const float* __restrict__ k,
    const float* __restrict__ v, float* __restrict__ o)
{
    extern __shared__ float sm[];
    float* Qs   = sm;
    float* Ks   = sm + 4096;
    float* Vs   = sm + 8192;
    float* Ss   = sm + 12288;        // stride 65
    float* mrow = Ss + 64 * 65;
    float* lrow = mrow + 64;
    float* cfr  = lrow + 64;

    const int tid = threadIdx.x;
    const int ty = tid >> 4;
    const int tx = tid & 15;
    const int n = blockIdx.x, h = blockIdx.y, b = blockIdx.z;

    const size_t qbase = ((size_t)b * TLEN + (size_t)n * 64) * DIM + h * HD;

#pragma unroll
    for (int it = 0; it < 4; it++) {
        int t  = tid + it * 256;
        int i  = t >> 4;
        int dq = (t & 15) * 4;
        float4 vq = *(const float4*)&q[qbase + (size_t)i * DIM + dq];
        Qs[(dq + 0) * 64 + i] = vq.x; Qs[(dq + 1) * 64 + i] = vq.y;
        Qs[(dq + 2) * 64 + i] = vq.z; Qs[(dq + 3) * 64 + i] = vq.w;
    }
    if (tid < 64) { mrow[tid] = -1e9f; lrow[tid] = 0.f; }

    float acc[4][4];
#pragma unroll
    for (int a = 0; a < 4; a++)
#pragma unroll
        for (int c = 0; c < 4; c++) acc[a][c] = 0.f;

    for (int off = -8; off <= 0; off++) {
        int jb = n + off;
        if (jb < 0) continue;
        const size_t kbase = ((size_t)b * TLEN + (size_t)jb * 64) * DIM + h * HD;

#pragma unroll
        for (int it = 0; it < 4; it++) {
            int t  = tid + it * 256;
            int j  = t >> 4;
            int dq = (t & 15) * 4;
            float4 kv = *(const float4*)&k[kbase + (size_t)j * DIM + dq];
            Ks[(dq + 0) * 64 + j] = kv.x; Ks[(dq + 1) * 64 + j] = kv.y;
            Ks[(dq + 2) * 64 + j] = kv.z; Ks[(dq + 3) * 64 + j] = kv.w;
            float4 vv = *(const float4*)&v[kbase + (size_t)j * DIM + dq];
            *(float4*)&Vs[j * 64 + dq] = vv;
        }
        __syncthreads();

        float s[4][4];
#pragma unroll
        for (int a = 0; a < 4; a++)
#pragma unroll
            for (int c = 0; c < 4; c++) s[a][c] = 0.f;
#pragma unroll 4
        for (int d = 0; d < 64; d++) {
            float4 qa = *(float4*)&Qs[d * 64 + 4 * ty];
            float4 kb = *(float4*)&Ks[d * 64 + 4 * tx];
            float ar[4] = {qa.x, qa.y, qa.z, qa.w};
            float br[4] = {kb.x, kb.y, kb.z, kb.w};
#pragma unroll
            for (int a = 0; a < 4; a++)
#pragma unroll
                for (int c = 0; c < 4; c++)
                    s[a][c] = fmaf(ar[a], br[c], s[a][c]);
        }
#pragma unroll
        for (int a = 0; a < 4; a++) {
            int r = 4 * ty + a;
#pragma unroll
            for (int c = 0; c < 4; c++) {
                int cc = 4 * tx + c;
                bool valid = (off == 0) ? (cc <= r)
                           : (off == -8) ? (r < cc)
                           : true;
                Ss[r * 65 + cc] = valid ? s[a][c] * SCALE : -1e9f;
            }
        }
        __syncthreads();

        if (tid < 64) {
            float mo = mrow[tid];
            float mx = mo;
#pragma unroll 8
            for (int j = 0; j < 64; j++) mx = fmaxf(mx, Ss[tid * 65 + j]);
            float cf = __expf(mo - mx);
            float sum = 0.f;
#pragma unroll 8
            for (int j = 0; j < 64; j++) {
                float p = __expf(Ss[tid * 65 + j] - mx);
                Ss[tid * 65 + j] = p;
                sum += p;
            }
            mrow[tid] = mx;
            cfr[tid]  = cf;
            lrow[tid] = lrow[tid] * cf + sum;
        }
        __syncthreads();

        float cfa[4];
#pragma unroll
        for (int a = 0; a < 4; a++) cfa[a] = cfr[4 * ty + a];
#pragma unroll
        for (int a = 0; a < 4; a++)
#pragma unroll
            for (int c = 0; c < 4; c++) acc[a][c] *= cfa[a];

#pragma unroll 4
        for (int j = 0; j < 64; j++) {
            float4 vb = *(float4*)&Vs[j * 64 + 4 * tx];
            float br[4] = {vb.x, vb.y, vb.z, vb.w};
            float pr[4];
#pragma unroll
            for (int a = 0; a < 4; a++) pr[a] = Ss[(4 * ty + a) * 65 + j];
#pragma unroll
            for (int a = 0; a < 4; a++)
#pragma unroll
                for (int c = 0; c < 4; c++)
                    acc[a][c] = fmaf(pr[a], br[c], acc[a][c]);
        }
        __syncthreads();
    }

#pragma unroll
    for (int a = 0; a < 4; a++) {
        float li = 1.f / lrow[4 * ty + a];
        float4 ov = make_float4(acc[a][0] * li, acc[a][1] * li,
                                acc[a][2] * li, acc[a][3] * li);
        *(float4*)&o[qbase + (size_t)(4 * ty + a) * DIM + 4 * tx] = ov;
    }
}

// ---------------- launch ----------------
extern "C" void kernel_launch(void* const* d_in, const int* in_sizes, int n_in,
                              void* d_out, int out_size)
{
    const float* x  = (const float*)d_in[0];
    const float* Wq = (const float*)d_in[1];
    const float* Wk = (const float*)d_in[2];
    const float* Wv = (const float*)d_in[3];
    const float* Wo = (const float*)d_in[4];
    float* out = (float*)d_out;

    float *q, *k, *v, *a;
    unsigned short *xhi, *xlo, *whi, *wlo;
    cudaGetSymbolAddress((void**)&q, g_q);
    cudaGetSymbolAddress((void**)&k, g_k);
    cudaGetSymbolAddress((void**)&v, g_v);
    cudaGetSymbolAddress((void**)&a, g_a);
    cudaGetSymbolAddress((void**)&xhi, g_xhi);
    cudaGetSymbolAddress((void**)&xlo, g_xlo);
    cudaGetSymbolAddress((void**)&whi, g_whi);
    cudaGetSymbolAddress((void**)&wlo, g_wlo);

    const int ATTN_SMEM = 16640 * 4;
    cudaFuncSetAttribute(attn_kernel, cudaFuncAttributeMaxDynamicSharedMemorySize, ATTN_SMEM);
    cudaFuncSetAttribute(gemm_hmma_kernel, cudaFuncAttributeMaxDynamicSharedMemorySize, GEMM_SMEM);

    const int n4x = MTOT * DIM / 4;
    const int n4w = DIM * DIM / 4;

    split_kernel<<<n4x / 256, 256>>>((const float4*)x, (uint2*)xhi, (uint2*)xlo, n4x);
    split_kernel<<<n4w / 256, 256>>>((const float4*)Wq, (uint2*)(whi + 0 * DIM * DIM), (uint2*)(wlo + 0 * DIM * DIM), n4w);
    split_kernel<<<n4w / 256, 256>>>((const float4*)Wk, (uint2*)(whi + 1 * DIM * DIM), (uint2*)(wlo + 1 * DIM * DIM), n4w);
    split_kernel<<<n4w / 256, 256>>>((const float4*)Wv, (uint2*)(whi + 2 * DIM * DIM), (uint2*)(wlo + 2 * DIM * DIM), n4w);
    split_kernel<<<n4w / 256, 256>>>((const float4*)Wo, (uint2*)(whi + 3 * DIM * DIM), (uint2*)(wlo + 3 * DIM * DIM), n4w);

    dim3 ggrid(DIM / 128, MTOT / 128);   // (8, 64)
    gemm_hmma_kernel<<<ggrid, 256, GEMM_SMEM>>>(xhi, xlo, whi + 0 * DIM * DIM, wlo + 0 * DIM * DIM, q);
    gemm_hmma_kernel<<<ggrid, 256, GEMM_SMEM>>>(xhi, xlo, whi + 1 * DIM * DIM, wlo + 1 * DIM * DIM, k);
    gemm_hmma_kernel<<<ggrid, 256, GEMM_SMEM>>>(xhi, xlo, whi + 2 * DIM * DIM, wlo + 2 * DIM * DIM, v);

    dim3 agrid(NBLK, NHEAD, BATCH);
    attn_kernel<<<agrid, 256, ATTN_SMEM>>>(q, k, v, a);

    split_kernel<<<n4x / 256, 256>>>((const float4*)a, (uint2*)xhi, (uint2*)xlo, n4x);
    gemm_hmma_kernel<<<ggrid, 256, GEMM_SMEM>>>(xhi, xlo, whi + 3 * DIM * DIM, wlo + 3 * DIM * DIM, out);
}

// round 6
// speedup vs baseline: 2.8888x; 1.6454x over previous
#include <cuda_runtime.h>
#include <cuda_bf16.h>
#include <cuda_fp16.h>
#include <cstdint>

// Problem constants: B=2, T=4096, D=1024, H=16, hd=64, WIN=512, BS=64
#define DIM   1024
#define HD    64
#define NHEAD 16
#define TLEN  4096
#define BATCH 2
#define MTOT  (BATCH * TLEN)      // 8192
#define NBLK  (TLEN / 64)
#define SCALE 0.125f

// ---------------- scratch (device globals; allocation-free rule) ----------------
__device__ float g_q[MTOT * DIM];   // reused as __half q16
__device__ float g_k[MTOT * DIM];   // reused as __half k16
__device__ float g_v[MTOT * DIM];   // reused as __half v16
__device__ unsigned short g_xhi[MTOT * DIM];   // x hi; later attn-out hi
__device__ unsigned short g_xlo[MTOT * DIM];   // x lo; later attn-out lo
__device__ unsigned short g_whi[4 * DIM * DIM];
__device__ unsigned short g_wlo[4 * DIM * DIM];

// ---------------- helpers ----------------
__device__ __forceinline__ uint32_t smem_u32(const void* p) {
    uint32_t a;
    asm("{ .reg .u64 t; cvta.to.shared.u64 t, %1; cvt.u32.u64 %0, t; }" : "=r"(a) : "l"(p));
    return a;
}
__device__ __forceinline__ void cp16(uint32_t saddr, const void* g) {
    asm volatile("cp.async.cg.shared.global [%0], [%1], 16;" :: "r"(saddr), "l"(g));
}
#define CP_COMMIT() asm volatile("cp.async.commit_group;" ::: "memory")
#define CP_WAIT(n)  asm volatile("cp.async.wait_group %0;" :: "n"(n) : "memory")

__device__ __forceinline__ void ldsm4(uint32_t& r0, uint32_t& r1, uint32_t& r2, uint32_t& r3, uint32_t addr) {
    asm volatile("ldmatrix.sync.aligned.m8n8.x4.shared.b16 {%0,%1,%2,%3}, [%4];"
                 : "=r"(r0), "=r"(r1), "=r"(r2), "=r"(r3) : "r"(addr));
}
__device__ __forceinline__ void ldsm4t(uint32_t& r0, uint32_t& r1, uint32_t& r2, uint32_t& r3, uint32_t addr) {
    asm volatile("ldmatrix.sync.aligned.m8n8.x4.trans.shared.b16 {%0,%1,%2,%3}, [%4];"
                 : "=r"(r0), "=r"(r1), "=r"(r2), "=r"(r3) : "r"(addr));
}
__device__ __forceinline__ void mma_bf16(float* c, const uint32_t* a, const uint32_t* b) {
    asm volatile("mma.sync.aligned.m16n8k16.row.col.f32.bf16.bf16.f32 "
                 "{%0,%1,%2,%3}, {%4,%5,%6,%7}, {%8,%9}, {%0,%1,%2,%3};"
                 : "+f"(c[0]), "+f"(c[1]), "+f"(c[2]), "+f"(c[3])
                 : "r"(a[0]), "r"(a[1]), "r"(a[2]), "r"(a[3]), "r"(b[0]), "r"(b[1]));
}
__device__ __forceinline__ void mma_f16(float* c, const uint32_t* a, const uint32_t* b) {
    asm volatile("mma.sync.aligned.m16n8k16.row.col.f32.f16.f16.f32 "
                 "{%0,%1,%2,%3}, {%4,%5,%6,%7}, {%8,%9}, {%0,%1,%2,%3};"
                 : "+f"(c[0]), "+f"(c[1]), "+f"(c[2]), "+f"(c[3])
                 : "r"(a[0]), "r"(a[1]), "r"(a[2]), "r"(a[3]), "r"(b[0]), "r"(b[1]));
}

// ---------------- fp32 -> bf16 hi/lo split ----------------
__global__ __launch_bounds__(256) void split_kernel(
    const float4* __restrict__ src, uint2* __restrict__ hi, uint2* __restrict__ lo, int n4)
{
    int i = blockIdx.x * blockDim.x + threadIdx.x;
    if (i >= n4) return;
    float4 v = src[i];
    float f[4] = {v.x, v.y, v.z, v.w};
    uint32_t hs[4], ls[4];
#pragma unroll
    for (int j = 0; j < 4; ++j) {
        __nv_bfloat16 h = __float2bfloat16(f[j]);
        float r = f[j] - __bfloat162float(h);
        __nv_bfloat16 l = __float2bfloat16(r);
        hs[j] = (uint32_t)*reinterpret_cast<unsigned short*>(&h);
        ls[j] = (uint32_t)*reinterpret_cast<unsigned short*>(&l);
    }
    uint2 H, L;
    H.x = hs[0] | (hs[1] << 16); H.y = hs[2] | (hs[3] << 16);
    L.x = ls[0] | (ls[1] << 16); L.y = ls[2] | (ls[3] << 16);
    hi[i] = H; lo[i] = L;
}

// ---------------- HMMA bf16x3 GEMM: C[M,N] = A @ B^T ----------------
// CTA 128x128, BK=32, 8 warps (2x4), warp tile 64x32. 3-stage cp.async pipeline.
#define T_STRIDE 80
#define TILE_BYTES (128 * T_STRIDE)          // 10240
#define STAGE_BYTES (4 * TILE_BYTES)         // 40960
#define GEMM_SMEM (3 * STAGE_BYTES)          // 122880

__device__ __forceinline__ void load_tile_ca(
    const unsigned short* __restrict__ G, int row0, int k0, uint32_t stile, int tid)
{
#pragma unroll
    for (int h = 0; h < 2; ++h) {
        int idx = tid + h * 256;
        int r   = idx >> 2;
        int ch  = idx & 3;
        cp16(stile + (uint32_t)(r * T_STRIDE + ch * 16),
             G + (size_t)(row0 + r) * 1024 + k0 + ch * 8);
    }
}

__global__ __launch_bounds__(256, 1) void gemm_hmma_kernel(
    const unsigned short* __restrict__ Ahi, const unsigned short* __restrict__ Alo,
    const unsigned short* __restrict__ Bhi, const unsigned short* __restrict__ Blo,
    float* __restrict__ Cf, __half* __restrict__ Ch)
{
    extern __shared__ char gsm[];
    const uint32_t sbase = smem_u32(gsm);
    const int tid  = threadIdx.x;
    const int wid  = tid >> 5;
    const int lane = tid & 31;
    const int warp_m = wid >> 2;
    const int warp_n = wid & 3;
    const int bm = blockIdx.y * 128;
    const int bn = blockIdx.x * 128;

    float acc[4][4][4];
#pragma unroll
    for (int i = 0; i < 4; ++i)
#pragma unroll
        for (int j = 0; j < 4; ++j)
#pragma unroll
            for (int e = 0; e < 4; ++e) acc[i][j][e] = 0.f;

    const int a_r = lane & 15;
    const int a_c = lane >> 4;
    const int b_r = (lane & 7) + ((lane & 16) >> 1);
    const int b_c = (lane >> 3) & 1;

    const int NIT = 1024 / 32;   // 32

#pragma unroll
    for (int s = 0; s < 2; ++s) {
        const uint32_t st = sbase + (uint32_t)s * STAGE_BYTES;
        const int k0 = s * 32;
        load_tile_ca(Ahi, bm, k0, st + 0 * TILE_BYTES, tid);
        load_tile_ca(Alo, bm, k0, st + 1 * TILE_BYTES, tid);
        load_tile_ca(Bhi, bn, k0, st + 2 * TILE_BYTES, tid);
        load_tile_ca(Blo, bn, k0, st + 3 * TILE_BYTES, tid);
        CP_COMMIT();
    }

    int buf = 0, nbuf = 2;
    for (int it = 0; it < NIT; ++it) {
        if (it + 2 < NIT) {
            const uint32_t st = sbase + (uint32_t)nbuf * STAGE_BYTES;
            const int k0 = (it + 2) * 32;
            load_tile_ca(Ahi, bm, k0, st + 0 * TILE_BYTES, tid);
            load_tile_ca(Alo, bm, k0, st + 1 * TILE_BYTES, tid);
            load_tile_ca(Bhi, bn, k0, st + 2 * TILE_BYTES, tid);
            load_tile_ca(Blo, bn, k0, st + 3 * TILE_BYTES, tid);
            CP_COMMIT();
        }
        if (it + 2 < NIT)      CP_WAIT(2);
        else if (it + 1 < NIT) CP_WAIT(1);
        else                   CP_WAIT(0);
        __syncthreads();

        const uint32_t st = sbase + (uint32_t)buf * STAGE_BYTES;
        const uint32_t sAh = st + 0 * TILE_BYTES;
        const uint32_t sAl = st + 1 * TILE_BYTES;
        const uint32_t sBh = st + 2 * TILE_BYTES;
        const uint32_t sBl = st + 3 * TILE_BYTES;

#pragma unroll
        for (int ks = 0; ks < 2; ++ks) {
            uint32_t ah[4][4], al[4][4], bh[4][2], bl[4][2];
#pragma unroll
            for (int mf = 0; mf < 4; ++mf) {
                const uint32_t off = (uint32_t)((warp_m * 64 + mf * 16 + a_r) * T_STRIDE + ks * 32 + a_c * 16);
                ldsm4(ah[mf][0], ah[mf][1], ah[mf][2], ah[mf][3], sAh + off);
                ldsm4(al[mf][0], al[mf][1], al[mf][2], al[mf][3], sAl + off);
            }
#pragma unroll
            for (int bf = 0; bf < 2; ++bf) {
                const uint32_t off = (uint32_t)((warp_n * 32 + bf * 16 + b_r) * T_STRIDE + ks * 32 + b_c * 16);
                ldsm4(bh[2 * bf][0], bh[2 * bf][1], bh[2 * bf + 1][0], bh[2 * bf + 1][1], sBh + off);
                ldsm4(bl[2 * bf][0], bl[2 * bf][1], bl[2 * bf + 1][0], bl[2 * bf + 1][1], sBl + off);
            }
#pragma unroll
            for (int mf = 0; mf < 4; ++mf)
#pragma unroll
                for (int nf = 0; nf < 4; ++nf)
                    mma_bf16(acc[mf][nf], ah[mf], bh[nf]);
#pragma unroll
            for (int mf = 0; mf < 4; ++mf)
#pragma unroll
                for (int nf = 0; nf < 4; ++nf)
                    mma_bf16(acc[mf][nf], ah[mf], bl[nf]);
#pragma unroll
            for (int mf = 0; mf < 4; ++mf)
#pragma unroll
                for (int nf = 0; nf < 4; ++nf)
                    mma_bf16(acc[mf][nf], al[mf], bh[nf]);
        }
        __syncthreads();
        buf = (buf + 1 == 3) ? 0 : buf + 1;
        nbuf = (nbuf + 1 == 3) ? 0 : nbuf + 1;
    }

    const int er = lane >> 2;
    const int ec = (lane & 3) * 2;
    if (Ch) {
#pragma unroll
        for (int mf = 0; mf < 4; ++mf)
#pragma unroll
            for (int nf = 0; nf < 4; ++nf) {
                const size_t row = (size_t)(bm + warp_m * 64 + mf * 16 + er);
                const int col = bn + warp_n * 32 + nf * 8 + ec;
                __half2 h01 = __floats2half2_rn(acc[mf][nf][0], acc[mf][nf][1]);
                __half2 h23 = __floats2half2_rn(acc[mf][nf][2], acc[mf][nf][3]);
                *(uint32_t*)&Ch[row * 1024 + col]       = *(uint32_t*)&h01;
                *(uint32_t*)&Ch[(row + 8) * 1024 + col] = *(uint32_t*)&h23;
            }
    } else {
#pragma unroll
        for (int mf = 0; mf < 4; ++mf)
#pragma unroll
            for (int nf = 0; nf < 4; ++nf) {
                const size_t row = (size_t)(bm + warp_m * 64 + mf * 16 + er);
                const int col = bn + warp_n * 32 + nf * 8 + ec;
                *(float2*)&Cf[row * 1024 + col]       = make_float2(acc[mf][nf][0], acc[mf][nf][1]);
                *(float2*)&Cf[(row + 8) * 1024 + col] = make_float2(acc[mf][nf][2], acc[mf][nf][3]);
            }
    }
}

// ---------------- fp16 HMMA flash attention (banded, causal) ----------------
// CTA per (qblock n, head h, batch b). 4 warps x 16 rows.
// THREE-stage cp.async K/V pipeline (depth-2 prefetch requires 3 buffers).
// smem: Q [0,9216), stage s (s=i%3): K @9216+s*18432, V @+9216. Row stride 144 B.
#define ASTR 144
#define ATTN_STAGE(s) (9216u + (uint32_t)(s) * 18432u)
#define ATTN_SMEM (9216 + 3 * 18432)   // 64512

__global__ __launch_bounds__(128) void attn_hmma_kernel(
    const __half* __restrict__ qg, const __half* __restrict__ kg,
    const __half* __restrict__ vg,
    unsigned short* __restrict__ ahi, unsigned short* __restrict__ alo)
{
    extern __shared__ char smb[];
    const uint32_t sb = smem_u32(smb);
    const int tid = threadIdx.x;
    const int wid = tid >> 5;
    const int lane = tid & 31;
    const int n = blockIdx.x, h = blockIdx.y, b = blockIdx.z;

    const size_t qbase = ((size_t)(b * TLEN + n * 64)) * DIM + h * HD;

    // Q: 64 rows x 8 x 16B
#pragma unroll
    for (int i = 0; i < 4; ++i) {
        int idx = tid + i * 128;
        int r = idx >> 3, ch = idx & 7;
        cp16(sb + (uint32_t)(r * ASTR + ch * 16), qg + qbase + (size_t)r * DIM + ch * 8);
    }
    CP_COMMIT();

    const int jb0 = (n >= 8) ? n - 8 : 0;
    const int NB = n - jb0 + 1;

    auto issue = [&](int i) {
        const int jb = jb0 + i;
        const size_t kb = ((size_t)(b * TLEN + jb * 64)) * DIM + h * HD;
        const uint32_t st = sb + ATTN_STAGE(i % 3);
#pragma unroll
        for (int t = 0; t < 4; ++t) {
            int idx = tid + t * 128;
            int r = idx >> 3, ch = idx & 7;
            cp16(st + (uint32_t)(r * ASTR + ch * 16), kg + kb + (size_t)r * DIM + ch * 8);
            cp16(st + 9216u + (uint32_t)(r * ASTR + ch * 16), vg + kb + (size_t)r * DIM + ch * 8);
        }
        CP_COMMIT();
    };

    issue(0);
    if (NB > 1) issue(1);

    const int a_r = lane & 15, a_c = lane >> 4;
    const int b_r = (lane & 7) + ((lane & 16) >> 1), b_c = (lane >> 3) & 1;
    const int er = lane >> 2, ec = 2 * (lane & 3);
    const int r0 = wid * 16 + er, r1 = r0 + 8;

    float m0 = -1e9f, m1 = -1e9f, l0 = 0.f, l1 = 0.f;
    float of[8][4];
#pragma unroll
    for (int nf = 0; nf < 8; ++nf)
#pragma unroll
        for (int e = 0; e < 4; ++e) of[nf][e] = 0.f;
    uint32_t qf[4][4];

    for (int i = 0; i < NB; ++i) {
        if (i + 2 < NB) issue(i + 2);
        if (i + 2 < NB)      CP_WAIT(2);
        else if (i + 1 < NB) CP_WAIT(1);
        else                 CP_WAIT(0);
        __syncthreads();

        if (i == 0) {
#pragma unroll
            for (int ks = 0; ks < 4; ++ks)
                ldsm4(qf[ks][0], qf[ks][1], qf[ks][2], qf[ks][3],
                      sb + (uint32_t)((wid * 16 + a_r) * ASTR + ks * 32 + a_c * 16));
        }

        const int off = (jb0 + i) - n;
        const uint32_t Kst = sb + ATTN_STAGE(i % 3);
        const uint32_t Vst = Kst + 9216u;

        // S = Q K^T
        float sf[8][4];
#pragma unroll
        for (int nf = 0; nf < 8; ++nf)
#pragma unroll
            for (int e = 0; e < 4; ++e) sf[nf][e] = 0.f;
#pragma unroll
        for (int ks = 0; ks < 4; ++ks) {
            uint32_t kf[8][2];
#pragma unroll
            for (int bf = 0; bf < 4; ++bf)
                ldsm4(kf[2 * bf][0], kf[2 * bf][1], kf[2 * bf + 1][0], kf[2 * bf + 1][1],
                      Kst + (uint32_t)((bf * 16 + b_r) * ASTR + ks * 32 + b_c * 16));
#pragma unroll
            for (int nf = 0; nf < 8; ++nf)
                mma_f16(sf[nf], qf[ks], kf[nf]);
        }

        // scale + mask
#pragma unroll
        for (int nf = 0; nf < 8; ++nf) {
#pragma unroll
            for (int e = 0; e < 4; ++e) {
                int row = (e < 2) ? r0 : r1;
                int c = nf * 8 + ec + (e & 1);
                float sv = sf[nf][e] * SCALE;
                bool valid = (off == 0) ? (c <= row) : ((off == -8) ? (row < c) : true);
                sf[nf][e] = valid ? sv : -1e9f;
            }
        }

        // online softmax
        float mx0 = sf[0][0], mx1 = sf[0][2];
#pragma unroll
        for (int nf = 0; nf < 8; ++nf) {
            mx0 = fmaxf(mx0, fmaxf(sf[nf][0], sf[nf][1]));
            mx1 = fmaxf(mx1, fmaxf(sf[nf][2], sf[nf][3]));
        }
        mx0 = fmaxf(mx0, __shfl_xor_sync(0xffffffffu, mx0, 1));
        mx0 = fmaxf(mx0, __shfl_xor_sync(0xffffffffu, mx0, 2));
        mx1 = fmaxf(mx1, __shfl_xor_sync(0xffffffffu, mx1, 1));
        mx1 = fmaxf(mx1, __shfl_xor_sync(0xffffffffu, mx1, 2));
        float mn0 = fmaxf(m0, mx0), mn1 = fmaxf(m1, mx1);
        float cf0 = __expf(m0 - mn0), cf1 = __expf(m1 - mn1);
        m0 = mn0; m1 = mn1;

        float s0 = 0.f, s1 = 0.f;
        uint32_t pf[4][4];
#pragma unroll
        for (int nf = 0; nf < 8; ++nf) {
            float p0 = __expf(sf[nf][0] - m0);
            float p1 = __expf(sf[nf][1] - m0);
            float p2 = __expf(sf[nf][2] - m1);
            float p3 = __expf(sf[nf][3] - m1);
            s0 += p0 + p1; s1 += p2 + p3;
            __half2 h01 = __floats2half2_rn(p0, p1);
            __half2 h23 = __floats2half2_rn(p2, p3);
            pf[nf >> 1][(nf & 1) * 2 + 0] = *(uint32_t*)&h01;
            pf[nf >> 1][(nf & 1) * 2 + 1] = *(uint32_t*)&h23;
        }
        l0 = l0 * cf0 + s0; l1 = l1 * cf1 + s1;
#pragma unroll
        for (int nf = 0; nf < 8; ++nf) {
            of[nf][0] *= cf0; of[nf][1] *= cf0;
            of[nf][2] *= cf1; of[nf][3] *= cf1;
        }

        // O += P V  (V via ldmatrix.trans on row-major tile)
#pragma unroll
        for (int ks = 0; ks < 4; ++ks) {
            uint32_t vf[8][2];
#pragma unroll
            for (int nfp = 0; nfp < 4; ++nfp)
                ldsm4t(vf[2 * nfp][0], vf[2 * nfp][1], vf[2 * nfp + 1][0], vf[2 * nfp + 1][1],
                       Vst + (uint32_t)((ks * 16 + (lane & 15)) * ASTR + (nfp * 2 + (lane >> 4)) * 16));
#pragma unroll
            for (int nf = 0; nf < 8; ++nf)
                mma_f16(of[nf], pf[ks], vf[nf]);
        }
        __syncthreads();
    }

    // finalize
    l0 += __shfl_xor_sync(0xffffffffu, l0, 1);
    l0 += __shfl_xor_sync(0xffffffffu, l0, 2);
    l1 += __shfl_xor_sync(0xffffffffu, l1, 1);
    l1 += __shfl_xor_sync(0xffffffffu, l1, 2);
    const float i0 = 1.f / l0, i1 = 1.f / l1;
    const size_t row0 = (size_t)(b * TLEN + n * 64 + r0);
    const size_t row1 = row0 + 8;
#pragma unroll
    for (int nf = 0; nf < 8; ++nf) {
        const int col = h * HD + nf * 8 + ec;
        float o[4] = {of[nf][0] * i0, of[nf][1] * i0, of[nf][2] * i1, of[nf][3] * i1};
        uint32_t hs[4], ls[4];
#pragma unroll
        for (int e = 0; e < 4; ++e) {
            __nv_bfloat16 hb = __float2bfloat16(o[e]);
            __nv_bfloat16 lb = __float2bfloat16(o[e] - __bfloat162float(hb));
            hs[e] = (uint32_t)*reinterpret_cast<unsigned short*>(&hb);
            ls[e] = (uint32_t)*reinterpret_cast<unsigned short*>(&lb);
        }
        *(uint32_t*)&ahi[row0 * DIM + col] = hs[0] | (hs[1] << 16);
        *(uint32_t*)&alo[row0 * DIM + col] = ls[0] | (ls[1] << 16);
        *(uint32_t*)&ahi[row1 * DIM + col] = hs[2] | (hs[3] << 16);
        *(uint32_t*)&alo[row1 * DIM + col] = ls[2] | (ls[3] << 16);
    }
}

// ---------------- launch ----------------
extern "C" void kernel_launch(void* const* d_in, const int* in_sizes, int n_in,
                              void* d_out, int out_size)
{
    const float* x  = (const float*)d_in[0];
    const float* Wq = (const float*)d_in[1];
    const float* Wk = (const float*)d_in[2];
    const float* Wv = (const float*)d_in[3];
    const float* Wo = (const float*)d_in[4];
    float* out = (float*)d_out;

    void *qv, *kv, *vv;
    unsigned short *xhi, *xlo, *whi, *wlo;
    cudaGetSymbolAddress(&qv, g_q);
    cudaGetSymbolAddress(&kv, g_k);
    cudaGetSymbolAddress(&vv, g_v);
    cudaGetSymbolAddress((void**)&xhi, g_xhi);
    cudaGetSymbolAddress((void**)&xlo, g_xlo);
    cudaGetSymbolAddress((void**)&whi, g_whi);
    cudaGetSymbolAddress((void**)&wlo, g_wlo);
    __half* q16 = (__half*)qv;
    __half* k16 = (__half*)kv;
    __half* v16 = (__half*)vv;

    cudaFuncSetAttribute(gemm_hmma_kernel, cudaFuncAttributeMaxDynamicSharedMemorySize, GEMM_SMEM);
    cudaFuncSetAttribute(attn_hmma_kernel, cudaFuncAttributeMaxDynamicSharedMemorySize, ATTN_SMEM);

    const int n4x = MTOT * DIM / 4;
    const int n4w = DIM * DIM / 4;

    split_kernel<<<n4x / 256, 256>>>((const float4*)x, (uint2*)xhi, (uint2*)xlo, n4x);
    split_kernel<<<n4w / 256, 256>>>((const float4*)Wq, (uint2*)(whi + 0 * DIM * DIM), (uint2*)(wlo + 0 * DIM * DIM), n4w);
    split_kernel<<<n4w / 256, 256>>>((const float4*)Wk, (uint2*)(whi + 1 * DIM * DIM), (uint2*)(wlo + 1 * DIM * DIM), n4w);
    split_kernel<<<n4w / 256, 256>>>((const float4*)Wv, (uint2*)(whi + 2 * DIM * DIM), (uint2*)(wlo + 2 * DIM * DIM), n4w);
    split_kernel<<<n4w / 256, 256>>>((const float4*)Wo, (uint2*)(whi + 3 * DIM * DIM), (uint2*)(wlo + 3 * DIM * DIM), n4w);

    dim3 ggrid(DIM / 128, MTOT / 128);   // (8, 64)
    gemm_hmma_kernel<<<ggrid, 256, GEMM_SMEM>>>(xhi, xlo, whi + 0 * DIM * DIM, wlo + 0 * DIM * DIM, nullptr, q16);
    gemm_hmma_kernel<<<ggrid, 256, GEMM_SMEM>>>(xhi, xlo, whi + 1 * DIM * DIM, wlo + 1 * DIM * DIM, nullptr, k16);
    gemm_hmma_kernel<<<ggrid, 256, GEMM_SMEM>>>(xhi, xlo, whi + 2 * DIM * DIM, wlo + 2 * DIM * DIM, nullptr, v16);

    dim3 agrid(NBLK, NHEAD, BATCH);      // (64, 16, 2)
    attn_hmma_kernel<<<agrid, 128, ATTN_SMEM>>>(q16, k16, v16, xhi, xlo);

    gemm_hmma_kernel<<<ggrid, 256, GEMM_SMEM>>>(xhi, xlo, whi + 3 * DIM * DIM, wlo + 3 * DIM * DIM, out, nullptr);
}

// round 7
// speedup vs baseline: 3.0000x; 1.0385x over previous
#include <cuda_runtime.h>
#include <cuda_bf16.h>
#include <cuda_fp16.h>
#include <cstdint>

// Problem constants: B=2, T=4096, D=1024, H=16, hd=64, WIN=512, BS=64
#define DIM   1024
#define HD    64
#define NHEAD 16
#define TLEN  4096
#define BATCH 2
#define MTOT  (BATCH * TLEN)      // 8192
#define NBLK  (TLEN / 64)
#define SCALE 0.125f

// ---------------- scratch (device globals; allocation-free rule) ----------------
__device__ float g_q[MTOT * DIM];   // reused as __half q16
__device__ float g_k[MTOT * DIM];   // reused as __half k16
__device__ float g_v[MTOT * DIM];   // reused as __half v16
__device__ unsigned short g_xhi[MTOT * DIM];   // x hi; later attn-out hi
__device__ unsigned short g_xlo[MTOT * DIM];   // x lo; later attn-out lo
__device__ unsigned short g_whi[4 * DIM * DIM];
__device__ unsigned short g_wlo[4 * DIM * DIM];

// ---------------- helpers ----------------
__device__ __forceinline__ uint32_t smem_u32(const void* p) {
    uint32_t a;
    asm("{ .reg .u64 t; cvta.to.shared.u64 t, %1; cvt.u32.u64 %0, t; }" : "=r"(a) : "l"(p));
    return a;
}
__device__ __forceinline__ void cp16(uint32_t saddr, const void* g) {
    asm volatile("cp.async.cg.shared.global [%0], [%1], 16;" :: "r"(saddr), "l"(g));
}
#define CP_COMMIT() asm volatile("cp.async.commit_group;" ::: "memory")
#define CP_WAIT(n)  asm volatile("cp.async.wait_group %0;" :: "n"(n) : "memory")

__device__ __forceinline__ void ldsm4(uint32_t& r0, uint32_t& r1, uint32_t& r2, uint32_t& r3, uint32_t addr) {
    asm volatile("ldmatrix.sync.aligned.m8n8.x4.shared.b16 {%0,%1,%2,%3}, [%4];"
                 : "=r"(r0), "=r"(r1), "=r"(r2), "=r"(r3) : "r"(addr));
}
__device__ __forceinline__ void ldsm4t(uint32_t& r0, uint32_t& r1, uint32_t& r2, uint32_t& r3, uint32_t addr) {
    asm volatile("ldmatrix.sync.aligned.m8n8.x4.trans.shared.b16 {%0,%1,%2,%3}, [%4];"
                 : "=r"(r0), "=r"(r1), "=r"(r2), "=r"(r3) : "r"(addr));
}
__device__ __forceinline__ void mma_bf16(float* c, const uint32_t* a, const uint32_t* b) {
    asm volatile("mma.sync.aligned.m16n8k16.row.col.f32.bf16.bf16.f32 "
                 "{%0,%1,%2,%3}, {%4,%5,%6,%7}, {%8,%9}, {%0,%1,%2,%3};"
                 : "+f"(c[0]), "+f"(c[1]), "+f"(c[2]), "+f"(c[3])
                 : "r"(a[0]), "r"(a[1]), "r"(a[2]), "r"(a[3]), "r"(b[0]), "r"(b[1]));
}
__device__ __forceinline__ void mma_f16(float* c, const uint32_t* a, const uint32_t* b) {
    asm volatile("mma.sync.aligned.m16n8k16.row.col.f32.f16.f16.f32 "
                 "{%0,%1,%2,%3}, {%4,%5,%6,%7}, {%8,%9}, {%0,%1,%2,%3};"
                 : "+f"(c[0]), "+f"(c[1]), "+f"(c[2]), "+f"(c[3])
                 : "r"(a[0]), "r"(a[1]), "r"(a[2]), "r"(a[3]), "r"(b[0]), "r"(b[1]));
}

// ---------------- fp32 -> bf16 hi/lo split ----------------
__global__ __launch_bounds__(256) void split_kernel(
    const float4* __restrict__ src, uint2* __restrict__ hi, uint2* __restrict__ lo, int n4)
{
    int i = blockIdx.x * blockDim.x + threadIdx.x;
    if (i >= n4) return;
    float4 v = src[i];
    float f[4] = {v.x, v.y, v.z, v.w};
    uint32_t hs[4], ls[4];
#pragma unroll
    for (int j = 0; j < 4; ++j) {
        __nv_bfloat16 h = __float2bfloat16(f[j]);
        float r = f[j] - __bfloat162float(h);
        __nv_bfloat16 l = __float2bfloat16(r);
        hs[j] = (uint32_t)*reinterpret_cast<unsigned short*>(&h);
        ls[j] = (uint32_t)*reinterpret_cast<unsigned short*>(&l);
    }
    uint2 H, L;
    H.x = hs[0] | (hs[1] << 16); H.y = hs[2] | (hs[3] << 16);
    L.x = ls[0] | (ls[1] << 16); L.y = ls[2] | (ls[3] << 16);
    hi[i] = H; lo[i] = L;
}

// ---------------- HMMA bf16x3 GEMM: C[M,N] = A @ B^T ----------------
// CTA 128x128, BK=32, 16 warps (4x4), warp tile 32x32. 3-stage cp.async pipeline.
// Single __syncthreads per k-iter: wait -> sync -> issue(it+2) -> compute.
#define T_STRIDE 80
#define TILE_BYTES (128 * T_STRIDE)          // 10240
#define STAGE_BYTES (4 * TILE_BYTES)         // 40960
#define GEMM_SMEM (3 * STAGE_BYTES)          // 122880

__device__ __forceinline__ void load_tile_ca(
    const unsigned short* __restrict__ G, int row0, int k0, uint32_t stile, int tid)
{
    // 512 float4 tasks, 512 threads -> 1 task each
    int r  = tid >> 2;
    int ch = tid & 3;
    cp16(stile + (uint32_t)(r * T_STRIDE + ch * 16),
         G + (size_t)(row0 + r) * 1024 + k0 + ch * 8);
}

__global__ __launch_bounds__(512, 1) void gemm_hmma_kernel(
    const unsigned short* __restrict__ Ahi, const unsigned short* __restrict__ Alo,
    const unsigned short* __restrict__ Bhi, const unsigned short* __restrict__ Blo,
    float* __restrict__ Cf, __half* __restrict__ Ch)
{
    extern __shared__ char gsm[];
    const uint32_t sbase = smem_u32(gsm);
    const int tid  = threadIdx.x;
    const int wid  = tid >> 5;
    const int lane = tid & 31;
    const int warp_m = wid >> 2;          // 0..3 -> rows warp_m*32
    const int warp_n = wid & 3;           // 0..3 -> cols warp_n*32
    const int bm = blockIdx.y * 128;
    const int bn = blockIdx.x * 128;

    float acc[2][4][4];
#pragma unroll
    for (int i = 0; i < 2; ++i)
#pragma unroll
        for (int j = 0; j < 4; ++j)
#pragma unroll
            for (int e = 0; e < 4; ++e) acc[i][j][e] = 0.f;

    const int a_r = lane & 15;
    const int a_c = lane >> 4;
    const int b_r = (lane & 7) + ((lane & 16) >> 1);
    const int b_c = (lane >> 3) & 1;

    const int NIT = 1024 / 32;   // 32

    // prologue: stages 0,1
#pragma unroll
    for (int s = 0; s < 2; ++s) {
        const uint32_t st = sbase + (uint32_t)s * STAGE_BYTES;
        const int k0 = s * 32;
        load_tile_ca(Ahi, bm, k0, st + 0 * TILE_BYTES, tid);
        load_tile_ca(Alo, bm, k0, st + 1 * TILE_BYTES, tid);
        load_tile_ca(Bhi, bn, k0, st + 2 * TILE_BYTES, tid);
        load_tile_ca(Blo, bn, k0, st + 3 * TILE_BYTES, tid);
        CP_COMMIT();
    }

    int buf = 0, nbuf = 2;   // nbuf = (it+2)%3
    for (int it = 0; it < NIT; ++it) {
        // ensure stage `it` arrived
        if (it < NIT - 1) { CP_WAIT(1); } else { CP_WAIT(0); }
        __syncthreads();
        // issue stage it+2 into buffer (it+2)%3 = (it-1)%3 — all warps are
        // past compute(it-1) due to the sync above, so the WAR is closed.
        if (it + 2 < NIT) {
            const uint32_t st = sbase + (uint32_t)nbuf * STAGE_BYTES;
            const int k0 = (it + 2) * 32;
            load_tile_ca(Ahi, bm, k0, st + 0 * TILE_BYTES, tid);
            load_tile_ca(Alo, bm, k0, st + 1 * TILE_BYTES, tid);
            load_tile_ca(Bhi, bn, k0, st + 2 * TILE_BYTES, tid);
            load_tile_ca(Blo, bn, k0, st + 3 * TILE_BYTES, tid);
            CP_COMMIT();
        }

        const uint32_t st = sbase + (uint32_t)buf * STAGE_BYTES;
        const uint32_t sAh = st + 0 * TILE_BYTES;
        const uint32_t sAl = st + 1 * TILE_BYTES;
        const uint32_t sBh = st + 2 * TILE_BYTES;
        const uint32_t sBl = st + 3 * TILE_BYTES;

#pragma unroll
        for (int ks = 0; ks < 2; ++ks) {
            uint32_t ah[2][4], al[2][4], bh[4][2], bl[4][2];
#pragma unroll
            for (int mf = 0; mf < 2; ++mf) {
                const uint32_t off = (uint32_t)((warp_m * 32 + mf * 16 + a_r) * T_STRIDE + ks * 32 + a_c * 16);
                ldsm4(ah[mf][0], ah[mf][1], ah[mf][2], ah[mf][3], sAh + off);
                ldsm4(al[mf][0], al[mf][1], al[mf][2], al[mf][3], sAl + off);
            }
#pragma unroll
            for (int bf = 0; bf < 2; ++bf) {
                const uint32_t off = (uint32_t)((warp_n * 32 + bf * 16 + b_r) * T_STRIDE + ks * 32 + b_c * 16);
                ldsm4(bh[2 * bf][0], bh[2 * bf][1], bh[2 * bf + 1][0], bh[2 * bf + 1][1], sBh + off);
                ldsm4(bl[2 * bf][0], bl[2 * bf][1], bl[2 * bf + 1][0], bl[2 * bf + 1][1], sBl + off);
            }
#pragma unroll
            for (int mf = 0; mf < 2; ++mf)
#pragma unroll
                for (int nf = 0; nf < 4; ++nf)
                    mma_bf16(acc[mf][nf], ah[mf], bh[nf]);
#pragma unroll
            for (int mf = 0; mf < 2; ++mf)
#pragma unroll
                for (int nf = 0; nf < 4; ++nf)
                    mma_bf16(acc[mf][nf], ah[mf], bl[nf]);
#pragma unroll
            for (int mf = 0; mf < 2; ++mf)
#pragma unroll
                for (int nf = 0; nf < 4; ++nf)
                    mma_bf16(acc[mf][nf], al[mf], bh[nf]);
        }

        buf = (buf + 1 == 3) ? 0 : buf + 1;
        nbuf = (nbuf + 1 == 3) ? 0 : nbuf + 1;
    }

    const int er = lane >> 2;
    const int ec = (lane & 3) * 2;
    if (Ch) {
#pragma unroll
        for (int mf = 0; mf < 2; ++mf)
#pragma unroll
            for (int nf = 0; nf < 4; ++nf) {
                const size_t row = (size_t)(bm + warp_m * 32 + mf * 16 + er);
                const int col = bn + warp_n * 32 + nf * 8 + ec;
                __half2 h01 = __floats2half2_rn(acc[mf][nf][0], acc[mf][nf][1]);
                __half2 h23 = __floats2half2_rn(acc[mf][nf][2], acc[mf][nf][3]);
                *(uint32_t*)&Ch[row * 1024 + col]       = *(uint32_t*)&h01;
                *(uint32_t*)&Ch[(row + 8) * 1024 + col] = *(uint32_t*)&h23;
            }
    } else {
#pragma unroll
        for (int mf = 0; mf < 2; ++mf)
#pragma unroll
            for (int nf = 0; nf < 4; ++nf) {
                const size_t row = (size_t)(bm + warp_m * 32 + mf * 16 + er);
                const int col = bn + warp_n * 32 + nf * 8 + ec;
                *(float2*)&Cf[row * 1024 + col]       = make_float2(acc[mf][nf][0], acc[mf][nf][1]);
                *(float2*)&Cf[(row + 8) * 1024 + col] = make_float2(acc[mf][nf][2], acc[mf][nf][3]);
            }
    }
}

// ---------------- fp16 HMMA flash attention (banded, causal) ----------------
// Unchanged from round 6 (passing). CTA per (qblock n, head h, batch b).
// 4 warps x 16 rows. THREE-stage cp.async K/V pipeline.
#define ASTR 144
#define ATTN_STAGE(s) (9216u + (uint32_t)(s) * 18432u)
#define ATTN_SMEM (9216 + 3 * 18432)   // 64512

__global__ __launch_bounds__(128) void attn_hmma_kernel(
    const __half* __restrict__ qg, const __half* __restrict__ kg,
    const __half* __restrict__ vg,
    unsigned short* __restrict__ ahi, unsigned short* __restrict__ alo)
{
    extern __shared__ char smb[];
    const uint32_t sb = smem_u32(smb);
    const int tid = threadIdx.x;
    const int wid = tid >> 5;
    const int lane = tid & 31;
    const int n = blockIdx.x, h = blockIdx.y, b = blockIdx.z;

    const size_t qbase = ((size_t)(b * TLEN + n * 64)) * DIM + h * HD;

#pragma unroll
    for (int i = 0; i < 4; ++i) {
        int idx = tid + i * 128;
        int r = idx >> 3, ch = idx & 7;
        cp16(sb + (uint32_t)(r * ASTR + ch * 16), qg + qbase + (size_t)r * DIM + ch * 8);
    }
    CP_COMMIT();

    const int jb0 = (n >= 8) ? n - 8 : 0;
    const int NB = n - jb0 + 1;

    auto issue = [&](int i) {
        const int jb = jb0 + i;
        const size_t kb = ((size_t)(b * TLEN + jb * 64)) * DIM + h * HD;
        const uint32_t st = sb + ATTN_STAGE(i % 3);
#pragma unroll
        for (int t = 0; t < 4; ++t) {
            int idx = tid + t * 128;
            int r = idx >> 3, ch = idx & 7;
            cp16(st + (uint32_t)(r * ASTR + ch * 16), kg + kb + (size_t)r * DIM + ch * 8);
            cp16(st + 9216u + (uint32_t)(r * ASTR + ch * 16), vg + kb + (size_t)r * DIM + ch * 8);
        }
        CP_COMMIT();
    };

    issue(0);
    if (NB > 1) issue(1);

    const int a_r = lane & 15, a_c = lane >> 4;
    const int b_r = (lane & 7) + ((lane & 16) >> 1), b_c = (lane >> 3) & 1;
    const int er = lane >> 2, ec = 2 * (lane & 3);
    const int r0 = wid * 16 + er, r1 = r0 + 8;

    float m0 = -1e9f, m1 = -1e9f, l0 = 0.f, l1 = 0.f;
    float of[8][4];
#pragma unroll
    for (int nf = 0; nf < 8; ++nf)
#pragma unroll
        for (int e = 0; e < 4; ++e) of[nf][e] = 0.f;
    uint32_t qf[4][4];

    for (int i = 0; i < NB; ++i) {
        if (i + 2 < NB) issue(i + 2);
        if (i + 2 < NB)      CP_WAIT(2);
        else if (i + 1 < NB) CP_WAIT(1);
        else                 CP_WAIT(0);
        __syncthreads();

        if (i == 0) {
#pragma unroll
            for (int ks = 0; ks < 4; ++ks)
                ldsm4(qf[ks][0], qf[ks][1], qf[ks][2], qf[ks][3],
                      sb + (uint32_t)((wid * 16 + a_r) * ASTR + ks * 32 + a_c * 16));
        }

        const int off = (jb0 + i) - n;
        const uint32_t Kst = sb + ATTN_STAGE(i % 3);
        const uint32_t Vst = Kst + 9216u;

        float sf[8][4];
#pragma unroll
        for (int nf = 0; nf < 8; ++nf)
#pragma unroll
            for (int e = 0; e < 4; ++e) sf[nf][e] = 0.f;
#pragma unroll
        for (int ks = 0; ks < 4; ++ks) {
            uint32_t kf[8][2];
#pragma unroll
            for (int bf = 0; bf < 4; ++bf)
                ldsm4(kf[2 * bf][0], kf[2 * bf][1], kf[2 * bf + 1][0], kf[2 * bf + 1][1],
                      Kst + (uint32_t)((bf * 16 + b_r) * ASTR + ks * 32 + b_c * 16));
#pragma unroll
            for (int nf = 0; nf < 8; ++nf)
                mma_f16(sf[nf], qf[ks], kf[nf]);
        }

#pragma unroll
        for (int nf = 0; nf < 8; ++nf) {
#pragma unroll
            for (int e = 0; e < 4; ++e) {
                int row = (e < 2) ? r0 : r1;
                int c = nf * 8 + ec + (e & 1);
                float sv = sf[nf][e] * SCALE;
                bool valid = (off == 0) ? (c <= row) : ((off == -8) ? (row < c) : true);
                sf[nf][e] = valid ? sv : -1e9f;
            }
        }

        float mx0 = sf[0][0], mx1 = sf[0][2];
#pragma unroll
        for (int nf = 0; nf < 8; ++nf) {
            mx0 = fmaxf(mx0, fmaxf(sf[nf][0], sf[nf][1]));
            mx1 = fmaxf(mx1, fmaxf(sf[nf][2], sf[nf][3]));
        }
        mx0 = fmaxf(mx0, __shfl_xor_sync(0xffffffffu, mx0, 1));
        mx0 = fmaxf(mx0, __shfl_xor_sync(0xffffffffu, mx0, 2));
        mx1 = fmaxf(mx1, __shfl_xor_sync(0xffffffffu, mx1, 1));
        mx1 = fmaxf(mx1, __shfl_xor_sync(0xffffffffu, mx1, 2));
        float mn0 = fmaxf(m0, mx0), mn1 = fmaxf(m1, mx1);
        float cf0 = __expf(m0 - mn0), cf1 = __expf(m1 - mn1);
        m0 = mn0; m1 = mn1;

        float s0 = 0.f, s1 = 0.f;
        uint32_t pf[4][4];
#pragma unroll
        for (int nf = 0; nf < 8; ++nf) {
            float p0 = __expf(sf[nf][0] - m0);
            float p1 = __expf(sf[nf][1] - m0);
            float p2 = __expf(sf[nf][2] - m1);
            float p3 = __expf(sf[nf][3] - m1);
            s0 += p0 + p1; s1 += p2 + p3;
            __half2 h01 = __floats2half2_rn(p0, p1);
            __half2 h23 = __floats2half2_rn(p2, p3);
            pf[nf >> 1][(nf & 1) * 2 + 0] = *(uint32_t*)&h01;
            pf[nf >> 1][(nf & 1) * 2 + 1] = *(uint32_t*)&h23;
        }
        l0 = l0 * cf0 + s0; l1 = l1 * cf1 + s1;
#pragma unroll
        for (int nf = 0; nf < 8; ++nf) {
            of[nf][0] *= cf0; of[nf][1] *= cf0;
            of[nf][2] *= cf1; of[nf][3] *= cf1;
        }

#pragma unroll
        for (int ks = 0; ks < 4; ++ks) {
            uint32_t vf[8][2];
#pragma unroll
            for (int nfp = 0; nfp < 4; ++nfp)
                ldsm4t(vf[2 * nfp][0], vf[2 * nfp][1], vf[2 * nfp + 1][0], vf[2 * nfp + 1][1],
                       Vst + (uint32_t)((ks * 16 + (lane & 15)) * ASTR + (nfp * 2 + (lane >> 4)) * 16));
#pragma unroll
            for (int nf = 0; nf < 8; ++nf)
                mma_f16(of[nf], pf[ks], vf[nf]);
        }
        __syncthreads();
    }

    l0 += __shfl_xor_sync(0xffffffffu, l0, 1);
    l0 += __shfl_xor_sync(0xffffffffu, l0, 2);
    l1 += __shfl_xor_sync(0xffffffffu, l1, 1);
    l1 += __shfl_xor_sync(0xffffffffu, l1, 2);
    const float i0 = 1.f / l0, i1 = 1.f / l1;
    const size_t row0 = (size_t)(b * TLEN + n * 64 + r0);
    const size_t row1 = row0 + 8;
#pragma unroll
    for (int nf = 0; nf < 8; ++nf) {
        const int col = h * HD + nf * 8 + ec;
        float o[4] = {of[nf][0] * i0, of[nf][1] * i0, of[nf][2] * i1, of[nf][3] * i1};
        uint32_t hs[4], ls[4];
#pragma unroll
        for (int e = 0; e < 4; ++e) {
            __nv_bfloat16 hb = __float2bfloat16(o[e]);
            __nv_bfloat16 lb = __float2bfloat16(o[e] - __bfloat162float(hb));
            hs[e] = (uint32_t)*reinterpret_cast<unsigned short*>(&hb);
            ls[e] = (uint32_t)*reinterpret_cast<unsigned short*>(&lb);
        }
        *(uint32_t*)&ahi[row0 * DIM + col] = hs[0] | (hs[1] << 16);
        *(uint32_t*)&alo[row0 * DIM + col] = ls[0] | (ls[1] << 16);
        *(uint32_t*)&ahi[row1 * DIM + col] = hs[2] | (hs[3] << 16);
        *(uint32_t*)&alo[row1 * DIM + col] = ls[2] | (ls[3] << 16);
    }
}

// ---------------- launch ----------------
extern "C" void kernel_launch(void* const* d_in, const int* in_sizes, int n_in,
                              void* d_out, int out_size)
{
    const float* x  = (const float*)d_in[0];
    const float* Wq = (const float*)d_in[1];
    const float* Wk = (const float*)d_in[2];
    const float* Wv = (const float*)d_in[3];
    const float* Wo = (const float*)d_in[4];
    float* out = (float*)d_out;

    void *qv, *kv, *vv;
    unsigned short *xhi, *xlo, *whi, *wlo;
    cudaGetSymbolAddress(&qv, g_q);
    cudaGetSymbolAddress(&kv, g_k);
    cudaGetSymbolAddress(&vv, g_v);
    cudaGetSymbolAddress((void**)&xhi, g_xhi);
    cudaGetSymbolAddress((void**)&xlo, g_xlo);
    cudaGetSymbolAddress((void**)&whi, g_whi);
    cudaGetSymbolAddress((void**)&wlo, g_wlo);
    __half* q16 = (__half*)qv;
    __half* k16 = (__half*)kv;
    __half* v16 = (__half*)vv;

    cudaFuncSetAttribute(gemm_hmma_kernel, cudaFuncAttributeMaxDynamicSharedMemorySize, GEMM_SMEM);
    cudaFuncSetAttribute(attn_hmma_kernel, cudaFuncAttributeMaxDynamicSharedMemorySize, ATTN_SMEM);

    const int n4x = MTOT * DIM / 4;
    const int n4w = DIM * DIM / 4;

    split_kernel<<<n4x / 256, 256>>>((const float4*)x, (uint2*)xhi, (uint2*)xlo, n4x);
    split_kernel<<<n4w / 256, 256>>>((const float4*)Wq, (uint2*)(whi + 0 * DIM * DIM), (uint2*)(wlo + 0 * DIM * DIM), n4w);
    split_kernel<<<n4w / 256, 256>>>((const float4*)Wk, (uint2*)(whi + 1 * DIM * DIM), (uint2*)(wlo + 1 * DIM * DIM), n4w);
    split_kernel<<<n4w / 256, 256>>>((const float4*)Wv, (uint2*)(whi + 2 * DIM * DIM), (uint2*)(wlo + 2 * DIM * DIM), n4w);
    split_kernel<<<n4w / 256, 256>>>((const float4*)Wo, (uint2*)(whi + 3 * DIM * DIM), (uint2*)(wlo + 3 * DIM * DIM), n4w);

    dim3 ggrid(DIM / 128, MTOT / 128);   // (8, 64)
    gemm_hmma_kernel<<<ggrid, 512, GEMM_SMEM>>>(xhi, xlo, whi + 0 * DIM * DIM, wlo + 0 * DIM * DIM, nullptr, q16);
    gemm_hmma_kernel<<<ggrid, 512, GEMM_SMEM>>>(xhi, xlo, whi + 1 * DIM * DIM, wlo + 1 * DIM * DIM, nullptr, k16);
    gemm_hmma_kernel<<<ggrid, 512, GEMM_SMEM>>>(xhi, xlo, whi + 2 * DIM * DIM, wlo + 2 * DIM * DIM, nullptr, v16);

    dim3 agrid(NBLK, NHEAD, BATCH);      // (64, 16, 2)
    attn_hmma_kernel<<<agrid, 128, ATTN_SMEM>>>(q16, k16, v16, xhi, xlo);

    gemm_hmma_kernel<<<ggrid, 512, GEMM_SMEM>>>(xhi, xlo, whi + 3 * DIM * DIM, wlo + 3 * DIM * DIM, out, nullptr);
}

// round 9
// speedup vs baseline: 3.7982x; 1.2661x over previous
#include <cuda_runtime.h>
#include <cuda_fp16.h>
#include <cstdint>

// Problem constants: B=2, T=4096, D=1024, H=16, hd=64, WIN=512, BS=64
#define DIM   1024
#define HD    64
#define NHEAD 16
#define TLEN  4096
#define BATCH 2
#define MTOT  (BATCH * TLEN)      // 8192
#define NBLK  (TLEN / 64)
#define SCALE 0.125f

// ---------------- scratch (device globals; allocation-free rule) ----------------
__device__ unsigned short g_q[MTOT * DIM];     // half q16
__device__ unsigned short g_k[MTOT * DIM];     // half k16
__device__ unsigned short g_v[MTOT * DIM];     // half v16
__device__ unsigned short g_x16[MTOT * DIM];   // half x
__device__ unsigned short g_a16[MTOT * DIM];   // half attn out
__device__ unsigned short g_whi[4 * DIM * DIM];
__device__ unsigned short g_wlo[4 * DIM * DIM];

// ---------------- helpers ----------------
__device__ __forceinline__ uint32_t smem_u32(const void* p) {
    uint32_t a;
    asm("{ .reg .u64 t; cvta.to.shared.u64 t, %1; cvt.u32.u64 %0, t; }" : "=r"(a) : "l"(p));
    return a;
}
__device__ __forceinline__ void cp16(uint32_t saddr, const void* g) {
    asm volatile("cp.async.cg.shared.global [%0], [%1], 16;" :: "r"(saddr), "l"(g));
}
#define CP_COMMIT() asm volatile("cp.async.commit_group;" ::: "memory")
#define CP_WAIT(n)  asm volatile("cp.async.wait_group %0;" :: "n"(n) : "memory")

__device__ __forceinline__ void ldsm4(uint32_t& r0, uint32_t& r1, uint32_t& r2, uint32_t& r3, uint32_t addr) {
    asm volatile("ldmatrix.sync.aligned.m8n8.x4.shared.b16 {%0,%1,%2,%3}, [%4];"
                 : "=r"(r0), "=r"(r1), "=r"(r2), "=r"(r3) : "r"(addr));
}
__device__ __forceinline__ void ldsm4t(uint32_t& r0, uint32_t& r1, uint32_t& r2, uint32_t& r3, uint32_t addr) {
    asm volatile("ldmatrix.sync.aligned.m8n8.x4.trans.shared.b16 {%0,%1,%2,%3}, [%4];"
                 : "=r"(r0), "=r"(r1), "=r"(r2), "=r"(r3) : "r"(addr));
}
__device__ __forceinline__ void mma_f16(float* c, const uint32_t* a, const uint32_t* b) {
    asm volatile("mma.sync.aligned.m16n8k16.row.col.f32.f16.f16.f32 "
                 "{%0,%1,%2,%3}, {%4,%5,%6,%7}, {%8,%9}, {%0,%1,%2,%3};"
                 : "+f"(c[0]), "+f"(c[1]), "+f"(c[2]), "+f"(c[3])
                 : "r"(a[0]), "r"(a[1]), "r"(a[2]), "r"(a[3]), "r"(b[0]), "r"(b[1]));
}

// ---------------- fp32 -> fp16 convert (activations) ----------------
__global__ __launch_bounds__(256) void cvt_half_kernel(
    const float4* __restrict__ src, uint2* __restrict__ dst, int n4)
{
    int i = blockIdx.x * blockDim.x + threadIdx.x;
    if (i >= n4) return;
    float4 v = src[i];
    __half2 h01 = __floats2half2_rn(v.x, v.y);
    __half2 h23 = __floats2half2_rn(v.z, v.w);
    uint2 o;
    o.x = *(uint32_t*)&h01;
    o.y = *(uint32_t*)&h23;
    dst[i] = o;
}

// ---------------- fp32 -> fp16 hi/lo split (weights) ----------------
__global__ __launch_bounds__(256) void split_w_kernel(
    const float4* __restrict__ src, uint2* __restrict__ hi, uint2* __restrict__ lo, int n4)
{
    int i = blockIdx.x * blockDim.x + threadIdx.x;
    if (i >= n4) return;
    float4 v = src[i];
    float f[4] = {v.x, v.y, v.z, v.w};
    __half h[4], l[4];
#pragma unroll
    for (int j = 0; j < 4; ++j) {
        h[j] = __float2half_rn(f[j]);
        l[j] = __float2half_rn(f[j] - __half2float(h[j]));
    }
    uint2 H, L;
    H.x = ((uint32_t)*(unsigned short*)&h[0]) | ((uint32_t)*(unsigned short*)&h[1] << 16);
    H.y = ((uint32_t)*(unsigned short*)&h[2]) | ((uint32_t)*(unsigned short*)&h[3] << 16);
    L.x = ((uint32_t)*(unsigned short*)&l[0]) | ((uint32_t)*(unsigned short*)&l[1] << 16);
    L.y = ((uint32_t)*(unsigned short*)&l[2]) | ((uint32_t)*(unsigned short*)&l[3] << 16);
    hi[i] = H; lo[i] = L;
}

// ---------------- HMMA fp16x2 GEMM: C[M,N] = A @ (Whi+Wlo)^T ----------------
// CTA 128x128, BK=32, 8 warps (2x4), warp tile 64x32. 3-stage cp.async pipeline,
// single __syncthreads per k-iter (wait -> sync -> issue(it+2) -> compute).
// Stage tiles: A, Bhi, Blo (each 128 rows x 80B).
#define T_STRIDE 80
#define TILE_BYTES (128 * T_STRIDE)          // 10240
#define STAGE_BYTES (3 * TILE_BYTES)         // 30720
#define GEMM_SMEM (3 * STAGE_BYTES)          // 92160

__device__ __forceinline__ void load_tile_ca(
    const unsigned short* __restrict__ G, int row0, int k0, uint32_t stile, int tid)
{
#pragma unroll
    for (int h = 0; h < 2; ++h) {
        int idx = tid + h * 256;          // 0..511
        int r   = idx >> 2;
        int ch  = idx & 3;
        cp16(stile + (uint32_t)(r * T_STRIDE + ch * 16),
             G + (size_t)(row0 + r) * 1024 + k0 + ch * 8);
    }
}

__global__ __launch_bounds__(256, 1) void gemm_f16x2_kernel(
    const unsigned short* __restrict__ A,
    const unsigned short* __restrict__ Bhi, const unsigned short* __restrict__ Blo,
    float* __restrict__ Cf, __half* __restrict__ Ch)
{
    extern __shared__ char gsm[];
    const uint32_t sbase = smem_u32(gsm);
    const int tid  = threadIdx.x;
    const int wid  = tid >> 5;
    const int lane = tid & 31;
    const int warp_m = wid >> 2;          // 0..1 -> rows warp_m*64
    const int warp_n = wid & 3;           // 0..3 -> cols warp_n*32
    const int bm = blockIdx.y * 128;
    const int bn = blockIdx.x * 128;

    float acc[4][4][4];
#pragma unroll
    for (int i = 0; i < 4; ++i)
#pragma unroll
        for (int j = 0; j < 4; ++j)
#pragma unroll
            for (int e = 0; e < 4; ++e) acc[i][j][e] = 0.f;

    const int a_r = lane & 15;
    const int a_c = lane >> 4;
    const int b_r = (lane & 7) + ((lane & 16) >> 1);
    const int b_c = (lane >> 3) & 1;

    const int NIT = 1024 / 32;   // 32

    // prologue: stages 0,1
#pragma unroll
    for (int s = 0; s < 2; ++s) {
        const uint32_t st = sbase + (uint32_t)s * STAGE_BYTES;
        const int k0 = s * 32;
        load_tile_ca(A,   bm, k0, st + 0 * TILE_BYTES, tid);
        load_tile_ca(Bhi, bn, k0, st + 1 * TILE_BYTES, tid);
        load_tile_ca(Blo, bn, k0, st + 2 * TILE_BYTES, tid);
        CP_COMMIT();
    }

    int buf = 0, nbuf = 2;
    for (int it = 0; it < NIT; ++it) {
        if (it < NIT - 1) { CP_WAIT(1); } else { CP_WAIT(0); }
        __syncthreads();
        // issue stage it+2 into (it+2)%3 = (it-1)%3 — all warps are past
        // compute(it-1) due to the sync above, closing the WAR hazard.
        if (it + 2 < NIT) {
            const uint32_t st = sbase + (uint32_t)nbuf * STAGE_BYTES;
            const int k0 = (it + 2) * 32;
            load_tile_ca(A,   bm, k0, st + 0 * TILE_BYTES, tid);
            load_tile_ca(Bhi, bn, k0, st + 1 * TILE_BYTES, tid);
            load_tile_ca(Blo, bn, k0, st + 2 * TILE_BYTES, tid);
            CP_COMMIT();
        }

        const uint32_t st = sbase + (uint32_t)buf * STAGE_BYTES;
        const uint32_t sA  = st + 0 * TILE_BYTES;
        const uint32_t sBh = st + 1 * TILE_BYTES;
        const uint32_t sBl = st + 2 * TILE_BYTES;

#pragma unroll
        for (int ks = 0; ks < 2; ++ks) {
            uint32_t af[4][4], bh[4][2], bl[4][2];
#pragma unroll
            for (int mf = 0; mf < 4; ++mf) {
                const uint32_t off = (uint32_t)((warp_m * 64 + mf * 16 + a_r) * T_STRIDE + ks * 32 + a_c * 16);
                ldsm4(af[mf][0], af[mf][1], af[mf][2], af[mf][3], sA + off);
            }
#pragma unroll
            for (int bf = 0; bf < 2; ++bf) {
                const uint32_t off = (uint32_t)((warp_n * 32 + bf * 16 + b_r) * T_STRIDE + ks * 32 + b_c * 16);
                ldsm4(bh[2 * bf][0], bh[2 * bf][1], bh[2 * bf + 1][0], bh[2 * bf + 1][1], sBh + off);
                ldsm4(bl[2 * bf][0], bl[2 * bf][1], bl[2 * bf + 1][0], bl[2 * bf + 1][1], sBl + off);
            }
#pragma unroll
            for (int mf = 0; mf < 4; ++mf)
#pragma unroll
                for (int nf = 0; nf < 4; ++nf)
                    mma_f16(acc[mf][nf], af[mf], bh[nf]);
#pragma unroll
            for (int mf = 0; mf < 4; ++mf)
#pragma unroll
                for (int nf = 0; nf < 4; ++nf)
                    mma_f16(acc[mf][nf], af[mf], bl[nf]);
        }

        buf = (buf + 1 == 3) ? 0 : buf + 1;
        nbuf = (nbuf + 1 == 3) ? 0 : nbuf + 1;
    }

    const int er = lane >> 2;
    const int ec = (lane & 3) * 2;
    if (Ch) {
#pragma unroll
        for (int mf = 0; mf < 4; ++mf)
#pragma unroll
            for (int nf = 0; nf < 4; ++nf) {
                const size_t row = (size_t)(bm + warp_m * 64 + mf * 16 + er);
                const int col = bn + warp_n * 32 + nf * 8 + ec;
                __half2 h01 = __floats2half2_rn(acc[mf][nf][0], acc[mf][nf][1]);
                __half2 h23 = __floats2half2_rn(acc[mf][nf][2], acc[mf][nf][3]);
                *(uint32_t*)&Ch[row * 1024 + col]       = *(uint32_t*)&h01;
                *(uint32_t*)&Ch[(row + 8) * 1024 + col] = *(uint32_t*)&h23;
            }
    } else {
#pragma unroll
        for (int mf = 0; mf < 4; ++mf)
#pragma unroll
            for (int nf = 0; nf < 4; ++nf) {
                const size_t row = (size_t)(bm + warp_m * 64 + mf * 16 + er);
                const int col = bn + warp_n * 32 + nf * 8 + ec;
                *(float2*)&Cf[row * 1024 + col]       = make_float2(acc[mf][nf][0], acc[mf][nf][1]);
                *(float2*)&Cf[(row + 8) * 1024 + col] = make_float2(acc[mf][nf][2], acc[mf][nf][3]);
            }
    }
}

// ---------------- fp16 HMMA flash attention (banded, causal) ----------------
// CTA per (qblock n, head h, batch b). 4 warps x 16 rows.
// THREE-stage cp.async K/V pipeline. Output single fp16.
#define ASTR 144
#define ATTN_STAGE(s) (9216u + (uint32_t)(s) * 18432u)
#define ATTN_SMEM (9216 + 3 * 18432)   // 64512

__global__ __launch_bounds__(128) void attn_hmma_kernel(
    const __half* __restrict__ qg, const __half* __restrict__ kg,
    const __half* __restrict__ vg, __half* __restrict__ aout)
{
    extern __shared__ char smb[];
    const uint32_t sb = smem_u32(smb);
    const int tid = threadIdx.x;
    const int wid = tid >> 5;
    const int lane = tid & 31;
    const int n = blockIdx.x, h = blockIdx.y, b = blockIdx.z;

    const size_t qbase = ((size_t)(b * TLEN + n * 64)) * DIM + h * HD;

#pragma unroll
    for (int i = 0; i < 4; ++i) {
        int idx = tid + i * 128;
        int r = idx >> 3, ch = idx & 7;
        cp16(sb + (uint32_t)(r * ASTR + ch * 16), qg + qbase + (size_t)r * DIM + ch * 8);
    }
    CP_COMMIT();

    const int jb0 = (n >= 8) ? n - 8 : 0;
    const int NB = n - jb0 + 1;

    auto issue = [&](int i) {
        const int jb = jb0 + i;
        const size_t kb = ((size_t)(b * TLEN + jb * 64)) * DIM + h * HD;
        const uint32_t st = sb + ATTN_STAGE(i % 3);
#pragma unroll
        for (int t = 0; t < 4; ++t) {
            int idx = tid + t * 128;
            int r = idx >> 3, ch = idx & 7;
            cp16(st + (uint32_t)(r * ASTR + ch * 16), kg + kb + (size_t)r * DIM + ch * 8);
            cp16(st + 9216u + (uint32_t)(r * ASTR + ch * 16), vg + kb + (size_t)r * DIM + ch * 8);
        }
        CP_COMMIT();
    };

    issue(0);
    if (NB > 1) issue(1);

    const int a_r = lane & 15, a_c = lane >> 4;
    const int b_r = (lane & 7) + ((lane & 16) >> 1), b_c = (lane >> 3) & 1;
    const int er = lane >> 2, ec = 2 * (lane & 3);
    const int r0 = wid * 16 + er, r1 = r0 + 8;

    float m0 = -1e9f, m1 = -1e9f, l0 = 0.f, l1 = 0.f;
    float of[8][4];
#pragma unroll
    for (int nf = 0; nf < 8; ++nf)
#pragma unroll
        for (int e = 0; e < 4; ++e) of[nf][e] = 0.f;
    uint32_t qf[4][4];

    for (int i = 0; i < NB; ++i) {
        if (i + 2 < NB) issue(i + 2);
        if (i + 2 < NB)      CP_WAIT(2);
        else if (i + 1 < NB) CP_WAIT(1);
        else                 CP_WAIT(0);
        __syncthreads();

        if (i == 0) {
#pragma unroll
            for (int ks = 0; ks < 4; ++ks)
                ldsm4(qf[ks][0], qf[ks][1], qf[ks][2], qf[ks][3],
                      sb + (uint32_t)((wid * 16 + a_r) * ASTR + ks * 32 + a_c * 16));
        }

        const int off = (jb0 + i) - n;
        const uint32_t Kst = sb + ATTN_STAGE(i % 3);
        const uint32_t Vst = Kst + 9216u;

        float sf[8][4];
#pragma unroll
        for (int nf = 0; nf < 8; ++nf)
#pragma unroll
            for (int e = 0; e < 4; ++e) sf[nf][e] = 0.f;
#pragma unroll
        for (int ks = 0; ks < 4; ++ks) {
            uint32_t kf[8][2];
#pragma unroll
            for (int bf = 0; bf < 4; ++bf)
                ldsm4(kf[2 * bf][0], kf[2 * bf][1], kf[2 * bf + 1][0], kf[2 * bf + 1][1],
                      Kst + (uint32_t)((bf * 16 + b_r) * ASTR + ks * 32 + b_c * 16));
#pragma unroll
            for (int nf = 0; nf < 8; ++nf)
                mma_f16(sf[nf], qf[ks], kf[nf]);
        }

#pragma unroll
        for (int nf = 0; nf < 8; ++nf) {
#pragma unroll
            for (int e = 0; e < 4; ++e) {
                int row = (e < 2) ? r0 : r1;
                int c = nf * 8 + ec + (e & 1);
                float sv = sf[nf][e] * SCALE;
                bool valid = (off == 0) ? (c <= row) : ((off == -8) ? (row < c) : true);
                sf[nf][e] = valid ? sv : -1e9f;
            }
        }

        float mx0 = sf[0][0], mx1 = sf[0][2];
#pragma unroll
        for (int nf = 0; nf < 8; ++nf) {
            mx0 = fmaxf(mx0, fmaxf(sf[nf][0], sf[nf][1]));
            mx1 = fmaxf(mx1, fmaxf(sf[nf][2], sf[nf][3]));
        }
        mx0 = fmaxf(mx0, __shfl_xor_sync(0xffffffffu, mx0, 1));
        mx0 = fmaxf(mx0, __shfl_xor_sync(0xffffffffu, mx0, 2));
        mx1 = fmaxf(mx1, __shfl_xor_sync(0xffffffffu, mx1, 1));
        mx1 = fmaxf(mx1, __shfl_xor_sync(0xffffffffu, mx1, 2));
        float mn0 = fmaxf(m0, mx0), mn1 = fmaxf(m1, mx1);
        float cf0 = __expf(m0 - mn0), cf1 = __expf(m1 - mn1);
        m0 = mn0; m1 = mn1;

        float s0 = 0.f, s1 = 0.f;
        uint32_t pf[4][4];
#pragma unroll
        for (int nf = 0; nf < 8; ++nf) {
            float p0 = __expf(sf[nf][0] - m0);
            float p1 = __expf(sf[nf][1] - m0);
            float p2 = __expf(sf[nf][2] - m1);
            float p3 = __expf(sf[nf][3] - m1);
            s0 += p0 + p1; s1 += p2 + p3;
            __half2 h01 = __floats2half2_rn(p0, p1);
            __half2 h23 = __floats2half2_rn(p2, p3);
            pf[nf >> 1][(nf & 1) * 2 + 0] = *(uint32_t*)&h01;
            pf[nf >> 1][(nf & 1) * 2 + 1] = *(uint32_t*)&h23;
        }
        l0 = l0 * cf0 + s0; l1 = l1 * cf1 + s1;
#pragma unroll
        for (int nf = 0; nf < 8; ++nf) {
            of[nf][0] *= cf0; of[nf][1] *= cf0;
            of[nf][2] *= cf1; of[nf][3] *= cf1;
        }

#pragma unroll
        for (int ks = 0; ks < 4; ++ks) {
            uint32_t vf[8][2];
#pragma unroll
            for (int nfp = 0; nfp < 4; ++nfp)
                ldsm4t(vf[2 * nfp][0], vf[2 * nfp][1], vf[2 * nfp + 1][0], vf[2 * nfp + 1][1],
                       Vst + (uint32_t)((ks * 16 + (lane & 15)) * ASTR + (nfp * 2 + (lane >> 4)) * 16));
#pragma unroll
            for (int nf = 0; nf < 8; ++nf)
                mma_f16(of[nf], pf[ks], vf[nf]);
        }
        __syncthreads();
    }

    l0 += __shfl_xor_sync(0xffffffffu, l0, 1);
    l0 += __shfl_xor_sync(0xffffffffu, l0, 2);
    l1 += __shfl_xor_sync(0xffffffffu, l1, 1);
    l1 += __shfl_xor_sync(0xffffffffu, l1, 2);
    const float i0 = 1.f / l0, i1 = 1.f / l1;
    const size_t row0 = (size_t)(b * TLEN + n * 64 + r0);
    const size_t row1 = row0 + 8;
#pragma unroll
    for (int nf = 0; nf < 8; ++nf) {
        const int col = h * HD + nf * 8 + ec;
        __half2 h01 = __floats2half2_rn(of[nf][0] * i0, of[nf][1] * i0);
        __half2 h23 = __floats2half2_rn(of[nf][2] * i1, of[nf][3] * i1);
        *(uint32_t*)&aout[row0 * DIM + col] = *(uint32_t*)&h01;
        *(uint32_t*)&aout[row1 * DIM + col] = *(uint32_t*)&h23;
    }
}

// ---------------- launch ----------------
extern "C" void kernel_launch(void* const* d_in, const int* in_sizes, int n_in,
                              void* d_out, int out_size)
{
    const float* x  = (const float*)d_in[0];
    const float* Wq = (const float*)d_in[1];
    const float* Wk = (const float*)d_in[2];
    const float* Wv = (const float*)d_in[3];
    const float* Wo = (const float*)d_in[4];
    float* out = (float*)d_out;

    unsigned short *q16, *k16, *v16, *x16, *a16, *whi, *wlo;
    cudaGetSymbolAddress((void**)&q16, g_q);
    cudaGetSymbolAddress((void**)&k16, g_k);
    cudaGetSymbolAddress((void**)&v16, g_v);
    cudaGetSymbolAddress((void**)&x16, g_x16);
    cudaGetSymbolAddress((void**)&a16, g_a16);
    cudaGetSymbolAddress((void**)&whi, g_whi);
    cudaGetSymbolAddress((void**)&wlo, g_wlo);

    cudaFuncSetAttribute(gemm_f16x2_kernel, cudaFuncAttributeMaxDynamicSharedMemorySize, GEMM_SMEM);
    cudaFuncSetAttribute(attn_hmma_kernel, cudaFuncAttributeMaxDynamicSharedMemorySize, ATTN_SMEM);

    const int n4x = MTOT * DIM / 4;   // 2M
    const int n4w = DIM * DIM / 4;    // 256K

    cvt_half_kernel<<<n4x / 256, 256>>>((const float4*)x, (uint2*)x16, n4x);
    split_w_kernel<<<n4w / 256, 256>>>((const float4*)Wq, (uint2*)(whi + 0 * DIM * DIM), (uint2*)(wlo + 0 * DIM * DIM), n4w);
    split_w_kernel<<<n4w / 256, 256>>>((const float4*)Wk, (uint2*)(whi + 1 * DIM * DIM), (uint2*)(wlo + 1 * DIM * DIM), n4w);
    split_w_kernel<<<n4w / 256, 256>>>((const float4*)Wv, (uint2*)(whi + 2 * DIM * DIM), (uint2*)(wlo + 2 * DIM * DIM), n4w);
    split_w_kernel<<<n4w / 256, 256>>>((const float4*)Wo, (uint2*)(whi + 3 * DIM * DIM), (uint2*)(wlo + 3 * DIM * DIM), n4w);

    dim3 ggrid(DIM / 128, MTOT / 128);   // (8, 64)
    gemm_f16x2_kernel<<<ggrid, 256, GEMM_SMEM>>>(x16, whi + 0 * DIM * DIM, wlo + 0 * DIM * DIM, nullptr, (__half*)q16);
    gemm_f16x2_kernel<<<ggrid, 256, GEMM_SMEM>>>(x16, whi + 1 * DIM * DIM, wlo + 1 * DIM * DIM, nullptr, (__half*)k16);
    gemm_f16x2_kernel<<<ggrid, 256, GEMM_SMEM>>>(x16, whi + 2 * DIM * DIM, wlo + 2 * DIM * DIM, nullptr, (__half*)v16);

    dim3 agrid(NBLK, NHEAD, BATCH);      // (64, 16, 2)
    attn_hmma_kernel<<<agrid, 128, ATTN_SMEM>>>((const __half*)q16, (const __half*)k16, (const __half*)v16, (__half*)a16);

    gemm_f16x2_kernel<<<ggrid, 256, GEMM_SMEM>>>(a16, whi + 3 * DIM * DIM, wlo + 3 * DIM * DIM, out, nullptr);
}

// round 10
// speedup vs baseline: 4.3935x; 1.1567x over previous
#include <cuda_runtime.h>
#include <cuda_fp16.h>
#include <cstdint>

// Problem constants: B=2, T=4096, D=1024, H=16, hd=64, WIN=512, BS=64
#define DIM   1024
#define HD    64
#define NHEAD 16
#define TLEN  4096
#define BATCH 2
#define MTOT  (BATCH * TLEN)      // 8192
#define NBLK  (TLEN / 64)
#define SCALE 0.125f

// ---------------- scratch (device globals; allocation-free rule) ----------------
__device__ unsigned short g_q[MTOT * DIM];     // half q16
__device__ unsigned short g_k[MTOT * DIM];     // half k16
__device__ unsigned short g_v[MTOT * DIM];     // half v16
__device__ unsigned short g_x16[MTOT * DIM];   // half x
__device__ unsigned short g_a16[MTOT * DIM];   // half attn out
__device__ unsigned short g_whi[4 * DIM * DIM];
__device__ unsigned short g_wlo[4 * DIM * DIM];

// ---------------- helpers ----------------
__device__ __forceinline__ uint32_t smem_u32(const void* p) {
    uint32_t a;
    asm("{ .reg .u64 t; cvta.to.shared.u64 t, %1; cvt.u32.u64 %0, t; }" : "=r"(a) : "l"(p));
    return a;
}
__device__ __forceinline__ void cp16(uint32_t saddr, const void* g) {
    asm volatile("cp.async.cg.shared.global [%0], [%1], 16;" :: "r"(saddr), "l"(g));
}
#define CP_COMMIT() asm volatile("cp.async.commit_group;" ::: "memory")
#define CP_WAIT(n)  asm volatile("cp.async.wait_group %0;" :: "n"(n) : "memory")

__device__ __forceinline__ void ldsm4(uint32_t& r0, uint32_t& r1, uint32_t& r2, uint32_t& r3, uint32_t addr) {
    asm volatile("ldmatrix.sync.aligned.m8n8.x4.shared.b16 {%0,%1,%2,%3}, [%4];"
                 : "=r"(r0), "=r"(r1), "=r"(r2), "=r"(r3) : "r"(addr));
}
__device__ __forceinline__ void ldsm4t(uint32_t& r0, uint32_t& r1, uint32_t& r2, uint32_t& r3, uint32_t addr) {
    asm volatile("ldmatrix.sync.aligned.m8n8.x4.trans.shared.b16 {%0,%1,%2,%3}, [%4];"
                 : "=r"(r0), "=r"(r1), "=r"(r2), "=r"(r3) : "r"(addr));
}
__device__ __forceinline__ void mma_f16(float* c, const uint32_t* a, const uint32_t* b) {
    asm volatile("mma.sync.aligned.m16n8k16.row.col.f32.f16.f16.f32 "
                 "{%0,%1,%2,%3}, {%4,%5,%6,%7}, {%8,%9}, {%0,%1,%2,%3};"
                 : "+f"(c[0]), "+f"(c[1]), "+f"(c[2]), "+f"(c[3])
                 : "r"(a[0]), "r"(a[1]), "r"(a[2]), "r"(a[3]), "r"(b[0]), "r"(b[1]));
}

// ---------------- fp32 -> fp16 convert (activations) ----------------
__global__ __launch_bounds__(256) void cvt_half_kernel(
    const float4* __restrict__ src, uint2* __restrict__ dst, int n4)
{
    int i = blockIdx.x * blockDim.x + threadIdx.x;
    if (i >= n4) return;
    float4 v = src[i];
    __half2 h01 = __floats2half2_rn(v.x, v.y);
    __half2 h23 = __floats2half2_rn(v.z, v.w);
    uint2 o;
    o.x = *(uint32_t*)&h01;
    o.y = *(uint32_t*)&h23;
    dst[i] = o;
}

// ---------------- fp32 -> fp16 hi/lo split (weights) ----------------
__global__ __launch_bounds__(256) void split_w_kernel(
    const float4* __restrict__ src, uint2* __restrict__ hi, uint2* __restrict__ lo, int n4)
{
    int i = blockIdx.x * blockDim.x + threadIdx.x;
    if (i >= n4) return;
    float4 v = src[i];
    float f[4] = {v.x, v.y, v.z, v.w};
    __half h[4], l[4];
#pragma unroll
    for (int j = 0; j < 4; ++j) {
        h[j] = __float2half_rn(f[j]);
        l[j] = __float2half_rn(f[j] - __half2float(h[j]));
    }
    uint2 H, L;
    H.x = ((uint32_t)*(unsigned short*)&h[0]) | ((uint32_t)*(unsigned short*)&h[1] << 16);
    H.y = ((uint32_t)*(unsigned short*)&h[2]) | ((uint32_t)*(unsigned short*)&h[3] << 16);
    L.x = ((uint32_t)*(unsigned short*)&l[0]) | ((uint32_t)*(unsigned short*)&l[1] << 16);
    L.y = ((uint32_t)*(unsigned short*)&l[2]) | ((uint32_t)*(unsigned short*)&l[3] << 16);
    hi[i] = H; lo[i] = L;
}

// ---------------- HMMA fp16x2 GEMM: C[M,N] = A @ (Whi+Wlo)^T ----------------
// CTA 256x128, BK=32, 8 warps (2x4), warp tile 128x32. 3-stage cp.async pipeline,
// single __syncthreads per k-iter (wait -> sync -> issue(it+2) -> compute).
// Stage tiles: A (256 rows x 80B), Bhi, Blo (128 rows x 80B each).
#define T_STRIDE 80
#define A_TILE_BYTES (256 * T_STRIDE)        // 20480
#define B_TILE_BYTES (128 * T_STRIDE)        // 10240
#define STAGE_BYTES (A_TILE_BYTES + 2 * B_TILE_BYTES)   // 40960
#define GEMM_SMEM (3 * STAGE_BYTES)          // 122880

__device__ __forceinline__ void load_tileA_ca(
    const unsigned short* __restrict__ G, int row0, int k0, uint32_t stile, int tid)
{
#pragma unroll
    for (int h = 0; h < 4; ++h) {
        int idx = tid + h * 256;          // 0..1023
        int r   = idx >> 2;
        int ch  = idx & 3;
        cp16(stile + (uint32_t)(r * T_STRIDE + ch * 16),
             G + (size_t)(row0 + r) * 1024 + k0 + ch * 8);
    }
}
__device__ __forceinline__ void load_tileB_ca(
    const unsigned short* __restrict__ G, int row0, int k0, uint32_t stile, int tid)
{
#pragma unroll
    for (int h = 0; h < 2; ++h) {
        int idx = tid + h * 256;          // 0..511
        int r   = idx >> 2;
        int ch  = idx & 3;
        cp16(stile + (uint32_t)(r * T_STRIDE + ch * 16),
             G + (size_t)(row0 + r) * 1024 + k0 + ch * 8);
    }
}

__global__ __launch_bounds__(256, 1) void gemm_f16x2_kernel(
    const unsigned short* __restrict__ A,
    const unsigned short* __restrict__ Bhi, const unsigned short* __restrict__ Blo,
    float* __restrict__ Cf, __half* __restrict__ Ch)
{
    extern __shared__ char gsm[];
    const uint32_t sbase = smem_u32(gsm);
    const int tid  = threadIdx.x;
    const int wid  = tid >> 5;
    const int lane = tid & 31;
    const int warp_m = wid >> 2;          // 0..1 -> rows warp_m*128
    const int warp_n = wid & 3;           // 0..3 -> cols warp_n*32
    const int bm = blockIdx.y * 256;
    const int bn = blockIdx.x * 128;

    float acc[8][4][4];
#pragma unroll
    for (int i = 0; i < 8; ++i)
#pragma unroll
        for (int j = 0; j < 4; ++j)
#pragma unroll
            for (int e = 0; e < 4; ++e) acc[i][j][e] = 0.f;

    const int a_r = lane & 15;
    const int a_c = lane >> 4;
    const int b_r = (lane & 7) + ((lane & 16) >> 1);
    const int b_c = (lane >> 3) & 1;

    const int NIT = 1024 / 32;   // 32

    // prologue: stages 0,1
#pragma unroll
    for (int s = 0; s < 2; ++s) {
        const uint32_t st = sbase + (uint32_t)s * STAGE_BYTES;
        const int k0 = s * 32;
        load_tileA_ca(A,   bm, k0, st, tid);
        load_tileB_ca(Bhi, bn, k0, st + A_TILE_BYTES, tid);
        load_tileB_ca(Blo, bn, k0, st + A_TILE_BYTES + B_TILE_BYTES, tid);
        CP_COMMIT();
    }

    int buf = 0, nbuf = 2;
    for (int it = 0; it < NIT; ++it) {
        if (it < NIT - 1) { CP_WAIT(1); } else { CP_WAIT(0); }
        __syncthreads();
        // issue stage it+2 into (it+2)%3 = (it-1)%3 — all warps are past
        // compute(it-1) due to the sync above, closing the WAR hazard.
        if (it + 2 < NIT) {
            const uint32_t st = sbase + (uint32_t)nbuf * STAGE_BYTES;
            const int k0 = (it + 2) * 32;
            load_tileA_ca(A,   bm, k0, st, tid);
            load_tileB_ca(Bhi, bn, k0, st + A_TILE_BYTES, tid);
            load_tileB_ca(Blo, bn, k0, st + A_TILE_BYTES + B_TILE_BYTES, tid);
            CP_COMMIT();
        }

        const uint32_t st = sbase + (uint32_t)buf * STAGE_BYTES;
        const uint32_t sA  = st;
        const uint32_t sBh = st + A_TILE_BYTES;
        const uint32_t sBl = st + A_TILE_BYTES + B_TILE_BYTES;

#pragma unroll
        for (int ks = 0; ks < 2; ++ks) {
            uint32_t af[8][4], bh[4][2], bl[4][2];
#pragma unroll
            for (int mf = 0; mf < 8; ++mf) {
                const uint32_t off = (uint32_t)((warp_m * 128 + mf * 16 + a_r) * T_STRIDE + ks * 32 + a_c * 16);
                ldsm4(af[mf][0], af[mf][1], af[mf][2], af[mf][3], sA + off);
            }
#pragma unroll
            for (int bf = 0; bf < 2; ++bf) {
                const uint32_t off = (uint32_t)((warp_n * 32 + bf * 16 + b_r) * T_STRIDE + ks * 32 + b_c * 16);
                ldsm4(bh[2 * bf][0], bh[2 * bf][1], bh[2 * bf + 1][0], bh[2 * bf + 1][1], sBh + off);
                ldsm4(bl[2 * bf][0], bl[2 * bf][1], bl[2 * bf + 1][0], bl[2 * bf + 1][1], sBl + off);
            }
#pragma unroll
            for (int mf = 0; mf < 8; ++mf)
#pragma unroll
                for (int nf = 0; nf < 4; ++nf)
                    mma_f16(acc[mf][nf], af[mf], bh[nf]);
#pragma unroll
            for (int mf = 0; mf < 8; ++mf)
#pragma unroll
                for (int nf = 0; nf < 4; ++nf)
                    mma_f16(acc[mf][nf], af[mf], bl[nf]);
        }

        buf = (buf + 1 == 3) ? 0 : buf + 1;
        nbuf = (nbuf + 1 == 3) ? 0 : nbuf + 1;
    }

    const int er = lane >> 2;
    const int ec = (lane & 3) * 2;
    if (Ch) {
#pragma unroll
        for (int mf = 0; mf < 8; ++mf)
#pragma unroll
            for (int nf = 0; nf < 4; ++nf) {
                const size_t row = (size_t)(bm + warp_m * 128 + mf * 16 + er);
                const int col = bn + warp_n * 32 + nf * 8 + ec;
                __half2 h01 = __floats2half2_rn(acc[mf][nf][0], acc[mf][nf][1]);
                __half2 h23 = __floats2half2_rn(acc[mf][nf][2], acc[mf][nf][3]);
                *(uint32_t*)&Ch[row * 1024 + col]       = *(uint32_t*)&h01;
                *(uint32_t*)&Ch[(row + 8) * 1024 + col] = *(uint32_t*)&h23;
            }
    } else {
#pragma unroll
        for (int mf = 0; mf < 8; ++mf)
#pragma unroll
            for (int nf = 0; nf < 4; ++nf) {
                const size_t row = (size_t)(bm + warp_m * 128 + mf * 16 + er);
                const int col = bn + warp_n * 32 + nf * 8 + ec;
                *(float2*)&Cf[row * 1024 + col]       = make_float2(acc[mf][nf][0], acc[mf][nf][1]);
                *(float2*)&Cf[(row + 8) * 1024 + col] = make_float2(acc[mf][nf][2], acc[mf][nf][3]);
            }
    }
}

// ---------------- fp16 HMMA flash attention (banded, causal) ----------------
// Unchanged from round 9 (passing). CTA per (qblock n, head h, batch b).
// 4 warps x 16 rows. THREE-stage cp.async K/V pipeline. Output single fp16.
#define ASTR 144
#define ATTN_STAGE(s) (9216u + (uint32_t)(s) * 18432u)
#define ATTN_SMEM (9216 + 3 * 18432)   // 64512

__global__ __launch_bounds__(128) void attn_hmma_kernel(
    const __half* __restrict__ qg, const __half* __restrict__ kg,
    const __half* __restrict__ vg, __half* __restrict__ aout)
{
    extern __shared__ char smb[];
    const uint32_t sb = smem_u32(smb);
    const int tid = threadIdx.x;
    const int wid = tid >> 5;
    const int lane = tid & 31;
    const int n = blockIdx.x, h = blockIdx.y, b = blockIdx.z;

    const size_t qbase = ((size_t)(b * TLEN + n * 64)) * DIM + h * HD;

#pragma unroll
    for (int i = 0; i < 4; ++i) {
        int idx = tid + i * 128;
        int r = idx >> 3, ch = idx & 7;
        cp16(sb + (uint32_t)(r * ASTR + ch * 16), qg + qbase + (size_t)r * DIM + ch * 8);
    }
    CP_COMMIT();

    const int jb0 = (n >= 8) ? n - 8 : 0;
    const int NB = n - jb0 + 1;

    auto issue = [&](int i) {
        const int jb = jb0 + i;
        const size_t kb = ((size_t)(b * TLEN + jb * 64)) * DIM + h * HD;
        const uint32_t st = sb + ATTN_STAGE(i % 3);
#pragma unroll
        for (int t = 0; t < 4; ++t) {
            int idx = tid + t * 128;
            int r = idx >> 3, ch = idx & 7;
            cp16(st + (uint32_t)(r * ASTR + ch * 16), kg + kb + (size_t)r * DIM + ch * 8);
            cp16(st + 9216u + (uint32_t)(r * ASTR + ch * 16), vg + kb + (size_t)r * DIM + ch * 8);
        }
        CP_COMMIT();
    };

    issue(0);
    if (NB > 1) issue(1);

    const int a_r = lane & 15, a_c = lane >> 4;
    const int b_r = (lane & 7) + ((lane & 16) >> 1), b_c = (lane >> 3) & 1;
    const int er = lane >> 2, ec = 2 * (lane & 3);
    const int r0 = wid * 16 + er, r1 = r0 + 8;

    float m0 = -1e9f, m1 = -1e9f, l0 = 0.f, l1 = 0.f;
    float of[8][4];
#pragma unroll
    for (int nf = 0; nf < 8; ++nf)
#pragma unroll
        for (int e = 0; e < 4; ++e) of[nf][e] = 0.f;
    uint32_t qf[4][4];

    for (int i = 0; i < NB; ++i) {
        if (i + 2 < NB) issue(i + 2);
        if (i + 2 < NB)      CP_WAIT(2);
        else if (i + 1 < NB) CP_WAIT(1);
        else                 CP_WAIT(0);
        __syncthreads();

        if (i == 0) {
#pragma unroll
            for (int ks = 0; ks < 4; ++ks)
                ldsm4(qf[ks][0], qf[ks][1], qf[ks][2], qf[ks][3],
                      sb + (uint32_t)((wid * 16 + a_r) * ASTR + ks * 32 + a_c * 16));
        }

        const int off = (jb0 + i) - n;
        const uint32_t Kst = sb + ATTN_STAGE(i % 3);
        const uint32_t Vst = Kst + 9216u;

        float sf[8][4];
#pragma unroll
        for (int nf = 0; nf < 8; ++nf)
#pragma unroll
            for (int e = 0; e < 4; ++e) sf[nf][e] = 0.f;
#pragma unroll
        for (int ks = 0; ks < 4; ++ks) {
            uint32_t kf[8][2];
#pragma unroll
            for (int bf = 0; bf < 4; ++bf)
                ldsm4(kf[2 * bf][0], kf[2 * bf][1], kf[2 * bf + 1][0], kf[2 * bf + 1][1],
                      Kst + (uint32_t)((bf * 16 + b_r) * ASTR + ks * 32 + b_c * 16));
#pragma unroll
            for (int nf = 0; nf < 8; ++nf)
                mma_f16(sf[nf], qf[ks], kf[nf]);
        }

#pragma unroll
        for (int nf = 0; nf < 8; ++nf) {
#pragma unroll
            for (int e = 0; e < 4; ++e) {
                int row = (e < 2) ? r0 : r1;
                int c = nf * 8 + ec + (e & 1);
                float sv = sf[nf][e] * SCALE;
                bool valid = (off == 0) ? (c <= row) : ((off == -8) ? (row < c) : true);
                sf[nf][e] = valid ? sv : -1e9f;
            }
        }

        float mx0 = sf[0][0], mx1 = sf[0][2];
#pragma unroll
        for (int nf = 0; nf < 8; ++nf) {
            mx0 = fmaxf(mx0, fmaxf(sf[nf][0], sf[nf][1]));
            mx1 = fmaxf(mx1, fmaxf(sf[nf][2], sf[nf][3]));
        }
        mx0 = fmaxf(mx0, __shfl_xor_sync(0xffffffffu, mx0, 1));
        mx0 = fmaxf(mx0, __shfl_xor_sync(0xffffffffu, mx0, 2));
        mx1 = fmaxf(mx1, __shfl_xor_sync(0xffffffffu, mx1, 1));
        mx1 = fmaxf(mx1, __shfl_xor_sync(0xffffffffu, mx1, 2));
        float mn0 = fmaxf(m0, mx0), mn1 = fmaxf(m1, mx1);
        float cf0 = __expf(m0 - mn0), cf1 = __expf(m1 - mn1);
        m0 = mn0; m1 = mn1;

        float s0 = 0.f, s1 = 0.f;
        uint32_t pf[4][4];
#pragma unroll
        for (int nf = 0; nf < 8; ++nf) {
            float p0 = __expf(sf[nf][0] - m0);
            float p1 = __expf(sf[nf][1] - m0);
            float p2 = __expf(sf[nf][2] - m1);
            float p3 = __expf(sf[nf][3] - m1);
            s0 += p0 + p1; s1 += p2 + p3;
            __half2 h01 = __floats2half2_rn(p0, p1);
            __half2 h23 = __floats2half2_rn(p2, p3);
            pf[nf >> 1][(nf & 1) * 2 + 0] = *(uint32_t*)&h01;
            pf[nf >> 1][(nf & 1) * 2 + 1] = *(uint32_t*)&h23;
        }
        l0 = l0 * cf0 + s0; l1 = l1 * cf1 + s1;
#pragma unroll
        for (int nf = 0; nf < 8; ++nf) {
            of[nf][0] *= cf0; of[nf][1] *= cf0;
            of[nf][2] *= cf1; of[nf][3] *= cf1;
        }

#pragma unroll
        for (int ks = 0; ks < 4; ++ks) {
            uint32_t vf[8][2];
#pragma unroll
            for (int nfp = 0; nfp < 4; ++nfp)
                ldsm4t(vf[2 * nfp][0], vf[2 * nfp][1], vf[2 * nfp + 1][0], vf[2 * nfp + 1][1],
                       Vst + (uint32_t)((ks * 16 + (lane & 15)) * ASTR + (nfp * 2 + (lane >> 4)) * 16));
#pragma unroll
            for (int nf = 0; nf < 8; ++nf)
                mma_f16(of[nf], pf[ks], vf[nf]);
        }
        __syncthreads();
    }

    l0 += __shfl_xor_sync(0xffffffffu, l0, 1);
    l0 += __shfl_xor_sync(0xffffffffu, l0, 2);
    l1 += __shfl_xor_sync(0xffffffffu, l1, 1);
    l1 += __shfl_xor_sync(0xffffffffu, l1, 2);
    const float i0 = 1.f / l0, i1 = 1.f / l1;
    const size_t row0 = (size_t)(b * TLEN + n * 64 + r0);
    const size_t row1 = row0 + 8;
#pragma unroll
    for (int nf = 0; nf < 8; ++nf) {
        const int col = h * HD + nf * 8 + ec;
        __half2 h01 = __floats2half2_rn(of[nf][0] * i0, of[nf][1] * i0);
        __half2 h23 = __floats2half2_rn(of[nf][2] * i1, of[nf][3] * i1);
        *(uint32_t*)&aout[row0 * DIM + col] = *(uint32_t*)&h01;
        *(uint32_t*)&aout[row1 * DIM + col] = *(uint32_t*)&h23;
    }
}

// ---------------- launch ----------------
extern "C" void kernel_launch(void* const* d_in, const int* in_sizes, int n_in,
                              void* d_out, int out_size)
{
    const float* x  = (const float*)d_in[0];
    const float* Wq = (const float*)d_in[1];
    const float* Wk = (const float*)d_in[2];
    const float* Wv = (const float*)d_in[3];
    const float* Wo = (const float*)d_in[4];
    float* out = (float*)d_out;

    unsigned short *q16, *k16, *v16, *x16, *a16, *whi, *wlo;
    cudaGetSymbolAddress((void**)&q16, g_q);
    cudaGetSymbolAddress((void**)&k16, g_k);
    cudaGetSymbolAddress((void**)&v16, g_v);
    cudaGetSymbolAddress((void**)&x16, g_x16);
    cudaGetSymbolAddress((void**)&a16, g_a16);
    cudaGetSymbolAddress((void**)&whi, g_whi);
    cudaGetSymbolAddress((void**)&wlo, g_wlo);

    cudaFuncSetAttribute(gemm_f16x2_kernel, cudaFuncAttributeMaxDynamicSharedMemorySize, GEMM_SMEM);
    cudaFuncSetAttribute(attn_hmma_kernel, cudaFuncAttributeMaxDynamicSharedMemorySize, ATTN_SMEM);

    const int n4x = MTOT * DIM / 4;   // 2M
    const int n4w = DIM * DIM / 4;    // 256K

    cvt_half_kernel<<<n4x / 256, 256>>>((const float4*)x, (uint2*)x16, n4x);
    split_w_kernel<<<n4w / 256, 256>>>((const float4*)Wq, (uint2*)(whi + 0 * DIM * DIM), (uint2*)(wlo + 0 * DIM * DIM), n4w);
    split_w_kernel<<<n4w / 256, 256>>>((const float4*)Wk, (uint2*)(whi + 1 * DIM * DIM), (uint2*)(wlo + 1 * DIM * DIM), n4w);
    split_w_kernel<<<n4w / 256, 256>>>((const float4*)Wv, (uint2*)(whi + 2 * DIM * DIM), (uint2*)(wlo + 2 * DIM * DIM), n4w);
    split_w_kernel<<<n4w / 256, 256>>>((const float4*)Wo, (uint2*)(whi + 3 * DIM * DIM), (uint2*)(wlo + 3 * DIM * DIM), n4w);

    dim3 ggrid(DIM / 128, MTOT / 256);   // (8, 32)
    gemm_f16x2_kernel<<<ggrid, 256, GEMM_SMEM>>>(x16, whi + 0 * DIM * DIM, wlo + 0 * DIM * DIM, nullptr, (__half*)q16);
    gemm_f16x2_kernel<<<ggrid, 256, GEMM_SMEM>>>(x16, whi + 1 * DIM * DIM, wlo + 1 * DIM * DIM, nullptr, (__half*)k16);
    gemm_f16x2_kernel<<<ggrid, 256, GEMM_SMEM>>>(x16, whi + 2 * DIM * DIM, wlo + 2 * DIM * DIM, nullptr, (__half*)v16);

    dim3 agrid(NBLK, NHEAD, BATCH);      // (64, 16, 2)
    attn_hmma_kernel<<<agrid, 128, ATTN_SMEM>>>((const __half*)q16, (const __half*)k16, (const __half*)v16, (__half*)a16);

    gemm_f16x2_kernel<<<ggrid, 256, GEMM_SMEM>>>(a16, whi + 3 * DIM * DIM, wlo + 3 * DIM * DIM, out, nullptr);
}

// round 11
// speedup vs baseline: 5.5914x; 1.2727x over previous
#include <cuda_runtime.h>
#include <cuda_fp16.h>
#include <cstdint>

// Problem constants: B=2, T=4096, D=1024, H=16, hd=64, WIN=512, BS=64
#define DIM   1024
#define HD    64
#define NHEAD 16
#define TLEN  4096
#define BATCH 2
#define MTOT  (BATCH * TLEN)      // 8192
#define NBLK  (TLEN / 64)
#define SCALE 0.125f

// ---------------- scratch (device globals; allocation-free rule) ----------------
__device__ unsigned short g_q[MTOT * DIM];     // half q16
__device__ unsigned short g_k[MTOT * DIM];     // half k16
__device__ unsigned short g_v[MTOT * DIM];     // half v16
__device__ unsigned short g_x16[MTOT * DIM];   // half x
__device__ unsigned short g_a16[MTOT * DIM];   // half attn out
__device__ unsigned short g_whi[4 * DIM * DIM];
__device__ unsigned short g_wlo[DIM * DIM];    // only Wo needs the lo part

// ---------------- helpers ----------------
__device__ __forceinline__ uint32_t smem_u32(const void* p) {
    uint32_t a;
    asm("{ .reg .u64 t; cvta.to.shared.u64 t, %1; cvt.u32.u64 %0, t; }" : "=r"(a) : "l"(p));
    return a;
}
__device__ __forceinline__ void cp16(uint32_t saddr, const void* g) {
    asm volatile("cp.async.cg.shared.global [%0], [%1], 16;" :: "r"(saddr), "l"(g));
}
#define CP_COMMIT() asm volatile("cp.async.commit_group;" ::: "memory")
#define CP_WAIT(n)  asm volatile("cp.async.wait_group %0;" :: "n"(n) : "memory")

__device__ __forceinline__ void ldsm4(uint32_t& r0, uint32_t& r1, uint32_t& r2, uint32_t& r3, uint32_t addr) {
    asm volatile("ldmatrix.sync.aligned.m8n8.x4.shared.b16 {%0,%1,%2,%3}, [%4];"
                 : "=r"(r0), "=r"(r1), "=r"(r2), "=r"(r3) : "r"(addr));
}
__device__ __forceinline__ void ldsm4t(uint32_t& r0, uint32_t& r1, uint32_t& r2, uint32_t& r3, uint32_t addr) {
    asm volatile("ldmatrix.sync.aligned.m8n8.x4.trans.shared.b16 {%0,%1,%2,%3}, [%4];"
                 : "=r"(r0), "=r"(r1), "=r"(r2), "=r"(r3) : "r"(addr));
}
__device__ __forceinline__ void mma_f16(float* c, const uint32_t* a, const uint32_t* b) {
    asm volatile("mma.sync.aligned.m16n8k16.row.col.f32.f16.f16.f32 "
                 "{%0,%1,%2,%3}, {%4,%5,%6,%7}, {%8,%9}, {%0,%1,%2,%3};"
                 : "+f"(c[0]), "+f"(c[1]), "+f"(c[2]), "+f"(c[3])
                 : "r"(a[0]), "r"(a[1]), "r"(a[2]), "r"(a[3]), "r"(b[0]), "r"(b[1]));
}

// ---------------- fp32 -> fp16 convert (activations) ----------------
__global__ __launch_bounds__(256) void cvt_half_kernel(
    const float4* __restrict__ src, uint2* __restrict__ dst, int n4)
{
    int i = blockIdx.x * blockDim.x + threadIdx.x;
    if (i >= n4) return;
    float4 v = src[i];
    __half2 h01 = __floats2half2_rn(v.x, v.y);
    __half2 h23 = __floats2half2_rn(v.z, v.w);
    uint2 o;
    o.x = *(uint32_t*)&h01;
    o.y = *(uint32_t*)&h23;
    dst[i] = o;
}

// ---------------- fp32 -> fp16 hi/lo split (weights) ----------------
__global__ __launch_bounds__(256) void split_w_kernel(
    const float4* __restrict__ src, uint2* __restrict__ hi, uint2* __restrict__ lo, int n4)
{
    int i = blockIdx.x * blockDim.x + threadIdx.x;
    if (i >= n4) return;
    float4 v = src[i];
    float f[4] = {v.x, v.y, v.z, v.w};
    __half h[4], l[4];
#pragma unroll
    for (int j = 0; j < 4; ++j) {
        h[j] = __float2half_rn(f[j]);
        l[j] = __float2half_rn(f[j] - __half2float(h[j]));
    }
    uint2 H, L;
    H.x = ((uint32_t)*(unsigned short*)&h[0]) | ((uint32_t)*(unsigned short*)&h[1] << 16);
    H.y = ((uint32_t)*(unsigned short*)&h[2]) | ((uint32_t)*(unsigned short*)&h[3] << 16);
    L.x = ((uint32_t)*(unsigned short*)&l[0]) | ((uint32_t)*(unsigned short*)&l[1] << 16);
    L.y = ((uint32_t)*(unsigned short*)&l[2]) | ((uint32_t)*(unsigned short*)&l[3] << 16);
    hi[i] = H;
    if (lo) lo[i] = L;
}

// ---------------- HMMA GEMM common geometry ----------------
// CTA 256x128, BK=32, 8 warps (2x4), warp tile 128x32. 3-stage cp.async pipeline,
// single __syncthreads per k-iter (wait -> sync -> issue(it+2) -> compute).
#define T_STRIDE 80
#define A_TILE_BYTES (256 * T_STRIDE)        // 20480
#define B_TILE_BYTES (128 * T_STRIDE)        // 10240
#define STAGE2 (A_TILE_BYTES + B_TILE_BYTES)         // 30720 (x1 variant)
#define STAGE3 (A_TILE_BYTES + 2 * B_TILE_BYTES)     // 40960 (x2 variant)
#define GEMM_SMEM_X1 (3 * STAGE2)            // 92160
#define GEMM_SMEM_X2 (3 * STAGE3)            // 122880

__device__ __forceinline__ void load_tileA_ca(
    const unsigned short* __restrict__ G, int row0, int k0, uint32_t stile, int tid)
{
#pragma unroll
    for (int h = 0; h < 4; ++h) {
        int idx = tid + h * 256;          // 0..1023
        int r   = idx >> 2;
        int ch  = idx & 3;
        cp16(stile + (uint32_t)(r * T_STRIDE + ch * 16),
             G + (size_t)(row0 + r) * 1024 + k0 + ch * 8);
    }
}
__device__ __forceinline__ void load_tileB_ca(
    const unsigned short* __restrict__ G, int row0, int k0, uint32_t stile, int tid)
{
#pragma unroll
    for (int h = 0; h < 2; ++h) {
        int idx = tid + h * 256;          // 0..511
        int r   = idx >> 2;
        int ch  = idx & 3;
        cp16(stile + (uint32_t)(r * T_STRIDE + ch * 16),
             G + (size_t)(row0 + r) * 1024 + k0 + ch * 8);
    }
}

// ---------------- single-fp16-weight GEMM (QKV): C = A @ W^T -> half ----------------
__global__ __launch_bounds__(256, 1) void gemm_f16x1_kernel(
    const unsigned short* __restrict__ A,
    const unsigned short* __restrict__ B,
    __half* __restrict__ Ch)
{
    extern __shared__ char gsm[];
    const uint32_t sbase = smem_u32(gsm);
    const int tid  = threadIdx.x;
    const int wid  = tid >> 5;
    const int lane = tid & 31;
    const int warp_m = wid >> 2;
    const int warp_n = wid & 3;
    const int bm = blockIdx.y * 256;
    const int bn = blockIdx.x * 128;

    float acc[8][4][4];
#pragma unroll
    for (int i = 0; i < 8; ++i)
#pragma unroll
        for (int j = 0; j < 4; ++j)
#pragma unroll
            for (int e = 0; e < 4; ++e) acc[i][j][e] = 0.f;

    const int a_r = lane & 15;
    const int a_c = lane >> 4;
    const int b_r = (lane & 7) + ((lane & 16) >> 1);
    const int b_c = (lane >> 3) & 1;

    const int NIT = 1024 / 32;   // 32

#pragma unroll
    for (int s = 0; s < 2; ++s) {
        const uint32_t st = sbase + (uint32_t)s * STAGE2;
        const int k0 = s * 32;
        load_tileA_ca(A, bm, k0, st, tid);
        load_tileB_ca(B, bn, k0, st + A_TILE_BYTES, tid);
        CP_COMMIT();
    }

    int buf = 0, nbuf = 2;
    for (int it = 0; it < NIT; ++it) {
        if (it < NIT - 1) { CP_WAIT(1); } else { CP_WAIT(0); }
        __syncthreads();
        if (it + 2 < NIT) {
            const uint32_t st = sbase + (uint32_t)nbuf * STAGE2;
            const int k0 = (it + 2) * 32;
            load_tileA_ca(A, bm, k0, st, tid);
            load_tileB_ca(B, bn, k0, st + A_TILE_BYTES, tid);
            CP_COMMIT();
        }

        const uint32_t st = sbase + (uint32_t)buf * STAGE2;
        const uint32_t sA = st;
        const uint32_t sB = st + A_TILE_BYTES;

#pragma unroll
        for (int ks = 0; ks < 2; ++ks) {
            uint32_t af[8][4], bf2[4][2];
#pragma unroll
            for (int mf = 0; mf < 8; ++mf) {
                const uint32_t off = (uint32_t)((warp_m * 128 + mf * 16 + a_r) * T_STRIDE + ks * 32 + a_c * 16);
                ldsm4(af[mf][0], af[mf][1], af[mf][2], af[mf][3], sA + off);
            }
#pragma unroll
            for (int bf = 0; bf < 2; ++bf) {
                const uint32_t off = (uint32_t)((warp_n * 32 + bf * 16 + b_r) * T_STRIDE + ks * 32 + b_c * 16);
                ldsm4(bf2[2 * bf][0], bf2[2 * bf][1], bf2[2 * bf + 1][0], bf2[2 * bf + 1][1], sB + off);
            }
#pragma unroll
            for (int mf = 0; mf < 8; ++mf)
#pragma unroll
                for (int nf = 0; nf < 4; ++nf)
                    mma_f16(acc[mf][nf], af[mf], bf2[nf]);
        }

        buf = (buf + 1 == 3) ? 0 : buf + 1;
        nbuf = (nbuf + 1 == 3) ? 0 : nbuf + 1;
    }

    const int er = lane >> 2;
    const int ec = (lane & 3) * 2;
#pragma unroll
    for (int mf = 0; mf < 8; ++mf)
#pragma unroll
        for (int nf = 0; nf < 4; ++nf) {
            const size_t row = (size_t)(bm + warp_m * 128 + mf * 16 + er);
            const int col = bn + warp_n * 32 + nf * 8 + ec;
            __half2 h01 = __floats2half2_rn(acc[mf][nf][0], acc[mf][nf][1]);
            __half2 h23 = __floats2half2_rn(acc[mf][nf][2], acc[mf][nf][3]);
            *(uint32_t*)&Ch[row * 1024 + col]       = *(uint32_t*)&h01;
            *(uint32_t*)&Ch[(row + 8) * 1024 + col] = *(uint32_t*)&h23;
        }
}

// ---------------- fp16x2 GEMM (output projection): C = A @ (Whi+Wlo)^T -> fp32 ----------------
__global__ __launch_bounds__(256, 1) void gemm_f16x2_kernel(
    const unsigned short* __restrict__ A,
    const unsigned short* __restrict__ Bhi, const unsigned short* __restrict__ Blo,
    float* __restrict__ Cf)
{
    extern __shared__ char gsm[];
    const uint32_t sbase = smem_u32(gsm);
    const int tid  = threadIdx.x;
    const int wid  = tid >> 5;
    const int lane = tid & 31;
    const int warp_m = wid >> 2;
    const int warp_n = wid & 3;
    const int bm = blockIdx.y * 256;
    const int bn = blockIdx.x * 128;

    float acc[8][4][4];
#pragma unroll
    for (int i = 0; i < 8; ++i)
#pragma unroll
        for (int j = 0; j < 4; ++j)
#pragma unroll
            for (int e = 0; e < 4; ++e) acc[i][j][e] = 0.f;

    const int a_r = lane & 15;
    const int a_c = lane >> 4;
    const int b_r = (lane & 7) + ((lane & 16) >> 1);
    const int b_c = (lane >> 3) & 1;

    const int NIT = 1024 / 32;

#pragma unroll
    for (int s = 0; s < 2; ++s) {
        const uint32_t st = sbase + (uint32_t)s * STAGE3;
        const int k0 = s * 32;
        load_tileA_ca(A,   bm, k0, st, tid);
        load_tileB_ca(Bhi, bn, k0, st + A_TILE_BYTES, tid);
        load_tileB_ca(Blo, bn, k0, st + A_TILE_BYTES + B_TILE_BYTES, tid);
        CP_COMMIT();
    }

    int buf = 0, nbuf = 2;
    for (int it = 0; it < NIT; ++it) {
        if (it < NIT - 1) { CP_WAIT(1); } else { CP_WAIT(0); }
        __syncthreads();
        if (it + 2 < NIT) {
            const uint32_t st = sbase + (uint32_t)nbuf * STAGE3;
            const int k0 = (it + 2) * 32;
            load_tileA_ca(A,   bm, k0, st, tid);
            load_tileB_ca(Bhi, bn, k0, st + A_TILE_BYTES, tid);
            load_tileB_ca(Blo, bn, k0, st + A_TILE_BYTES + B_TILE_BYTES, tid);
            CP_COMMIT();
        }

        const uint32_t st = sbase + (uint32_t)buf * STAGE3;
        const uint32_t sA  = st;
        const uint32_t sBh = st + A_TILE_BYTES;
        const uint32_t sBl = st + A_TILE_BYTES + B_TILE_BYTES;

#pragma unroll
        for (int ks = 0; ks < 2; ++ks) {
            uint32_t af[8][4], bh[4][2], bl[4][2];
#pragma unroll
            for (int mf = 0; mf < 8; ++mf) {
                const uint32_t off = (uint32_t)((warp_m * 128 + mf * 16 + a_r) * T_STRIDE + ks * 32 + a_c * 16);
                ldsm4(af[mf][0], af[mf][1], af[mf][2], af[mf][3], sA + off);
            }
#pragma unroll
            for (int bf = 0; bf < 2; ++bf) {
                const uint32_t off = (uint32_t)((warp_n * 32 + bf * 16 + b_r) * T_STRIDE + ks * 32 + b_c * 16);
                ldsm4(bh[2 * bf][0], bh[2 * bf][1], bh[2 * bf + 1][0], bh[2 * bf + 1][1], sBh + off);
                ldsm4(bl[2 * bf][0], bl[2 * bf][1], bl[2 * bf + 1][0], bl[2 * bf + 1][1], sBl + off);
            }
#pragma unroll
            for (int mf = 0; mf < 8; ++mf)
#pragma unroll
                for (int nf = 0; nf < 4; ++nf)
                    mma_f16(acc[mf][nf], af[mf], bh[nf]);
#pragma unroll
            for (int mf = 0; mf < 8; ++mf)
#pragma unroll
                for (int nf = 0; nf < 4; ++nf)
                    mma_f16(acc[mf][nf], af[mf], bl[nf]);
        }

        buf = (buf + 1 == 3) ? 0 : buf + 1;
        nbuf = (nbuf + 1 == 3) ? 0 : nbuf + 1;
    }

    const int er = lane >> 2;
    const int ec = (lane & 3) * 2;
#pragma unroll
    for (int mf = 0; mf < 8; ++mf)
#pragma unroll
        for (int nf = 0; nf < 4; ++nf) {
            const size_t row = (size_t)(bm + warp_m * 128 + mf * 16 + er);
            const int col = bn + warp_n * 32 + nf * 8 + ec;
            *(float2*)&Cf[row * 1024 + col]       = make_float2(acc[mf][nf][0], acc[mf][nf][1]);
            *(float2*)&Cf[(row + 8) * 1024 + col] = make_float2(acc[mf][nf][2], acc[mf][nf][3]);
        }
}

// ---------------- fp16 HMMA flash attention (banded, causal) ----------------
// Unchanged from round 10 (passing).
#define ASTR 144
#define ATTN_STAGE(s) (9216u + (uint32_t)(s) * 18432u)
#define ATTN_SMEM (9216 + 3 * 18432)   // 64512

__global__ __launch_bounds__(128) void attn_hmma_kernel(
    const __half* __restrict__ qg, const __half* __restrict__ kg,
    const __half* __restrict__ vg, __half* __restrict__ aout)
{
    extern __shared__ char smb[];
    const uint32_t sb = smem_u32(smb);
    const int tid = threadIdx.x;
    const int wid = tid >> 5;
    const int lane = tid & 31;
    const int n = blockIdx.x, h = blockIdx.y, b = blockIdx.z;

    const size_t qbase = ((size_t)(b * TLEN + n * 64)) * DIM + h * HD;

#pragma unroll
    for (int i = 0; i < 4; ++i) {
        int idx = tid + i * 128;
        int r = idx >> 3, ch = idx & 7;
        cp16(sb + (uint32_t)(r * ASTR + ch * 16), qg + qbase + (size_t)r * DIM + ch * 8);
    }
    CP_COMMIT();

    const int jb0 = (n >= 8) ? n - 8 : 0;
    const int NB = n - jb0 + 1;

    auto issue = [&](int i) {
        const int jb = jb0 + i;
        const size_t kb = ((size_t)(b * TLEN + jb * 64)) * DIM + h * HD;
        const uint32_t st = sb + ATTN_STAGE(i % 3);
#pragma unroll
        for (int t = 0; t < 4; ++t) {
            int idx = tid + t * 128;
            int r = idx >> 3, ch = idx & 7;
            cp16(st + (uint32_t)(r * ASTR + ch * 16), kg + kb + (size_t)r * DIM + ch * 8);
            cp16(st + 9216u + (uint32_t)(r * ASTR + ch * 16), vg + kb + (size_t)r * DIM + ch * 8);
        }
        CP_COMMIT();
    };

    issue(0);
    if (NB > 1) issue(1);

    const int a_r = lane & 15, a_c = lane >> 4;
    const int b_r = (lane & 7) + ((lane & 16) >> 1), b_c = (lane >> 3) & 1;
    const int er = lane >> 2, ec = 2 * (lane & 3);
    const int r0 = wid * 16 + er, r1 = r0 + 8;

    float m0 = -1e9f, m1 = -1e9f, l0 = 0.f, l1 = 0.f;
    float of[8][4];
#pragma unroll
    for (int nf = 0; nf < 8; ++nf)
#pragma unroll
        for (int e = 0; e < 4; ++e) of[nf][e] = 0.f;
    uint32_t qf[4][4];

    for (int i = 0; i < NB; ++i) {
        if (i + 2 < NB) issue(i + 2);
        if (i + 2 < NB)      CP_WAIT(2);
        else if (i + 1 < NB) CP_WAIT(1);
        else                 CP_WAIT(0);
        __syncthreads();

        if (i == 0) {
#pragma unroll
            for (int ks = 0; ks < 4; ++ks)
                ldsm4(qf[ks][0], qf[ks][1], qf[ks][2], qf[ks][3],
                      sb + (uint32_t)((wid * 16 + a_r) * ASTR + ks * 32 + a_c * 16));
        }

        const int off = (jb0 + i) - n;
        const uint32_t Kst = sb + ATTN_STAGE(i % 3);
        const uint32_t Vst = Kst + 9216u;

        float sf[8][4];
#pragma unroll
        for (int nf = 0; nf < 8; ++nf)
#pragma unroll
            for (int e = 0; e < 4; ++e) sf[nf][e] = 0.f;
#pragma unroll
        for (int ks = 0; ks < 4; ++ks) {
            uint32_t kf[8][2];
#pragma unroll
            for (int bf = 0; bf < 4; ++bf)
                ldsm4(kf[2 * bf][0], kf[2 * bf][1], kf[2 * bf + 1][0], kf[2 * bf + 1][1],
                      Kst + (uint32_t)((bf * 16 + b_r) * ASTR + ks * 32 + b_c * 16));
#pragma unroll
            for (int nf = 0; nf < 8; ++nf)
                mma_f16(sf[nf], qf[ks], kf[nf]);
        }

#pragma unroll
        for (int nf = 0; nf < 8; ++nf) {
#pragma unroll
            for (int e = 0; e < 4; ++e) {
                int row = (e < 2) ? r0 : r1;
                int c = nf * 8 + ec + (e & 1);
                float sv = sf[nf][e] * SCALE;
                bool valid = (off == 0) ? (c <= row) : ((off == -8) ? (row < c) : true);
                sf[nf][e] = valid ? sv : -1e9f;
            }
        }

        float mx0 = sf[0][0], mx1 = sf[0][2];
#pragma unroll
        for (int nf = 0; nf < 8; ++nf) {
            mx0 = fmaxf(mx0, fmaxf(sf[nf][0], sf[nf][1]));
            mx1 = fmaxf(mx1, fmaxf(sf[nf][2], sf[nf][3]));
        }
        mx0 = fmaxf(mx0, __shfl_xor_sync(0xffffffffu, mx0, 1));
        mx0 = fmaxf(mx0, __shfl_xor_sync(0xffffffffu, mx0, 2));
        mx1 = fmaxf(mx1, __shfl_xor_sync(0xffffffffu, mx1, 1));
        mx1 = fmaxf(mx1, __shfl_xor_sync(0xffffffffu, mx1, 2));
        float mn0 = fmaxf(m0, mx0), mn1 = fmaxf(m1, mx1);
        float cf0 = __expf(m0 - mn0), cf1 = __expf(m1 - mn1);
        m0 = mn0; m1 = mn1;

        float s0 = 0.f, s1 = 0.f;
        uint32_t pf[4][4];
#pragma unroll
        for (int nf = 0; nf < 8; ++nf) {
            float p0 = __expf(sf[nf][0] - m0);
            float p1 = __expf(sf[nf][1] - m0);
            float p2 = __expf(sf[nf][2] - m1);
            float p3 = __expf(sf[nf][3] - m1);
            s0 += p0 + p1; s1 += p2 + p3;
            __half2 h01 = __floats2half2_rn(p0, p1);
            __half2 h23 = __floats2half2_rn(p2, p3);
            pf[nf >> 1][(nf & 1) * 2 + 0] = *(uint32_t*)&h01;
            pf[nf >> 1][(nf & 1) * 2 + 1] = *(uint32_t*)&h23;
        }
        l0 = l0 * cf0 + s0; l1 = l1 * cf1 + s1;
#pragma unroll
        for (int nf = 0; nf < 8; ++nf) {
            of[nf][0] *= cf0; of[nf][1] *= cf0;
            of[nf][2] *= cf1; of[nf][3] *= cf1;
        }

#pragma unroll
        for (int ks = 0; ks < 4; ++ks) {
            uint32_t vf[8][2];
#pragma unroll
            for (int nfp = 0; nfp < 4; ++nfp)
                ldsm4t(vf[2 * nfp][0], vf[2 * nfp][1], vf[2 * nfp + 1][0], vf[2 * nfp + 1][1],
                       Vst + (uint32_t)((ks * 16 + (lane & 15)) * ASTR + (nfp * 2 + (lane >> 4)) * 16));
#pragma unroll
            for (int nf = 0; nf < 8; ++nf)
                mma_f16(of[nf], pf[ks], vf[nf]);
        }
        __syncthreads();
    }

    l0 += __shfl_xor_sync(0xffffffffu, l0, 1);
    l0 += __shfl_xor_sync(0xffffffffu, l0, 2);
    l1 += __shfl_xor_sync(0xffffffffu, l1, 1);
    l1 += __shfl_xor_sync(0xffffffffu, l1, 2);
    const float i0 = 1.f / l0, i1 = 1.f / l1;
    const size_t row0 = (size_t)(b * TLEN + n * 64 + r0);
    const size_t row1 = row0 + 8;
#pragma unroll
    for (int nf = 0; nf < 8; ++nf) {
        const int col = h * HD + nf * 8 + ec;
        __half2 h01 = __floats2half2_rn(of[nf][0] * i0, of[nf][1] * i0);
        __half2 h23 = __floats2half2_rn(of[nf][2] * i1, of[nf][3] * i1);
        *(uint32_t*)&aout[row0 * DIM + col] = *(uint32_t*)&h01;
        *(uint32_t*)&aout[row1 * DIM + col] = *(uint32_t*)&h23;
    }
}

// ---------------- launch ----------------
extern "C" void kernel_launch(void* const* d_in, const int* in_sizes, int n_in,
                              void* d_out, int out_size)
{
    const float* x  = (const float*)d_in[0];
    const float* Wq = (const float*)d_in[1];
    const float* Wk = (const float*)d_in[2];
    const float* Wv = (const float*)d_in[3];
    const float* Wo = (const float*)d_in[4];
    float* out = (float*)d_out;

    unsigned short *q16, *k16, *v16, *x16, *a16, *whi, *wlo;
    cudaGetSymbolAddress((void**)&q16, g_q);
    cudaGetSymbolAddress((void**)&k16, g_k);
    cudaGetSymbolAddress((void**)&v16, g_v);
    cudaGetSymbolAddress((void**)&x16, g_x16);
    cudaGetSymbolAddress((void**)&a16, g_a16);
    cudaGetSymbolAddress((void**)&whi, g_whi);
    cudaGetSymbolAddress((void**)&wlo, g_wlo);

    cudaFuncSetAttribute(gemm_f16x1_kernel, cudaFuncAttributeMaxDynamicSharedMemorySize, GEMM_SMEM_X1);
    cudaFuncSetAttribute(gemm_f16x2_kernel, cudaFuncAttributeMaxDynamicSharedMemorySize, GEMM_SMEM_X2);
    cudaFuncSetAttribute(attn_hmma_kernel, cudaFuncAttributeMaxDynamicSharedMemorySize, ATTN_SMEM);

    const int n4x = MTOT * DIM / 4;   // 2M
    const int n4w = DIM * DIM / 4;    // 256K

    cvt_half_kernel<<<n4x / 256, 256>>>((const float4*)x, (uint2*)x16, n4x);
    // QKV weights: hi only. Wo: hi + lo.
    split_w_kernel<<<n4w / 256, 256>>>((const float4*)Wq, (uint2*)(whi + 0 * DIM * DIM), nullptr, n4w);
    split_w_kernel<<<n4w / 256, 256>>>((const float4*)Wk, (uint2*)(whi + 1 * DIM * DIM), nullptr, n4w);
    split_w_kernel<<<n4w / 256, 256>>>((const float4*)Wv, (uint2*)(whi + 2 * DIM * DIM), nullptr, n4w);
    split_w_kernel<<<n4w / 256, 256>>>((const float4*)Wo, (uint2*)(whi + 3 * DIM * DIM), (uint2*)wlo, n4w);

    dim3 ggrid(DIM / 128, MTOT / 256);   // (8, 32)
    gemm_f16x1_kernel<<<ggrid, 256, GEMM_SMEM_X1>>>(x16, whi + 0 * DIM * DIM, (__half*)q16);
    gemm_f16x1_kernel<<<ggrid, 256, GEMM_SMEM_X1>>>(x16, whi + 1 * DIM * DIM, (__half*)k16);
    gemm_f16x1_kernel<<<ggrid, 256, GEMM_SMEM_X1>>>(x16, whi + 2 * DIM * DIM, (__half*)v16);

    dim3 agrid(NBLK, NHEAD, BATCH);      // (64, 16, 2)
    attn_hmma_kernel<<<agrid, 128, ATTN_SMEM>>>((const __half*)q16, (const __half*)k16, (const __half*)v16, (__half*)a16);

    gemm_f16x2_kernel<<<ggrid, 256, GEMM_SMEM_X2>>>(a16, whi + 3 * DIM * DIM, wlo, out);
}

// round 12
// speedup vs baseline: 6.3252x; 1.1312x over previous
#include <cuda_runtime.h>
#include <cuda_fp16.h>
#include <cstdint>

// Problem constants: B=2, T=4096, D=1024, H=16, hd=64, WIN=512, BS=64
#define DIM   1024
#define HD    64
#define NHEAD 16
#define TLEN  4096
#define BATCH 2
#define MTOT  (BATCH * TLEN)      // 8192
#define SCALE 0.125f

// ---------------- scratch (device globals; allocation-free rule) ----------------
__device__ unsigned short g_q[MTOT * DIM];     // half q16 (pre-scaled by 1/8)
__device__ unsigned short g_k[MTOT * DIM];     // half k16
__device__ unsigned short g_v[MTOT * DIM];     // half v16
__device__ unsigned short g_x16[MTOT * DIM];   // half x
__device__ unsigned short g_a16[MTOT * DIM];   // half attn out
__device__ unsigned short g_w16[4 * DIM * DIM];

// ---------------- helpers ----------------
__device__ __forceinline__ uint32_t smem_u32(const void* p) {
    uint32_t a;
    asm("{ .reg .u64 t; cvta.to.shared.u64 t, %1; cvt.u32.u64 %0, t; }" : "=r"(a) : "l"(p));
    return a;
}
__device__ __forceinline__ void cp16(uint32_t saddr, const void* g) {
    asm volatile("cp.async.cg.shared.global [%0], [%1], 16;" :: "r"(saddr), "l"(g));
}
#define CP_COMMIT() asm volatile("cp.async.commit_group;" ::: "memory")
#define CP_WAIT(n)  asm volatile("cp.async.wait_group %0;" :: "n"(n) : "memory")

__device__ __forceinline__ void ldsm4(uint32_t& r0, uint32_t& r1, uint32_t& r2, uint32_t& r3, uint32_t addr) {
    asm volatile("ldmatrix.sync.aligned.m8n8.x4.shared.b16 {%0,%1,%2,%3}, [%4];"
                 : "=r"(r0), "=r"(r1), "=r"(r2), "=r"(r3) : "r"(addr));
}
__device__ __forceinline__ void ldsm4t(uint32_t& r0, uint32_t& r1, uint32_t& r2, uint32_t& r3, uint32_t addr) {
    asm volatile("ldmatrix.sync.aligned.m8n8.x4.trans.shared.b16 {%0,%1,%2,%3}, [%4];"
                 : "=r"(r0), "=r"(r1), "=r"(r2), "=r"(r3) : "r"(addr));
}
__device__ __forceinline__ void mma_f16(float* c, const uint32_t* a, const uint32_t* b) {
    asm volatile("mma.sync.aligned.m16n8k16.row.col.f32.f16.f16.f32 "
                 "{%0,%1,%2,%3}, {%4,%5,%6,%7}, {%8,%9}, {%0,%1,%2,%3};"
                 : "+f"(c[0]), "+f"(c[1]), "+f"(c[2]), "+f"(c[3])
                 : "r"(a[0]), "r"(a[1]), "r"(a[2]), "r"(a[3]), "r"(b[0]), "r"(b[1]));
}

// ---------------- fp32 -> fp16 convert ----------------
__global__ __launch_bounds__(256) void cvt_half_kernel(
    const float4* __restrict__ src, uint2* __restrict__ dst, int n4)
{
    int i = blockIdx.x * blockDim.x + threadIdx.x;
    if (i >= n4) return;
    float4 v = src[i];
    __half2 h01 = __floats2half2_rn(v.x, v.y);
    __half2 h23 = __floats2half2_rn(v.z, v.w);
    uint2 o;
    o.x = *(uint32_t*)&h01;
    o.y = *(uint32_t*)&h23;
    dst[i] = o;
}

// ---------------- HMMA fp16 GEMM: C = A @ W^T ----------------
// CTA 256x128, BK=32, 8 warps (2x4), warp tile 128x32. 3-stage cp.async pipeline,
// single __syncthreads per k-iter. Output: half (acc*scale) or fp32.
#define T_STRIDE 80
#define A_TILE_BYTES (256 * T_STRIDE)        // 20480
#define B_TILE_BYTES (128 * T_STRIDE)        // 10240
#define STAGE2 (A_TILE_BYTES + B_TILE_BYTES) // 30720
#define GEMM_SMEM (3 * STAGE2)               // 92160

__device__ __forceinline__ void load_tileA_ca(
    const unsigned short* __restrict__ G, int row0, int k0, uint32_t stile, int tid)
{
#pragma unroll
    for (int h = 0; h < 4; ++h) {
        int idx = tid + h * 256;          // 0..1023
        int r   = idx >> 2;
        int ch  = idx & 3;
        cp16(stile + (uint32_t)(r * T_STRIDE + ch * 16),
             G + (size_t)(row0 + r) * 1024 + k0 + ch * 8);
    }
}
__device__ __forceinline__ void load_tileB_ca(
    const unsigned short* __restrict__ G, int row0, int k0, uint32_t stile, int tid)
{
#pragma unroll
    for (int h = 0; h < 2; ++h) {
        int idx = tid + h * 256;          // 0..511
        int r   = idx >> 2;
        int ch  = idx & 3;
        cp16(stile + (uint32_t)(r * T_STRIDE + ch * 16),
             G + (size_t)(row0 + r) * 1024 + k0 + ch * 8);
    }
}

__global__ __launch_bounds__(256, 1) void gemm_f16_kernel(
    const unsigned short* __restrict__ A,
    const unsigned short* __restrict__ B,
    float* __restrict__ Cf, __half* __restrict__ Ch, float scale)
{
    extern __shared__ char gsm[];
    const uint32_t sbase = smem_u32(gsm);
    const int tid  = threadIdx.x;
    const int wid  = tid >> 5;
    const int lane = tid & 31;
    const int warp_m = wid >> 2;
    const int warp_n = wid & 3;
    const int bm = blockIdx.y * 256;
    const int bn = blockIdx.x * 128;

    float acc[8][4][4];
#pragma unroll
    for (int i = 0; i < 8; ++i)
#pragma unroll
        for (int j = 0; j < 4; ++j)
#pragma unroll
            for (int e = 0; e < 4; ++e) acc[i][j][e] = 0.f;

    const int a_r = lane & 15;
    const int a_c = lane >> 4;
    const int b_r = (lane & 7) + ((lane & 16) >> 1);
    const int b_c = (lane >> 3) & 1;

    const int NIT = 1024 / 32;   // 32

#pragma unroll
    for (int s = 0; s < 2; ++s) {
        const uint32_t st = sbase + (uint32_t)s * STAGE2;
        const int k0 = s * 32;
        load_tileA_ca(A, bm, k0, st, tid);
        load_tileB_ca(B, bn, k0, st + A_TILE_BYTES, tid);
        CP_COMMIT();
    }

    int buf = 0, nbuf = 2;
    for (int it = 0; it < NIT; ++it) {
        if (it < NIT - 1) { CP_WAIT(1); } else { CP_WAIT(0); }
        __syncthreads();
        if (it + 2 < NIT) {
            const uint32_t st = sbase + (uint32_t)nbuf * STAGE2;
            const int k0 = (it + 2) * 32;
            load_tileA_ca(A, bm, k0, st, tid);
            load_tileB_ca(B, bn, k0, st + A_TILE_BYTES, tid);
            CP_COMMIT();
        }

        const uint32_t st = sbase + (uint32_t)buf * STAGE2;
        const uint32_t sA = st;
        const uint32_t sB = st + A_TILE_BYTES;

#pragma unroll
        for (int ks = 0; ks < 2; ++ks) {
            uint32_t af[8][4], bf2[4][2];
#pragma unroll
            for (int mf = 0; mf < 8; ++mf) {
                const uint32_t off = (uint32_t)((warp_m * 128 + mf * 16 + a_r) * T_STRIDE + ks * 32 + a_c * 16);
                ldsm4(af[mf][0], af[mf][1], af[mf][2], af[mf][3], sA + off);
            }
#pragma unroll
            for (int bf = 0; bf < 2; ++bf) {
                const uint32_t off = (uint32_t)((warp_n * 32 + bf * 16 + b_r) * T_STRIDE + ks * 32 + b_c * 16);
                ldsm4(bf2[2 * bf][0], bf2[2 * bf][1], bf2[2 * bf + 1][0], bf2[2 * bf + 1][1], sB + off);
            }
#pragma unroll
            for (int mf = 0; mf < 8; ++mf)
#pragma unroll
                for (int nf = 0; nf < 4; ++nf)
                    mma_f16(acc[mf][nf], af[mf], bf2[nf]);
        }

        buf = (buf + 1 == 3) ? 0 : buf + 1;
        nbuf = (nbuf + 1 == 3) ? 0 : nbuf + 1;
    }

    const int er = lane >> 2;
    const int ec = (lane & 3) * 2;
    if (Ch) {
#pragma unroll
        for (int mf = 0; mf < 8; ++mf)
#pragma unroll
            for (int nf = 0; nf < 4; ++nf) {
                const size_t row = (size_t)(bm + warp_m * 128 + mf * 16 + er);
                const int col = bn + warp_n * 32 + nf * 8 + ec;
                __half2 h01 = __floats2half2_rn(acc[mf][nf][0] * scale, acc[mf][nf][1] * scale);
                __half2 h23 = __floats2half2_rn(acc[mf][nf][2] * scale, acc[mf][nf][3] * scale);
                *(uint32_t*)&Ch[row * 1024 + col]       = *(uint32_t*)&h01;
                *(uint32_t*)&Ch[(row + 8) * 1024 + col] = *(uint32_t*)&h23;
            }
    } else {
#pragma unroll
        for (int mf = 0; mf < 8; ++mf)
#pragma unroll
            for (int nf = 0; nf < 4; ++nf) {
                const size_t row = (size_t)(bm + warp_m * 128 + mf * 16 + er);
                const int col = bn + warp_n * 32 + nf * 8 + ec;
                *(float2*)&Cf[row * 1024 + col]       = make_float2(acc[mf][nf][0], acc[mf][nf][1]);
                *(float2*)&Cf[(row + 8) * 1024 + col] = make_float2(acc[mf][nf][2], acc[mf][nf][3]);
            }
    }
}

// ---------------- fp16 HMMA flash attention (banded, causal) ----------------
// CTA per (query PAIR np, head h, batch b): 128 query rows, 8 warps x 16 rows.
// Key blocks i = 0..9, jb = 2*np - 8 + i. Warp-half wh (rows wh*64..wh*64+63)
// is active on i in [wh, wh+8]; i==wh carries the window-edge mask (row < col),
// i==wh+8 the causal mask (col <= row); the 7 middle blocks are unmasked.
// q is pre-scaled by 1/8 in the projection epilogue.
// THREE-stage cp.async K/V pipeline; smem: Q 18432 + 3 x (K 9216 + V 9216).
#define ASTR 144
#define ATTN_STAGE(s) (18432u + (uint32_t)(s) * 18432u)
#define ATTN_SMEM (18432 + 3 * 18432)   // 73728

__global__ __launch_bounds__(256, 2) void attn_hmma_kernel(
    const __half* __restrict__ qg, const __half* __restrict__ kg,
    const __half* __restrict__ vg, __half* __restrict__ aout)
{
    extern __shared__ char smb[];
    const uint32_t sb = smem_u32(smb);
    const int tid = threadIdx.x;
    const int wid = tid >> 5;
    const int lane = tid & 31;
    const int np = blockIdx.x;            // query pair index (0..31)
    const int h = blockIdx.y, b = blockIdx.z;

    const size_t qbase = ((size_t)(b * TLEN + np * 128)) * DIM + h * HD;

    // Q: 128 rows x 8 chunks = 1024 tasks
#pragma unroll
    for (int i = 0; i < 4; ++i) {
        int idx = tid + i * 256;
        int r = idx >> 3, ch = idx & 7;
        cp16(sb + (uint32_t)(r * ASTR + ch * 16), qg + qbase + (size_t)r * DIM + ch * 8);
    }
    CP_COMMIT();

    const int jb_base = 2 * np - 8;
    const int i0 = (jb_base < 0) ? -jb_base : 0;   // first i with jb >= 0 (<= 8)

    auto issue = [&](int i) {
        const int jb = jb_base + i;
        const size_t kb = ((size_t)(b * TLEN + jb * 64)) * DIM + h * HD;
        const uint32_t st = sb + ATTN_STAGE(i % 3);
#pragma unroll
        for (int t = 0; t < 2; ++t) {
            int idx = tid + t * 256;
            int r = idx >> 3, ch = idx & 7;
            cp16(st + (uint32_t)(r * ASTR + ch * 16), kg + kb + (size_t)r * DIM + ch * 8);
            cp16(st + 9216u + (uint32_t)(r * ASTR + ch * 16), vg + kb + (size_t)r * DIM + ch * 8);
        }
        CP_COMMIT();
    };

    issue(i0);
    if (i0 + 1 <= 9) issue(i0 + 1);

    const int a_r = lane & 15, a_c = lane >> 4;
    const int b_r = (lane & 7) + ((lane & 16) >> 1), b_c = (lane >> 3) & 1;
    const int er = lane >> 2, ec = 2 * (lane & 3);
    const int wh = wid >> 2;              // 0: rows 0-63, 1: rows 64-127
    const int r0 = wid * 16 + er;         // 0..127
    const int lr = r0 & 63;               // row within half (frag rows lr, lr+8)

    float m0 = -1e9f, m1 = -1e9f, l0 = 0.f, l1 = 0.f;
    float of[8][4];
#pragma unroll
    for (int nf = 0; nf < 8; ++nf)
#pragma unroll
        for (int e = 0; e < 4; ++e) of[nf][e] = 0.f;
    uint32_t qf[4][4];

    for (int i = i0; i <= 9; ++i) {
        if (i + 2 <= 9) issue(i + 2);
        if (i <= 7)      CP_WAIT(2);
        else if (i == 8) CP_WAIT(1);
        else             CP_WAIT(0);
        __syncthreads();

        if (i == i0) {
#pragma unroll
            for (int ks = 0; ks < 4; ++ks)
                ldsm4(qf[ks][0], qf[ks][1], qf[ks][2], qf[ks][3],
                      sb + (uint32_t)((wid * 16 + a_r) * ASTR + ks * 32 + a_c * 16));
        }

        const bool active = wh ? (i >= 1) : (i <= 8);
        if (active) {
            const uint32_t Kst = sb + ATTN_STAGE(i % 3);
            const uint32_t Vst = Kst + 9216u;

            // S = Q K^T (q pre-scaled)
            float sf[8][4];
#pragma unroll
            for (int nf = 0; nf < 8; ++nf)
#pragma unroll
                for (int e = 0; e < 4; ++e) sf[nf][e] = 0.f;
#pragma unroll
            for (int ks = 0; ks < 4; ++ks) {
                uint32_t kf[8][2];
#pragma unroll
                for (int bf = 0; bf < 4; ++bf)
                    ldsm4(kf[2 * bf][0], kf[2 * bf][1], kf[2 * bf + 1][0], kf[2 * bf + 1][1],
                          Kst + (uint32_t)((bf * 16 + b_r) * ASTR + ks * 32 + b_c * 16));
#pragma unroll
                for (int nf = 0; nf < 8; ++nf)
                    mma_f16(sf[nf], qf[ks], kf[nf]);
            }

            // masks: only the two band-edge blocks of this warp-half
            if (i == wh) {              // window edge: valid <=> row < col
#pragma unroll
                for (int nf = 0; nf < 8; ++nf)
#pragma unroll
                    for (int e = 0; e < 4; ++e) {
                        int row = (e < 2) ? lr : (lr + 8);
                        int c = nf * 8 + ec + (e & 1);
                        if (!(row < c)) sf[nf][e] = -1e9f;
                    }
            } else if (i == wh + 8) {   // causal: valid <=> col <= row
#pragma unroll
                for (int nf = 0; nf < 8; ++nf)
#pragma unroll
                    for (int e = 0; e < 4; ++e) {
                        int row = (e < 2) ? lr : (lr + 8);
                        int c = nf * 8 + ec + (e & 1);
                        if (!(c <= row)) sf[nf][e] = -1e9f;
                    }
            }

            // online softmax
            float mx0 = sf[0][0], mx1 = sf[0][2];
#pragma unroll
            for (int nf = 0; nf < 8; ++nf) {
                mx0 = fmaxf(mx0, fmaxf(sf[nf][0], sf[nf][1]));
                mx1 = fmaxf(mx1, fmaxf(sf[nf][2], sf[nf][3]));
            }
            mx0 = fmaxf(mx0, __shfl_xor_sync(0xffffffffu, mx0, 1));
            mx0 = fmaxf(mx0, __shfl_xor_sync(0xffffffffu, mx0, 2));
            mx1 = fmaxf(mx1, __shfl_xor_sync(0xffffffffu, mx1, 1));
            mx1 = fmaxf(mx1, __shfl_xor_sync(0xffffffffu, mx1, 2));
            float mn0 = fmaxf(m0, mx0), mn1 = fmaxf(m1, mx1);
            float cf0 = __expf(m0 - mn0), cf1 = __expf(m1 - mn1);
            m0 = mn0; m1 = mn1;

            float s0 = 0.f, s1 = 0.f;
            uint32_t pf[4][4];
#pragma unroll
            for (int nf = 0; nf < 8; ++nf) {
                float p0 = __expf(sf[nf][0] - m0);
                float p1 = __expf(sf[nf][1] - m0);
                float p2 = __expf(sf[nf][2] - m1);
                float p3 = __expf(sf[nf][3] - m1);
                s0 += p0 + p1; s1 += p2 + p3;
                __half2 h01 = __floats2half2_rn(p0, p1);
                __half2 h23 = __floats2half2_rn(p2, p3);
                pf[nf >> 1][(nf & 1) * 2 + 0] = *(uint32_t*)&h01;
                pf[nf >> 1][(nf & 1) * 2 + 1] = *(uint32_t*)&h23;
            }
            l0 = l0 * cf0 + s0; l1 = l1 * cf1 + s1;
#pragma unroll
            for (int nf = 0; nf < 8; ++nf) {
                of[nf][0] *= cf0; of[nf][1] *= cf0;
                of[nf][2] *= cf1; of[nf][3] *= cf1;
            }

            // O += P V
#pragma unroll
            for (int ks = 0; ks < 4; ++ks) {
                uint32_t vf[8][2];
#pragma unroll
                for (int nfp = 0; nfp < 4; ++nfp)
                    ldsm4t(vf[2 * nfp][0], vf[2 * nfp][1], vf[2 * nfp + 1][0], vf[2 * nfp + 1][1],
                           Vst + (uint32_t)((ks * 16 + (lane & 15)) * ASTR + (nfp * 2 + (lane >> 4)) * 16));
#pragma unroll
                for (int nf = 0; nf < 8; ++nf)
                    mma_f16(of[nf], pf[ks], vf[nf]);
            }
        }
        __syncthreads();
    }

    // finalize
    l0 += __shfl_xor_sync(0xffffffffu, l0, 1);
    l0 += __shfl_xor_sync(0xffffffffu, l0, 2);
    l1 += __shfl_xor_sync(0xffffffffu, l1, 1);
    l1 += __shfl_xor_sync(0xffffffffu, l1, 2);
    const float i0v = 1.f / l0, i1v = 1.f / l1;
    const size_t row0 = (size_t)(b * TLEN + np * 128 + r0);
    const size_t row1 = row0 + 8;
#pragma unroll
    for (int nf = 0; nf < 8; ++nf) {
        const int col = h * HD + nf * 8 + ec;
        __half2 h01 = __floats2half2_rn(of[nf][0] * i0v, of[nf][1] * i0v);
        __half2 h23 = __floats2half2_rn(of[nf][2] * i1v, of[nf][3] * i1v);
        *(uint32_t*)&aout[row0 * DIM + col] = *(uint32_t*)&h01;
        *(uint32_t*)&aout[row1 * DIM + col] = *(uint32_t*)&h23;
    }
}

// ---------------- launch ----------------
extern "C" void kernel_launch(void* const* d_in, const int* in_sizes, int n_in,
                              void* d_out, int out_size)
{
    const float* x  = (const float*)d_in[0];
    const float* Wq = (const float*)d_in[1];
    const float* Wk = (const float*)d_in[2];
    const float* Wv = (const float*)d_in[3];
    const float* Wo = (const float*)d_in[4];
    float* out = (float*)d_out;

    unsigned short *q16, *k16, *v16, *x16, *a16, *w16;
    cudaGetSymbolAddress((void**)&q16, g_q);
    cudaGetSymbolAddress((void**)&k16, g_k);
    cudaGetSymbolAddress((void**)&v16, g_v);
    cudaGetSymbolAddress((void**)&x16, g_x16);
    cudaGetSymbolAddress((void**)&a16, g_a16);
    cudaGetSymbolAddress((void**)&w16, g_w16);

    cudaFuncSetAttribute(gemm_f16_kernel, cudaFuncAttributeMaxDynamicSharedMemorySize, GEMM_SMEM);
    cudaFuncSetAttribute(attn_hmma_kernel, cudaFuncAttributeMaxDynamicSharedMemorySize, ATTN_SMEM);

    const int n4x = MTOT * DIM / 4;   // 2M
    const int n4w = DIM * DIM / 4;    // 256K

    cvt_half_kernel<<<n4x / 256, 256>>>((const float4*)x, (uint2*)x16, n4x);
    cvt_half_kernel<<<n4w / 256, 256>>>((const float4*)Wq, (uint2*)(w16 + 0 * DIM * DIM), n4w);
    cvt_half_kernel<<<n4w / 256, 256>>>((const float4*)Wk, (uint2*)(w16 + 1 * DIM * DIM), n4w);
    cvt_half_kernel<<<n4w / 256, 256>>>((const float4*)Wv, (uint2*)(w16 + 2 * DIM * DIM), n4w);
    cvt_half_kernel<<<n4w / 256, 256>>>((const float4*)Wo, (uint2*)(w16 + 3 * DIM * DIM), n4w);

    dim3 ggrid(DIM / 128, MTOT / 256);   // (8, 32)
    gemm_f16_kernel<<<ggrid, 256, GEMM_SMEM>>>(x16, w16 + 0 * DIM * DIM, nullptr, (__half*)q16, SCALE);
    gemm_f16_kernel<<<ggrid, 256, GEMM_SMEM>>>(x16, w16 + 1 * DIM * DIM, nullptr, (__half*)k16, 1.0f);
    gemm_f16_kernel<<<ggrid, 256, GEMM_SMEM>>>(x16, w16 + 2 * DIM * DIM, nullptr, (__half*)v16, 1.0f);

    dim3 agrid(TLEN / 128, NHEAD, BATCH);   // (32, 16, 2)
    attn_hmma_kernel<<<agrid, 256, ATTN_SMEM>>>((const __half*)q16, (const __half*)k16, (const __half*)v16, (__half*)a16);

    gemm_f16_kernel<<<ggrid, 256, GEMM_SMEM>>>(a16, w16 + 3 * DIM * DIM, out, nullptr, 1.0f);
}

// round 13
// speedup vs baseline: 6.5400x; 1.0340x over previous
#include <cuda_runtime.h>
#include <cuda_fp16.h>
#include <cstdint>

// Problem constants: B=2, T=4096, D=1024, H=16, hd=64, WIN=512, BS=64
#define DIM   1024
#define HD    64
#define NHEAD 16
#define TLEN  4096
#define BATCH 2
#define MTOT  (BATCH * TLEN)      // 8192
#define SCALE 0.125f
#define QSTR  3072                // qkv row stride

// ---------------- scratch (device globals; allocation-free rule) ----------------
__device__ unsigned short g_qkv[MTOT * QSTR];  // half q|k|v, row stride 3072
__device__ unsigned short g_x16[MTOT * DIM];   // half x
__device__ unsigned short g_a16[MTOT * DIM];   // half attn out
__device__ unsigned short g_w16[4 * DIM * DIM]; // Wq|Wk|Wv|Wo fp16

// ---------------- helpers ----------------
__device__ __forceinline__ uint32_t smem_u32(const void* p) {
    uint32_t a;
    asm("{ .reg .u64 t; cvta.to.shared.u64 t, %1; cvt.u32.u64 %0, t; }" : "=r"(a) : "l"(p));
    return a;
}
__device__ __forceinline__ void cp16(uint32_t saddr, const void* g) {
    asm volatile("cp.async.cg.shared.global [%0], [%1], 16;" :: "r"(saddr), "l"(g));
}
#define CP_COMMIT() asm volatile("cp.async.commit_group;" ::: "memory")
#define CP_WAIT(n)  asm volatile("cp.async.wait_group %0;" :: "n"(n) : "memory")

__device__ __forceinline__ void ldsm4(uint32_t& r0, uint32_t& r1, uint32_t& r2, uint32_t& r3, uint32_t addr) {
    asm volatile("ldmatrix.sync.aligned.m8n8.x4.shared.b16 {%0,%1,%2,%3}, [%4];"
                 : "=r"(r0), "=r"(r1), "=r"(r2), "=r"(r3) : "r"(addr));
}
__device__ __forceinline__ void ldsm4t(uint32_t& r0, uint32_t& r1, uint32_t& r2, uint32_t& r3, uint32_t addr) {
    asm volatile("ldmatrix.sync.aligned.m8n8.x4.trans.shared.b16 {%0,%1,%2,%3}, [%4];"
                 : "=r"(r0), "=r"(r1), "=r"(r2), "=r"(r3) : "r"(addr));
}
__device__ __forceinline__ void mma_f16(float* c, const uint32_t* a, const uint32_t* b) {
    asm volatile("mma.sync.aligned.m16n8k16.row.col.f32.f16.f16.f32 "
                 "{%0,%1,%2,%3}, {%4,%5,%6,%7}, {%8,%9}, {%0,%1,%2,%3};"
                 : "+f"(c[0]), "+f"(c[1]), "+f"(c[2]), "+f"(c[3])
                 : "r"(a[0]), "r"(a[1]), "r"(a[2]), "r"(a[3]), "r"(b[0]), "r"(b[1]));
}

// ---------------- fused fp32 -> fp16 convert: x + all 4 weights ----------------
#define N4X (MTOT * DIM / 4)      // 2097152
#define N4W (DIM * DIM / 4)       // 262144 = 2^18
__global__ __launch_bounds__(256) void cvt_all_kernel(
    const float4* __restrict__ x,
    const float4* __restrict__ wq, const float4* __restrict__ wk,
    const float4* __restrict__ wv, const float4* __restrict__ wo,
    uint2* __restrict__ x16, uint2* __restrict__ w16)
{
    int i = blockIdx.x * blockDim.x + threadIdx.x;
    const float4* src;
    uint2* dst;
    if (i < N4X) {
        src = x + i; dst = x16 + i;
    } else {
        int j = i - N4X;
        int w = j >> 18;              // 0..3
        int p = j & (N4W - 1);
        const float4* ws = (w == 0) ? wq : (w == 1) ? wk : (w == 2) ? wv : wo;
        src = ws + p;
        dst = w16 + (size_t)w * N4W + p;
    }
    float4 v = *src;
    __half2 h01 = __floats2half2_rn(v.x, v.y);
    __half2 h23 = __floats2half2_rn(v.z, v.w);
    uint2 o;
    o.x = *(uint32_t*)&h01;
    o.y = *(uint32_t*)&h23;
    *dst = o;
}

// ---------------- HMMA fp16 GEMM: C[M,N] = A @ W^T ----------------
// CTA 256x128, BK=32, 8 warps (4M x 2N), warp tile 64x64. 3-stage cp.async,
// single __syncthreads per k-iter. Epilogue: half (cols<q_cols scaled) or fp32.
#define T_STRIDE 80
#define A_TILE_BYTES (256 * T_STRIDE)        // 20480
#define B_TILE_BYTES (128 * T_STRIDE)        // 10240
#define STAGE2 (A_TILE_BYTES + B_TILE_BYTES) // 30720
#define GEMM_SMEM (3 * STAGE2)               // 92160

__device__ __forceinline__ void load_tileA_ca(
    const unsigned short* __restrict__ G, int row0, int k0, uint32_t stile, int tid)
{
#pragma unroll
    for (int h = 0; h < 4; ++h) {
        int idx = tid + h * 256;          // 0..1023
        int r   = idx >> 2;
        int ch  = idx & 3;
        cp16(stile + (uint32_t)(r * T_STRIDE + ch * 16),
             G + (size_t)(row0 + r) * 1024 + k0 + ch * 8);
    }
}
__device__ __forceinline__ void load_tileB_ca(
    const unsigned short* __restrict__ G, int row0, int k0, uint32_t stile, int tid)
{
#pragma unroll
    for (int h = 0; h < 2; ++h) {
        int idx = tid + h * 256;          // 0..511
        int r   = idx >> 2;
        int ch  = idx & 3;
        cp16(stile + (uint32_t)(r * T_STRIDE + ch * 16),
             G + (size_t)(row0 + r) * 1024 + k0 + ch * 8);
    }
}

__global__ __launch_bounds__(256, 1) void gemm_f16_kernel(
    const unsigned short* __restrict__ A,
    const unsigned short* __restrict__ B,
    float* __restrict__ Cf, __half* __restrict__ Ch, int ldc, int q_cols)
{
    extern __shared__ char gsm[];
    const uint32_t sbase = smem_u32(gsm);
    const int tid  = threadIdx.x;
    const int wid  = tid >> 5;
    const int lane = tid & 31;
    const int warp_m = wid >> 1;          // 0..3 -> rows warp_m*64
    const int warp_n = wid & 1;           // 0..1 -> cols warp_n*64
    const int bm = blockIdx.y * 256;
    const int bn = blockIdx.x * 128;

    float acc[4][8][4];
#pragma unroll
    for (int i = 0; i < 4; ++i)
#pragma unroll
        for (int j = 0; j < 8; ++j)
#pragma unroll
            for (int e = 0; e < 4; ++e) acc[i][j][e] = 0.f;

    const int a_r = lane & 15;
    const int a_c = lane >> 4;
    const int b_r = (lane & 7) + ((lane & 16) >> 1);
    const int b_c = (lane >> 3) & 1;

    const int NIT = 1024 / 32;   // 32

#pragma unroll
    for (int s = 0; s < 2; ++s) {
        const uint32_t st = sbase + (uint32_t)s * STAGE2;
        const int k0 = s * 32;
        load_tileA_ca(A, bm, k0, st, tid);
        load_tileB_ca(B, bn, k0, st + A_TILE_BYTES, tid);
        CP_COMMIT();
    }

    int buf = 0, nbuf = 2;
    for (int it = 0; it < NIT; ++it) {
        if (it < NIT - 1) { CP_WAIT(1); } else { CP_WAIT(0); }
        __syncthreads();
        // issue stage it+2 into (it+2)%3 = (it-1)%3 — all warps past compute(it-1).
        if (it + 2 < NIT) {
            const uint32_t st = sbase + (uint32_t)nbuf * STAGE2;
            const int k0 = (it + 2) * 32;
            load_tileA_ca(A, bm, k0, st, tid);
            load_tileB_ca(B, bn, k0, st + A_TILE_BYTES, tid);
            CP_COMMIT();
        }

        const uint32_t st = sbase + (uint32_t)buf * STAGE2;
        const uint32_t sA = st;
        const uint32_t sB = st + A_TILE_BYTES;

#pragma unroll
        for (int ks = 0; ks < 2; ++ks) {
            uint32_t af[4][4], bf2[8][2];
#pragma unroll
            for (int mf = 0; mf < 4; ++mf) {
                const uint32_t off = (uint32_t)((warp_m * 64 + mf * 16 + a_r) * T_STRIDE + ks * 32 + a_c * 16);
                ldsm4(af[mf][0], af[mf][1], af[mf][2], af[mf][3], sA + off);
            }
#pragma unroll
            for (int bf = 0; bf < 4; ++bf) {
                const uint32_t off = (uint32_t)((warp_n * 64 + bf * 16 + b_r) * T_STRIDE + ks * 32 + b_c * 16);
                ldsm4(bf2[2 * bf][0], bf2[2 * bf][1], bf2[2 * bf + 1][0], bf2[2 * bf + 1][1], sB + off);
            }
#pragma unroll
            for (int mf = 0; mf < 4; ++mf)
#pragma unroll
                for (int nf = 0; nf < 8; ++nf)
                    mma_f16(acc[mf][nf], af[mf], bf2[nf]);
        }

        buf = (buf + 1 == 3) ? 0 : buf + 1;
        nbuf = (nbuf + 1 == 3) ? 0 : nbuf + 1;
    }

    const int er = lane >> 2;
    const int ec = (lane & 3) * 2;
    if (Ch) {
        const float s = (bn < q_cols) ? SCALE : 1.0f;
#pragma unroll
        for (int mf = 0; mf < 4; ++mf)
#pragma unroll
            for (int nf = 0; nf < 8; ++nf) {
                const size_t row = (size_t)(bm + warp_m * 64 + mf * 16 + er);
                const int col = bn + warp_n * 64 + nf * 8 + ec;
                __half2 h01 = __floats2half2_rn(acc[mf][nf][0] * s, acc[mf][nf][1] * s);
                __half2 h23 = __floats2half2_rn(acc[mf][nf][2] * s, acc[mf][nf][3] * s);
                *(uint32_t*)&Ch[row * ldc + col]       = *(uint32_t*)&h01;
                *(uint32_t*)&Ch[(row + 8) * ldc + col] = *(uint32_t*)&h23;
            }
    } else {
#pragma unroll
        for (int mf = 0; mf < 4; ++mf)
#pragma unroll
            for (int nf = 0; nf < 8; ++nf) {
                const size_t row = (size_t)(bm + warp_m * 64 + mf * 16 + er);
                const int col = bn + warp_n * 64 + nf * 8 + ec;
                *(float2*)&Cf[row * ldc + col]       = make_float2(acc[mf][nf][0], acc[mf][nf][1]);
                *(float2*)&Cf[(row + 8) * ldc + col] = make_float2(acc[mf][nf][2], acc[mf][nf][3]);
            }
    }
}

// ---------------- fp16 HMMA flash attention (banded, causal) ----------------
// Same structure as round 12 (passing); q/k/v now read from the strided qkv
// buffer (row stride QSTR=3072). q pre-scaled by 1/8 in the GEMM epilogue.
#define ASTR 144
#define ATTN_STAGE(s) (18432u + (uint32_t)(s) * 18432u)
#define ATTN_SMEM (18432 + 3 * 18432)   // 73728

__global__ __launch_bounds__(256, 2) void attn_hmma_kernel(
    const __half* __restrict__ qkv, __half* __restrict__ aout)
{
    extern __shared__ char smb[];
    const uint32_t sb = smem_u32(smb);
    const int tid = threadIdx.x;
    const int wid = tid >> 5;
    const int lane = tid & 31;
    const int np = blockIdx.x;            // query pair index (0..31)
    const int h = blockIdx.y, b = blockIdx.z;

    const __half* qg = qkv;               // col 0
    const __half* kg = qkv + 1024;
    const __half* vg = qkv + 2048;

    const size_t qbase = ((size_t)(b * TLEN + np * 128)) * QSTR + h * HD;

    // Q: 128 rows x 8 chunks = 1024 tasks
#pragma unroll
    for (int i = 0; i < 4; ++i) {
        int idx = tid + i * 256;
        int r = idx >> 3, ch = idx & 7;
        cp16(sb + (uint32_t)(r * ASTR + ch * 16), qg + qbase + (size_t)r * QSTR + ch * 8);
    }
    CP_COMMIT();

    const int jb_base = 2 * np - 8;
    const int i0 = (jb_base < 0) ? -jb_base : 0;

    auto issue = [&](int i) {
        const int jb = jb_base + i;
        const size_t kb = ((size_t)(b * TLEN + jb * 64)) * QSTR + h * HD;
        const uint32_t st = sb + ATTN_STAGE(i % 3);
#pragma unroll
        for (int t = 0; t < 2; ++t) {
            int idx = tid + t * 256;
            int r = idx >> 3, ch = idx & 7;
            cp16(st + (uint32_t)(r * ASTR + ch * 16), kg + kb + (size_t)r * QSTR + ch * 8);
            cp16(st + 9216u + (uint32_t)(r * ASTR + ch * 16), vg + kb + (size_t)r * QSTR + ch * 8);
        }
        CP_COMMIT();
    };

    issue(i0);
    if (i0 + 1 <= 9) issue(i0 + 1);

    const int a_r = lane & 15, a_c = lane >> 4;
    const int b_r = (lane & 7) + ((lane & 16) >> 1), b_c = (lane >> 3) & 1;
    const int er = lane >> 2, ec = 2 * (lane & 3);
    const int wh = wid >> 2;
    const int r0 = wid * 16 + er;
    const int lr = r0 & 63;

    float m0 = -1e9f, m1 = -1e9f, l0 = 0.f, l1 = 0.f;
    float of[8][4];
#pragma unroll
    for (int nf = 0; nf < 8; ++nf)
#pragma unroll
        for (int e = 0; e < 4; ++e) of[nf][e] = 0.f;
    uint32_t qf[4][4];

    for (int i = i0; i <= 9; ++i) {
        if (i + 2 <= 9) issue(i + 2);
        if (i <= 7)      CP_WAIT(2);
        else if (i == 8) CP_WAIT(1);
        else             CP_WAIT(0);
        __syncthreads();

        if (i == i0) {
#pragma unroll
            for (int ks = 0; ks < 4; ++ks)
                ldsm4(qf[ks][0], qf[ks][1], qf[ks][2], qf[ks][3],
                      sb + (uint32_t)((wid * 16 + a_r) * ASTR + ks * 32 + a_c * 16));
        }

        const bool active = wh ? (i >= 1) : (i <= 8);
        if (active) {
            const uint32_t Kst = sb + ATTN_STAGE(i % 3);
            const uint32_t Vst = Kst + 9216u;

            float sf[8][4];
#pragma unroll
            for (int nf = 0; nf < 8; ++nf)
#pragma unroll
                for (int e = 0; e < 4; ++e) sf[nf][e] = 0.f;
#pragma unroll
            for (int ks = 0; ks < 4; ++ks) {
                uint32_t kf[8][2];
#pragma unroll
                for (int bf = 0; bf < 4; ++bf)
                    ldsm4(kf[2 * bf][0], kf[2 * bf][1], kf[2 * bf + 1][0], kf[2 * bf + 1][1],
                          Kst + (uint32_t)((bf * 16 + b_r) * ASTR + ks * 32 + b_c * 16));
#pragma unroll
                for (int nf = 0; nf < 8; ++nf)
                    mma_f16(sf[nf], qf[ks], kf[nf]);
            }

            if (i == wh) {              // window edge: valid <=> row < col
#pragma unroll
                for (int nf = 0; nf < 8; ++nf)
#pragma unroll
                    for (int e = 0; e < 4; ++e) {
                        int row = (e < 2) ? lr : (lr + 8);
                        int c = nf * 8 + ec + (e & 1);
                        if (!(row < c)) sf[nf][e] = -1e9f;
                    }
            } else if (i == wh + 8) {   // causal: valid <=> col <= row
#pragma unroll
                for (int nf = 0; nf < 8; ++nf)
#pragma unroll
                    for (int e = 0; e < 4; ++e) {
                        int row = (e < 2) ? lr : (lr + 8);
                        int c = nf * 8 + ec + (e & 1);
                        if (!(c <= row)) sf[nf][e] = -1e9f;
                    }
            }

            float mx0 = sf[0][0], mx1 = sf[0][2];
#pragma unroll
            for (int nf = 0; nf < 8; ++nf) {
                mx0 = fmaxf(mx0, fmaxf(sf[nf][0], sf[nf][1]));
                mx1 = fmaxf(mx1, fmaxf(sf[nf][2], sf[nf][3]));
            }
            mx0 = fmaxf(mx0, __shfl_xor_sync(0xffffffffu, mx0, 1));
            mx0 = fmaxf(mx0, __shfl_xor_sync(0xffffffffu, mx0, 2));
            mx1 = fmaxf(mx1, __shfl_xor_sync(0xffffffffu, mx1, 1));
            mx1 = fmaxf(mx1, __shfl_xor_sync(0xffffffffu, mx1, 2));
            float mn0 = fmaxf(m0, mx0), mn1 = fmaxf(m1, mx1);
            float cf0 = __expf(m0 - mn0), cf1 = __expf(m1 - mn1);
            m0 = mn0; m1 = mn1;

            float s0 = 0.f, s1 = 0.f;
            uint32_t pf[4][4];
#pragma unroll
            for (int nf = 0; nf < 8; ++nf) {
                float p0 = __expf(sf[nf][0] - m0);
                float p1 = __expf(sf[nf][1] - m0);
                float p2 = __expf(sf[nf][2] - m1);
                float p3 = __expf(sf[nf][3] - m1);
                s0 += p0 + p1; s1 += p2 + p3;
                __half2 h01 = __floats2half2_rn(p0, p1);
                __half2 h23 = __floats2half2_rn(p2, p3);
                pf[nf >> 1][(nf & 1) * 2 + 0] = *(uint32_t*)&h01;
                pf[nf >> 1][(nf & 1) * 2 + 1] = *(uint32_t*)&h23;
            }
            l0 = l0 * cf0 + s0; l1 = l1 * cf1 + s1;
#pragma unroll
            for (int nf = 0; nf < 8; ++nf) {
                of[nf][0] *= cf0; of[nf][1] *= cf0;
                of[nf][2] *= cf1; of[nf][3] *= cf1;
            }

#pragma unroll
            for (int ks = 0; ks < 4; ++ks) {
                uint32_t vf[8][2];
#pragma unroll
                for (int nfp = 0; nfp < 4; ++nfp)
                    ldsm4t(vf[2 * nfp][0], vf[2 * nfp][1], vf[2 * nfp + 1][0], vf[2 * nfp + 1][1],
                           Vst + (uint32_t)((ks * 16 + (lane & 15)) * ASTR + (nfp * 2 + (lane >> 4)) * 16));
#pragma unroll
                for (int nf = 0; nf < 8; ++nf)
                    mma_f16(of[nf], pf[ks], vf[nf]);
            }
        }
        __syncthreads();
    }

    l0 += __shfl_xor_sync(0xffffffffu, l0, 1);
    l0 += __shfl_xor_sync(0xffffffffu, l0, 2);
    l1 += __shfl_xor_sync(0xffffffffu, l1, 1);
    l1 += __shfl_xor_sync(0xffffffffu, l1, 2);
    const float i0v = 1.f / l0, i1v = 1.f / l1;
    const size_t row0 = (size_t)(b * TLEN + np * 128 + r0);
    const size_t row1 = row0 + 8;
#pragma unroll
    for (int nf = 0; nf < 8; ++nf) {
        const int col = h * HD + nf * 8 + ec;
        __half2 h01 = __floats2half2_rn(of[nf][0] * i0v, of[nf][1] * i0v);
        __half2 h23 = __floats2half2_rn(of[nf][2] * i1v, of[nf][3] * i1v);
        *(uint32_t*)&aout[row0 * DIM + col] = *(uint32_t*)&h01;
        *(uint32_t*)&aout[row1 * DIM + col] = *(uint32_t*)&h23;
    }
}

// ---------------- launch ----------------
extern "C" void kernel_launch(void* const* d_in, const int* in_sizes, int n_in,
                              void* d_out, int out_size)
{
    const float* x  = (const float*)d_in[0];
    const float* Wq = (const float*)d_in[1];
    const float* Wk = (const float*)d_in[2];
    const float* Wv = (const float*)d_in[3];
    const float* Wo = (const float*)d_in[4];
    float* out = (float*)d_out;

    unsigned short *qkv, *x16, *a16, *w16;
    cudaGetSymbolAddress((void**)&qkv, g_qkv);
    cudaGetSymbolAddress((void**)&x16, g_x16);
    cudaGetSymbolAddress((void**)&a16, g_a16);
    cudaGetSymbolAddress((void**)&w16, g_w16);

    cudaFuncSetAttribute(gemm_f16_kernel, cudaFuncAttributeMaxDynamicSharedMemorySize, GEMM_SMEM);
    cudaFuncSetAttribute(attn_hmma_kernel, cudaFuncAttributeMaxDynamicSharedMemorySize, ATTN_SMEM);

    // fused converts: x + Wq/Wk/Wv/Wo
    const int total4 = N4X + 4 * N4W;    // 3145728
    cvt_all_kernel<<<total4 / 256, 256>>>(
        (const float4*)x, (const float4*)Wq, (const float4*)Wk,
        (const float4*)Wv, (const float4*)Wo, (uint2*)x16, (uint2*)w16);

    // fused QKV projection: C[8192,3072] = x @ [Wq|Wk|Wv]^T (q cols pre-scaled)
    dim3 qkvgrid(QSTR / 128, MTOT / 256);   // (24, 32)
    gemm_f16_kernel<<<qkvgrid, 256, GEMM_SMEM>>>(x16, w16, nullptr, (__half*)qkv, QSTR, 1024);

    dim3 agrid(TLEN / 128, NHEAD, BATCH);   // (32, 16, 2)
    attn_hmma_kernel<<<agrid, 256, ATTN_SMEM>>>((const __half*)qkv, (__half*)a16);

    dim3 ogrid(DIM / 128, MTOT / 256);      // (8, 32)
    gemm_f16_kernel<<<ogrid, 256, GEMM_SMEM>>>(a16, w16 + 3 * DIM * DIM, out, nullptr, DIM, 0);
}

// round 15
// speedup vs baseline: 6.5741x; 1.0052x over previous
#include <cuda_runtime.h>
#include <cuda_fp16.h>
#include <cstdint>

// Problem constants: B=2, T=4096, D=1024, H=16, hd=64, WIN=512, BS=64
#define DIM   1024
#define HD    64
#define NHEAD 16
#define TLEN  4096
#define BATCH 2
#define MTOT  (BATCH * TLEN)      // 8192
#define SCALE 0.125f
#define QSTR  3072                // qkv row stride

// ---------------- scratch (device globals; allocation-free rule) ----------------
__device__ unsigned short g_qkv[MTOT * QSTR];  // half q|k|v, row stride 3072
__device__ unsigned short g_x16[MTOT * DIM];   // half x
__device__ unsigned short g_a16[MTOT * DIM];   // half attn out
__device__ unsigned short g_w16[4 * DIM * DIM]; // Wq|Wk|Wv|Wo fp16

// ---------------- helpers ----------------
__device__ __forceinline__ uint32_t smem_u32(const void* p) {
    uint32_t a;
    asm("{ .reg .u64 t; cvta.to.shared.u64 t, %1; cvt.u32.u64 %0, t; }" : "=r"(a) : "l"(p));
    return a;
}
__device__ __forceinline__ void cp16(uint32_t saddr, const void* g) {
    asm volatile("cp.async.cg.shared.global [%0], [%1], 16;" :: "r"(saddr), "l"(g));
}
#define CP_COMMIT() asm volatile("cp.async.commit_group;" ::: "memory")
#define CP_WAIT(n)  asm volatile("cp.async.wait_group %0;" :: "n"(n) : "memory")

__device__ __forceinline__ void ldsm4(uint32_t& r0, uint32_t& r1, uint32_t& r2, uint32_t& r3, uint32_t addr) {
    asm volatile("ldmatrix.sync.aligned.m8n8.x4.shared.b16 {%0,%1,%2,%3}, [%4];"
                 : "=r"(r0), "=r"(r1), "=r"(r2), "=r"(r3) : "r"(addr));
}
__device__ __forceinline__ void ldsm4t(uint32_t& r0, uint32_t& r1, uint32_t& r2, uint32_t& r3, uint32_t addr) {
    asm volatile("ldmatrix.sync.aligned.m8n8.x4.trans.shared.b16 {%0,%1,%2,%3}, [%4];"
                 : "=r"(r0), "=r"(r1), "=r"(r2), "=r"(r3) : "r"(addr));
}
__device__ __forceinline__ void mma_f16(float* c, const uint32_t* a, const uint32_t* b) {
    asm volatile("mma.sync.aligned.m16n8k16.row.col.f32.f16.f16.f32 "
                 "{%0,%1,%2,%3}, {%4,%5,%6,%7}, {%8,%9}, {%0,%1,%2,%3};"
                 : "+f"(c[0]), "+f"(c[1]), "+f"(c[2]), "+f"(c[3])
                 : "r"(a[0]), "r"(a[1]), "r"(a[2]), "r"(a[3]), "r"(b[0]), "r"(b[1]));
}

// ---------------- fused fp32 -> fp16 convert: x + all 4 weights ----------------
#define N4X (MTOT * DIM / 4)      // 2097152
#define N4W (DIM * DIM / 4)       // 262144 = 2^18
__global__ __launch_bounds__(256) void cvt_all_kernel(
    const float4* __restrict__ x,
    const float4* __restrict__ wq, const float4* __restrict__ wk,
    const float4* __restrict__ wv, const float4* __restrict__ wo,
    uint2* __restrict__ x16, uint2* __restrict__ w16)
{
    int i = blockIdx.x * blockDim.x + threadIdx.x;
    const float4* src;
    uint2* dst;
    if (i < N4X) {
        src = x + i; dst = x16 + i;
    } else {
        int j = i - N4X;
        int w = j >> 18;              // 0..3
        int p = j & (N4W - 1);
        const float4* ws = (w == 0) ? wq : (w == 1) ? wk : (w == 2) ? wv : wo;
        src = ws + p;
        dst = w16 + (size_t)w * N4W + p;
    }
    float4 v = *src;
    __half2 h01 = __floats2half2_rn(v.x, v.y);
    __half2 h23 = __floats2half2_rn(v.z, v.w);
    uint2 o;
    o.x = *(uint32_t*)&h01;
    o.y = *(uint32_t*)&h23;
    *dst = o;
}

// ---------------- HMMA fp16 GEMM: C[M,N] = A @ W^T ----------------
// CTA 256x128, BK=32, 512 threads = 16 warps (4M x 4N), warp tile 64x32.
// 3-stage cp.async, single __syncthreads per k-iter.
// acc = 64 regs/thread -> ~105 total -> 16 warps resident (4/SMSP).
#define T_STRIDE 80
#define A_TILE_BYTES (256 * T_STRIDE)        // 20480
#define B_TILE_BYTES (128 * T_STRIDE)        // 10240
#define STAGE2 (A_TILE_BYTES + B_TILE_BYTES) // 30720
#define GEMM_SMEM (3 * STAGE2)               // 92160

__device__ __forceinline__ void load_tileA_ca(
    const unsigned short* __restrict__ G, int row0, int k0, uint32_t stile, int tid)
{
#pragma unroll
    for (int h = 0; h < 2; ++h) {
        int idx = tid + h * 512;          // 0..1023
        int r   = idx >> 2;
        int ch  = idx & 3;
        cp16(stile + (uint32_t)(r * T_STRIDE + ch * 16),
             G + (size_t)(row0 + r) * 1024 + k0 + ch * 8);
    }
}
__device__ __forceinline__ void load_tileB_ca(
    const unsigned short* __restrict__ G, int row0, int k0, uint32_t stile, int tid)
{
    // 512 tasks, 512 threads
    int r  = tid >> 2;
    int ch = tid & 3;
    cp16(stile + (uint32_t)(r * T_STRIDE + ch * 16),
         G + (size_t)(row0 + r) * 1024 + k0 + ch * 8);
}

__global__ __launch_bounds__(512, 1) void gemm_f16_kernel(
    const unsigned short* __restrict__ A,
    const unsigned short* __restrict__ B,
    float* __restrict__ Cf, __half* __restrict__ Ch, int ldc, int q_cols)
{
    extern __shared__ char gsm[];
    const uint32_t sbase = smem_u32(gsm);
    const int tid  = threadIdx.x;
    const int wid  = tid >> 5;
    const int lane = tid & 31;
    const int warp_m = wid >> 2;          // 0..3 -> rows warp_m*64
    const int warp_n = wid & 3;           // 0..3 -> cols warp_n*32
    const int bm = blockIdx.y * 256;
    const int bn = blockIdx.x * 128;

    float acc[4][4][4];
#pragma unroll
    for (int i = 0; i < 4; ++i)
#pragma unroll
        for (int j = 0; j < 4; ++j)
#pragma unroll
            for (int e = 0; e < 4; ++e) acc[i][j][e] = 0.f;

    const int a_r = lane & 15;
    const int a_c = lane >> 4;
    const int b_r = (lane & 7) + ((lane & 16) >> 1);
    const int b_c = (lane >> 3) & 1;

    const int NIT = 1024 / 32;   // 32

#pragma unroll
    for (int s = 0; s < 2; ++s) {
        const uint32_t st = sbase + (uint32_t)s * STAGE2;
        const int k0 = s * 32;
        load_tileA_ca(A, bm, k0, st, tid);
        load_tileB_ca(B, bn, k0, st + A_TILE_BYTES, tid);
        CP_COMMIT();
    }

    int buf = 0, nbuf = 2;
    for (int it = 0; it < NIT; ++it) {
        if (it < NIT - 1) { CP_WAIT(1); } else { CP_WAIT(0); }
        __syncthreads();
        // issue stage it+2 into (it+2)%3 = (it-1)%3 — all warps past compute(it-1).
        if (it + 2 < NIT) {
            const uint32_t st = sbase + (uint32_t)nbuf * STAGE2;
            const int k0 = (it + 2) * 32;
            load_tileA_ca(A, bm, k0, st, tid);
            load_tileB_ca(B, bn, k0, st + A_TILE_BYTES, tid);
            CP_COMMIT();
        }

        const uint32_t st = sbase + (uint32_t)buf * STAGE2;
        const uint32_t sA = st;
        const uint32_t sB = st + A_TILE_BYTES;

#pragma unroll
        for (int ks = 0; ks < 2; ++ks) {
            uint32_t af[4][4], bf2[4][2];
#pragma unroll
            for (int mf = 0; mf < 4; ++mf) {
                const uint32_t off = (uint32_t)((warp_m * 64 + mf * 16 + a_r) * T_STRIDE + ks * 32 + a_c * 16);
                ldsm4(af[mf][0], af[mf][1], af[mf][2], af[mf][3], sA + off);
            }
#pragma unroll
            for (int bf = 0; bf < 2; ++bf) {
                const uint32_t off = (uint32_t)((warp_n * 32 + bf * 16 + b_r) * T_STRIDE + ks * 32 + b_c * 16);
                ldsm4(bf2[2 * bf][0], bf2[2 * bf][1], bf2[2 * bf + 1][0], bf2[2 * bf + 1][1], sB + off);
            }
#pragma unroll
            for (int mf = 0; mf < 4; ++mf)
#pragma unroll
                for (int nf = 0; nf < 4; ++nf)
                    mma_f16(acc[mf][nf], af[mf], bf2[nf]);
        }

        buf = (buf + 1 == 3) ? 0 : buf + 1;
        nbuf = (nbuf + 1 == 3) ? 0 : nbuf + 1;
    }

    const int er = lane >> 2;
    const int ec = (lane & 3) * 2;
    if (Ch) {
        const float s = (bn < q_cols) ? SCALE : 1.0f;
#pragma unroll
        for (int mf = 0; mf < 4; ++mf)
#pragma unroll
            for (int nf = 0; nf < 4; ++nf) {
                const size_t row = (size_t)(bm + warp_m * 64 + mf * 16 + er);
                const int col = bn + warp_n * 32 + nf * 8 + ec;
                __half2 h01 = __floats2half2_rn(acc[mf][nf][0] * s, acc[mf][nf][1] * s);
                __half2 h23 = __floats2half2_rn(acc[mf][nf][2] * s, acc[mf][nf][3] * s);
                *(uint32_t*)&Ch[row * ldc + col]       = *(uint32_t*)&h01;
                *(uint32_t*)&Ch[(row + 8) * ldc + col] = *(uint32_t*)&h23;
            }
    } else {
#pragma unroll
        for (int mf = 0; mf < 4; ++mf)
#pragma unroll
            for (int nf = 0; nf < 4; ++nf) {
                const size_t row = (size_t)(bm + warp_m * 64 + mf * 16 + er);
                const int col = bn + warp_n * 32 + nf * 8 + ec;
                *(float2*)&Cf[row * ldc + col]       = make_float2(acc[mf][nf][0], acc[mf][nf][1]);
                *(float2*)&Cf[(row + 8) * ldc + col] = make_float2(acc[mf][nf][2], acc[mf][nf][3]);
            }
    }
}

// ---------------- fp16 HMMA flash attention (banded, causal) ----------------
// Unchanged from round 13 (passing). qkv row stride QSTR; q pre-scaled by 1/8.
#define ASTR 144
#define ATTN_STAGE(s) (18432u + (uint32_t)(s) * 18432u)
#define ATTN_SMEM (18432 + 3 * 18432)   // 73728

__global__ __launch_bounds__(256, 2) void attn_hmma_kernel(
    const __half* __restrict__ qkv, __half* __restrict__ aout)
{
    extern __shared__ char smb[];
    const uint32_t sb = smem_u32(smb);
    const int tid = threadIdx.x;
    const int wid = tid >> 5;
    const int lane = tid & 31;
    const int np = blockIdx.x;
    const int h = blockIdx.y, b = blockIdx.z;

    const __half* qg = qkv;
    const __half* kg = qkv + 1024;
    const __half* vg = qkv + 2048;

    const size_t qbase = ((size_t)(b * TLEN + np * 128)) * QSTR + h * HD;

#pragma unroll
    for (int i = 0; i < 4; ++i) {
        int idx = tid + i * 256;
        int r = idx >> 3, ch = idx & 7;
        cp16(sb + (uint32_t)(r * ASTR + ch * 16), qg + qbase + (size_t)r * QSTR + ch * 8);
    }
    CP_COMMIT();

    const int jb_base = 2 * np - 8;
    const int i0 = (jb_base < 0) ? -jb_base : 0;

    auto issue = [&](int i) {
        const int jb = jb_base + i;
        const size_t kb = ((size_t)(b * TLEN + jb * 64)) * QSTR + h * HD;
        const uint32_t st = sb + ATTN_STAGE(i % 3);
#pragma unroll
        for (int t = 0; t < 2; ++t) {
            int idx = tid + t * 256;
            int r = idx >> 3, ch = idx & 7;
            cp16(st + (uint32_t)(r * ASTR + ch * 16), kg + kb + (size_t)r * QSTR + ch * 8);
            cp16(st + 9216u + (uint32_t)(r * ASTR + ch * 16), vg + kb + (size_t)r * QSTR + ch * 8);
        }
        CP_COMMIT();
    };

    issue(i0);
    if (i0 + 1 <= 9) issue(i0 + 1);

    const int a_r = lane & 15, a_c = lane >> 4;
    const int b_r = (lane & 7) + ((lane & 16) >> 1), b_c = (lane >> 3) & 1;
    const int er = lane >> 2, ec = 2 * (lane & 3);
    const int wh = wid >> 2;
    const int r0 = wid * 16 + er;
    const int lr = r0 & 63;

    float m0 = -1e9f, m1 = -1e9f, l0 = 0.f, l1 = 0.f;
    float of[8][4];
#pragma unroll
    for (int nf = 0; nf < 8; ++nf)
#pragma unroll
        for (int e = 0; e < 4; ++e) of[nf][e] = 0.f;
    uint32_t qf[4][4];

    for (int i = i0; i <= 9; ++i) {
        if (i + 2 <= 9) issue(i + 2);
        if (i <= 7)      CP_WAIT(2);
        else if (i == 8) CP_WAIT(1);
        else             CP_WAIT(0);
        __syncthreads();

        if (i == i0) {
#pragma unroll
            for (int ks = 0; ks < 4; ++ks)
                ldsm4(qf[ks][0], qf[ks][1], qf[ks][2], qf[ks][3],
                      sb + (uint32_t)((wid * 16 + a_r) * ASTR + ks * 32 + a_c * 16));
        }

        const bool active = wh ? (i >= 1) : (i <= 8);
        if (active) {
            const uint32_t Kst = sb + ATTN_STAGE(i % 3);
            const uint32_t Vst = Kst + 9216u;

            float sf[8][4];
#pragma unroll
            for (int nf = 0; nf < 8; ++nf)
#pragma unroll
                for (int e = 0; e < 4; ++e) sf[nf][e] = 0.f;
#pragma unroll
            for (int ks = 0; ks < 4; ++ks) {
                uint32_t kf[8][2];
#pragma unroll
                for (int bf = 0; bf < 4; ++bf)
                    ldsm4(kf[2 * bf][0], kf[2 * bf][1], kf[2 * bf + 1][0], kf[2 * bf + 1][1],
                          Kst + (uint32_t)((bf * 16 + b_r) * ASTR + ks * 32 + b_c * 16));
#pragma unroll
                for (int nf = 0; nf < 8; ++nf)
                    mma_f16(sf[nf], qf[ks], kf[nf]);
            }

            if (i == wh) {              // window edge: valid <=> row < col
#pragma unroll
                for (int nf = 0; nf < 8; ++nf)
#pragma unroll
                    for (int e = 0; e < 4; ++e) {
                        int row = (e < 2) ? lr : (lr + 8);
                        int c = nf * 8 + ec + (e & 1);
                        if (!(row < c)) sf[nf][e] = -1e9f;
                    }
            } else if (i == wh + 8) {   // causal: valid <=> col <= row
#pragma unroll
                for (int nf = 0; nf < 8; ++nf)
#pragma unroll
                    for (int e = 0; e < 4; ++e) {
                        int row = (e < 2) ? lr : (lr + 8);
                        int c = nf * 8 + ec + (e & 1);
                        if (!(c <= row)) sf[nf][e] = -1e9f;
                    }
            }

            float mx0 = sf[0][0], mx1 = sf[0][2];
#pragma unroll
            for (int nf = 0; nf < 8; ++nf) {
                mx0 = fmaxf(mx0, fmaxf(sf[nf][0], sf[nf][1]));
                mx1 = fmaxf(mx1, fmaxf(sf[nf][2], sf[nf][3]));
            }
            mx0 = fmaxf(mx0, __shfl_xor_sync(0xffffffffu, mx0, 1));
            mx0 = fmaxf(mx0, __shfl_xor_sync(0xffffffffu, mx0, 2));
            mx1 = fmaxf(mx1, __shfl_xor_sync(0xffffffffu, mx1, 1));
            mx1 = fmaxf(mx1, __shfl_xor_sync(0xffffffffu, mx1, 2));
            float mn0 = fmaxf(m0, mx0), mn1 = fmaxf(m1, mx1);
            float cf0 = __expf(m0 - mn0), cf1 = __expf(m1 - mn1);
            m0 = mn0; m1 = mn1;

            float s0 = 0.f, s1 = 0.f;
            uint32_t pf[4][4];
#pragma unroll
            for (int nf = 0; nf < 8; ++nf) {
                float p0 = __expf(sf[nf][0] - m0);
                float p1 = __expf(sf[nf][1] - m0);
                float p2 = __expf(sf[nf][2] - m1);
                float p3 = __expf(sf[nf][3] - m1);
                s0 += p0 + p1; s1 += p2 + p3;
                __half2 h01 = __floats2half2_rn(p0, p1);
                __half2 h23 = __floats2half2_rn(p2, p3);
                pf[nf >> 1][(nf & 1) * 2 + 0] = *(uint32_t*)&h01;
                pf[nf >> 1][(nf & 1) * 2 + 1] = *(uint32_t*)&h23;
            }
            l0 = l0 * cf0 + s0; l1 = l1 * cf1 + s1;
#pragma unroll
            for (int nf = 0; nf < 8; ++nf) {
                of[nf][0] *= cf0; of[nf][1] *= cf0;
                of[nf][2] *= cf1; of[nf][3] *= cf1;
            }

#pragma unroll
            for (int ks = 0; ks < 4; ++ks) {
                uint32_t vf[8][2];
#pragma unroll
                for (int nfp = 0; nfp < 4; ++nfp)
                    ldsm4t(vf[2 * nfp][0], vf[2 * nfp][1], vf[2 * nfp + 1][0], vf[2 * nfp + 1][1],
                           Vst + (uint32_t)((ks * 16 + (lane & 15)) * ASTR + (nfp * 2 + (lane >> 4)) * 16));
#pragma unroll
                for (int nf = 0; nf < 8; ++nf)
                    mma_f16(of[nf], pf[ks], vf[nf]);
            }
        }
        __syncthreads();
    }

    l0 += __shfl_xor_sync(0xffffffffu, l0, 1);
    l0 += __shfl_xor_sync(0xffffffffu, l0, 2);
    l1 += __shfl_xor_sync(0xffffffffu, l1, 1);
    l1 += __shfl_xor_sync(0xffffffffu, l1, 2);
    const float i0v = 1.f / l0, i1v = 1.f / l1;
    const size_t row0 = (size_t)(b * TLEN + np * 128 + r0);
    const size_t row1 = row0 + 8;
#pragma unroll
    for (int nf = 0; nf < 8; ++nf) {
        const int col = h * HD + nf * 8 + ec;
        __half2 h01 = __floats2half2_rn(of[nf][0] * i0v, of[nf][1] * i0v);
        __half2 h23 = __floats2half2_rn(of[nf][2] * i1v, of[nf][3] * i1v);
        *(uint32_t*)&aout[row0 * DIM + col] = *(uint32_t*)&h01;
        *(uint32_t*)&aout[row1 * DIM + col] = *(uint32_t*)&h23;
    }
}

// ---------------- launch ----------------
extern "C" void kernel_launch(void* const* d_in, const int* in_sizes, int n_in,
                              void* d_out, int out_size)
{
    const float* x  = (const float*)d_in[0];
    const float* Wq = (const float*)d_in[1];
    const float* Wk = (const float*)d_in[2];
    const float* Wv = (const float*)d_in[3];
    const float* Wo = (const float*)d_in[4];
    float* out = (float*)d_out;

    unsigned short *qkv, *x16, *a16, *w16;
    cudaGetSymbolAddress((void**)&qkv, g_qkv);
    cudaGetSymbolAddress((void**)&x16, g_x16);
    cudaGetSymbolAddress((void**)&a16, g_a16);
    cudaGetSymbolAddress((void**)&w16, g_w16);

    cudaFuncSetAttribute(gemm_f16_kernel, cudaFuncAttributeMaxDynamicSharedMemorySize, GEMM_SMEM);
    cudaFuncSetAttribute(attn_hmma_kernel, cudaFuncAttributeMaxDynamicSharedMemorySize, ATTN_SMEM);

    // fused converts: x + Wq/Wk/Wv/Wo
    const int total4 = N4X + 4 * N4W;    // 3145728
    cvt_all_kernel<<<total4 / 256, 256>>>(
        (const float4*)x, (const float4*)Wq, (const float4*)Wk,
        (const float4*)Wv, (const float4*)Wo, (uint2*)x16, (uint2*)w16);

    // fused QKV projection: C[8192,3072] = x @ [Wq|Wk|Wv]^T (q cols pre-scaled)
    dim3 qkvgrid(QSTR / 128, MTOT / 256);   // (24, 32)
    gemm_f16_kernel<<<qkvgrid, 512, GEMM_SMEM>>>(x16, w16, nullptr, (__half*)qkv, QSTR, 1024);

    dim3 agrid(TLEN / 128, NHEAD, BATCH);   // (32, 16, 2)
    attn_hmma_kernel<<<agrid, 256, ATTN_SMEM>>>((const __half*)qkv, (__half*)a16);

    dim3 ogrid(DIM / 128, MTOT / 256);      // (8, 32)
    gemm_f16_kernel<<<ogrid, 512, GEMM_SMEM>>>(a16, w16 + 3 * DIM * DIM, out, nullptr, DIM, 0);
}

// round 16
// speedup vs baseline: 6.7165x; 1.0217x over previous
#include <cuda_runtime.h>
#include <cuda_fp16.h>
#include <cstdint>

// Problem constants: B=2, T=4096, D=1024, H=16, hd=64, WIN=512, BS=64
#define DIM   1024
#define HD    64
#define NHEAD 16
#define TLEN  4096
#define BATCH 2
#define MTOT  (BATCH * TLEN)      // 8192
#define QSCALE 0.18033688f        // (1/8) * log2(e): softmax runs in exp2 domain
#define QSTR  3072                // qkv row stride

// ---------------- scratch (device globals; allocation-free rule) ----------------
__device__ unsigned short g_qkv[MTOT * QSTR];  // half q|k|v, row stride 3072
__device__ unsigned short g_x16[MTOT * DIM];   // half x
__device__ unsigned short g_a16[MTOT * DIM];   // half attn out
__device__ unsigned short g_w16[4 * DIM * DIM]; // Wq|Wk|Wv|Wo fp16

// ---------------- helpers ----------------
__device__ __forceinline__ uint32_t smem_u32(const void* p) {
    uint32_t a;
    asm("{ .reg .u64 t; cvta.to.shared.u64 t, %1; cvt.u32.u64 %0, t; }" : "=r"(a) : "l"(p));
    return a;
}
__device__ __forceinline__ void cp16(uint32_t saddr, const void* g) {
    asm volatile("cp.async.cg.shared.global [%0], [%1], 16;" :: "r"(saddr), "l"(g));
}
#define CP_COMMIT() asm volatile("cp.async.commit_group;" ::: "memory")
#define CP_WAIT(n)  asm volatile("cp.async.wait_group %0;" :: "n"(n) : "memory")

__device__ __forceinline__ void ldsm4(uint32_t& r0, uint32_t& r1, uint32_t& r2, uint32_t& r3, uint32_t addr) {
    asm volatile("ldmatrix.sync.aligned.m8n8.x4.shared.b16 {%0,%1,%2,%3}, [%4];"
                 : "=r"(r0), "=r"(r1), "=r"(r2), "=r"(r3) : "r"(addr));
}
__device__ __forceinline__ void ldsm4t(uint32_t& r0, uint32_t& r1, uint32_t& r2, uint32_t& r3, uint32_t addr) {
    asm volatile("ldmatrix.sync.aligned.m8n8.x4.trans.shared.b16 {%0,%1,%2,%3}, [%4];"
                 : "=r"(r0), "=r"(r1), "=r"(r2), "=r"(r3) : "r"(addr));
}
__device__ __forceinline__ void mma_f16(float* c, const uint32_t* a, const uint32_t* b) {
    asm volatile("mma.sync.aligned.m16n8k16.row.col.f32.f16.f16.f32 "
                 "{%0,%1,%2,%3}, {%4,%5,%6,%7}, {%8,%9}, {%0,%1,%2,%3};"
                 : "+f"(c[0]), "+f"(c[1]), "+f"(c[2]), "+f"(c[3])
                 : "r"(a[0]), "r"(a[1]), "r"(a[2]), "r"(a[3]), "r"(b[0]), "r"(b[1]));
}

// ---------------- fused fp32 -> fp16 convert: x + all 4 weights ----------------
#define N4X (MTOT * DIM / 4)      // 2097152
#define N4W (DIM * DIM / 4)       // 262144 = 2^18
__global__ __launch_bounds__(256) void cvt_all_kernel(
    const float4* __restrict__ x,
    const float4* __restrict__ wq, const float4* __restrict__ wk,
    const float4* __restrict__ wv, const float4* __restrict__ wo,
    uint2* __restrict__ x16, uint2* __restrict__ w16)
{
    int i = blockIdx.x * blockDim.x + threadIdx.x;
    const float4* src;
    uint2* dst;
    if (i < N4X) {
        src = x + i; dst = x16 + i;
    } else {
        int j = i - N4X;
        int w = j >> 18;              // 0..3
        int p = j & (N4W - 1);
        const float4* ws = (w == 0) ? wq : (w == 1) ? wk : (w == 2) ? wv : wo;
        src = ws + p;
        dst = w16 + (size_t)w * N4W + p;
    }
    float4 v = *src;
    __half2 h01 = __floats2half2_rn(v.x, v.y);
    __half2 h23 = __floats2half2_rn(v.z, v.w);
    uint2 o;
    o.x = *(uint32_t*)&h01;
    o.y = *(uint32_t*)&h23;
    *dst = o;
}

// ---------------- HMMA fp16 GEMM: C[M,N] = A @ W^T (templated M-tile) ----------------
// CTA MTxN128, BK=32, warp tile 64x32 (MT/64 x 4 warp grid), 3-stage cp.async,
// single __syncthreads per k-iter. MT=256: 512 thr, 1 CTA/SM. MT=128: 256 thr, 2 CTA/SM.
#define T_STRIDE 80
#define B_TILE_BYTES (128 * T_STRIDE)        // 10240

template<int MT, int NTHR>
__global__ __launch_bounds__(NTHR, (MT == 128) ? 2 : 1) void gemm_f16_kernel(
    const unsigned short* __restrict__ A,
    const unsigned short* __restrict__ B,
    float* __restrict__ Cf, __half* __restrict__ Ch, int ldc, int q_cols)
{
    constexpr int A_TILE = MT * T_STRIDE;
    constexpr int STAGE = A_TILE + B_TILE_BYTES;

    extern __shared__ char gsm[];
    const uint32_t sbase = smem_u32(gsm);
    const int tid  = threadIdx.x;
    const int wid  = tid >> 5;
    const int lane = tid & 31;
    const int warp_m = wid >> 2;          // rows warp_m*64
    const int warp_n = wid & 3;           // cols warp_n*32
    const int bm = blockIdx.y * MT;
    const int bn = blockIdx.x * 128;

    float acc[4][4][4];
#pragma unroll
    for (int i = 0; i < 4; ++i)
#pragma unroll
        for (int j = 0; j < 4; ++j)
#pragma unroll
            for (int e = 0; e < 4; ++e) acc[i][j][e] = 0.f;

    const int a_r = lane & 15;
    const int a_c = lane >> 4;
    const int b_r = (lane & 7) + ((lane & 16) >> 1);
    const int b_c = (lane >> 3) & 1;

    auto load_stage = [&](int k0, uint32_t st) {
        // A: MT rows x 4 chunks
#pragma unroll
        for (int h = 0; h < MT * 4 / NTHR; ++h) {
            int idx = tid + h * NTHR;
            int r   = idx >> 2;
            int ch  = idx & 3;
            cp16(st + (uint32_t)(r * T_STRIDE + ch * 16),
                 A + (size_t)(bm + r) * 1024 + k0 + ch * 8);
        }
        // B: 128 rows x 4 chunks = 512 tasks
#pragma unroll
        for (int h = 0; h < 512 / NTHR; ++h) {
            int idx = tid + h * NTHR;
            int r   = idx >> 2;
            int ch  = idx & 3;
            cp16(st + (uint32_t)A_TILE + (uint32_t)(r * T_STRIDE + ch * 16),
                 B + (size_t)(bn + r) * 1024 + k0 + ch * 8);
        }
        CP_COMMIT();
    };

    const int NIT = 1024 / 32;   // 32

#pragma unroll
    for (int s = 0; s < 2; ++s)
        load_stage(s * 32, sbase + (uint32_t)s * STAGE);

    int buf = 0, nbuf = 2;
    for (int it = 0; it < NIT; ++it) {
        if (it < NIT - 1) { CP_WAIT(1); } else { CP_WAIT(0); }
        __syncthreads();
        if (it + 2 < NIT)
            load_stage((it + 2) * 32, sbase + (uint32_t)nbuf * STAGE);

        const uint32_t st = sbase + (uint32_t)buf * STAGE;
        const uint32_t sA = st;
        const uint32_t sB = st + A_TILE;

#pragma unroll
        for (int ks = 0; ks < 2; ++ks) {
            uint32_t af[4][4], bf2[4][2];
#pragma unroll
            for (int mf = 0; mf < 4; ++mf) {
                const uint32_t off = (uint32_t)((warp_m * 64 + mf * 16 + a_r) * T_STRIDE + ks * 32 + a_c * 16);
                ldsm4(af[mf][0], af[mf][1], af[mf][2], af[mf][3], sA + off);
            }
#pragma unroll
            for (int bf = 0; bf < 2; ++bf) {
                const uint32_t off = (uint32_t)((warp_n * 32 + bf * 16 + b_r) * T_STRIDE + ks * 32 + b_c * 16);
                ldsm4(bf2[2 * bf][0], bf2[2 * bf][1], bf2[2 * bf + 1][0], bf2[2 * bf + 1][1], sB + off);
            }
#pragma unroll
            for (int mf = 0; mf < 4; ++mf)
#pragma unroll
                for (int nf = 0; nf < 4; ++nf)
                    mma_f16(acc[mf][nf], af[mf], bf2[nf]);
        }

        buf = (buf + 1 == 3) ? 0 : buf + 1;
        nbuf = (nbuf + 1 == 3) ? 0 : nbuf + 1;
    }

    const int er = lane >> 2;
    const int ec = (lane & 3) * 2;
    if (Ch) {
        const float s = (bn < q_cols) ? QSCALE : 1.0f;
#pragma unroll
        for (int mf = 0; mf < 4; ++mf)
#pragma unroll
            for (int nf = 0; nf < 4; ++nf) {
                const size_t row = (size_t)(bm + warp_m * 64 + mf * 16 + er);
                const int col = bn + warp_n * 32 + nf * 8 + ec;
                __half2 h01 = __floats2half2_rn(acc[mf][nf][0] * s, acc[mf][nf][1] * s);
                __half2 h23 = __floats2half2_rn(acc[mf][nf][2] * s, acc[mf][nf][3] * s);
                *(uint32_t*)&Ch[row * ldc + col]       = *(uint32_t*)&h01;
                *(uint32_t*)&Ch[(row + 8) * ldc + col] = *(uint32_t*)&h23;
            }
    } else {
#pragma unroll
        for (int mf = 0; mf < 4; ++mf)
#pragma unroll
            for (int nf = 0; nf < 4; ++nf) {
                const size_t row = (size_t)(bm + warp_m * 64 + mf * 16 + er);
                const int col = bn + warp_n * 32 + nf * 8 + ec;
                *(float2*)&Cf[row * ldc + col]       = make_float2(acc[mf][nf][0], acc[mf][nf][1]);
                *(float2*)&Cf[(row + 8) * ldc + col] = make_float2(acc[mf][nf][2], acc[mf][nf][3]);
            }
    }
}

// ---------------- fp16 HMMA flash attention (banded, causal, exp2 domain) ----------------
// CTA per (query PAIR np, head h, batch b): 128 query rows, 8 warps x 16 rows.
// q pre-scaled by (1/8)*log2(e): softmax uses exp2f (bare MUFU ex2).
// Single __syncthreads per iter: wait -> sync -> issue(i+2) -> compute.
// The top sync at iter i means all warps finished compute(i-1), so issue(i+2)
// overwriting buffer (i+2)%3 == (i-1)%3 is WAR-safe (same invariant as the GEMM).
#define ASTR 144
#define ATTN_STAGE(s) (18432u + (uint32_t)(s) * 18432u)
#define ATTN_SMEM (18432 + 3 * 18432)   // 73728

__global__ __launch_bounds__(256, 2) void attn_hmma_kernel(
    const __half* __restrict__ qkv, __half* __restrict__ aout)
{
    extern __shared__ char smb[];
    const uint32_t sb = smem_u32(smb);
    const int tid = threadIdx.x;
    const int wid = tid >> 5;
    const int lane = tid & 31;
    const int np = blockIdx.x;
    const int h = blockIdx.y, b = blockIdx.z;

    const __half* qg = qkv;
    const __half* kg = qkv + 1024;
    const __half* vg = qkv + 2048;

    const size_t qbase = ((size_t)(b * TLEN + np * 128)) * QSTR + h * HD;

#pragma unroll
    for (int i = 0; i < 4; ++i) {
        int idx = tid + i * 256;
        int r = idx >> 3, ch = idx & 7;
        cp16(sb + (uint32_t)(r * ASTR + ch * 16), qg + qbase + (size_t)r * QSTR + ch * 8);
    }
    CP_COMMIT();

    const int jb_base = 2 * np - 8;
    const int i0 = (jb_base < 0) ? -jb_base : 0;

    auto issue = [&](int i) {
        const int jb = jb_base + i;
        const size_t kb = ((size_t)(b * TLEN + jb * 64)) * QSTR + h * HD;
        const uint32_t st = sb + ATTN_STAGE(i % 3);
#pragma unroll
        for (int t = 0; t < 2; ++t) {
            int idx = tid + t * 256;
            int r = idx >> 3, ch = idx & 7;
            cp16(st + (uint32_t)(r * ASTR + ch * 16), kg + kb + (size_t)r * QSTR + ch * 8);
            cp16(st + 9216u + (uint32_t)(r * ASTR + ch * 16), vg + kb + (size_t)r * QSTR + ch * 8);
        }
        CP_COMMIT();
    };

    issue(i0);
    if (i0 + 1 <= 9) issue(i0 + 1);

    const int a_r = lane & 15, a_c = lane >> 4;
    const int b_r = (lane & 7) + ((lane & 16) >> 1), b_c = (lane >> 3) & 1;
    const int er = lane >> 2, ec = 2 * (lane & 3);
    const int wh = wid >> 2;
    const int r0 = wid * 16 + er;
    const int lr = r0 & 63;

    float m0 = -1e9f, m1 = -1e9f, l0 = 0.f, l1 = 0.f;
    float of[8][4];
#pragma unroll
    for (int nf = 0; nf < 8; ++nf)
#pragma unroll
        for (int e = 0; e < 4; ++e) of[nf][e] = 0.f;
    uint32_t qf[4][4];

    for (int i = i0; i <= 9; ++i) {
        if (i < 9) { CP_WAIT(1); } else { CP_WAIT(0); }
        __syncthreads();
        if (i + 2 <= 9) issue(i + 2);

        if (i == i0) {
#pragma unroll
            for (int ks = 0; ks < 4; ++ks)
                ldsm4(qf[ks][0], qf[ks][1], qf[ks][2], qf[ks][3],
                      sb + (uint32_t)((wid * 16 + a_r) * ASTR + ks * 32 + a_c * 16));
        }

        const bool active = wh ? (i >= 1) : (i <= 8);
        if (active) {
            const uint32_t Kst = sb + ATTN_STAGE(i % 3);
            const uint32_t Vst = Kst + 9216u;

            float sf[8][4];
#pragma unroll
            for (int nf = 0; nf < 8; ++nf)
#pragma unroll
                for (int e = 0; e < 4; ++e) sf[nf][e] = 0.f;
#pragma unroll
            for (int ks = 0; ks < 4; ++ks) {
                uint32_t kf[8][2];
#pragma unroll
                for (int bf = 0; bf < 4; ++bf)
                    ldsm4(kf[2 * bf][0], kf[2 * bf][1], kf[2 * bf + 1][0], kf[2 * bf + 1][1],
                          Kst + (uint32_t)((bf * 16 + b_r) * ASTR + ks * 32 + b_c * 16));
#pragma unroll
                for (int nf = 0; nf < 8; ++nf)
                    mma_f16(sf[nf], qf[ks], kf[nf]);
            }

            if (i == wh) {              // window edge: valid <=> row < col
#pragma unroll
                for (int nf = 0; nf < 8; ++nf)
#pragma unroll
                    for (int e = 0; e < 4; ++e) {
                        int row = (e < 2) ? lr : (lr + 8);
                        int c = nf * 8 + ec + (e & 1);
                        if (!(row < c)) sf[nf][e] = -1e9f;
                    }
            } else if (i == wh + 8) {   // causal: valid <=> col <= row
#pragma unroll
                for (int nf = 0; nf < 8; ++nf)
#pragma unroll
                    for (int e = 0; e < 4; ++e) {
                        int row = (e < 2) ? lr : (lr + 8);
                        int c = nf * 8 + ec + (e & 1);
                        if (!(c <= row)) sf[nf][e] = -1e9f;
                    }
            }

            float mx0 = sf[0][0], mx1 = sf[0][2];
#pragma unroll
            for (int nf = 0; nf < 8; ++nf) {
                mx0 = fmaxf(mx0, fmaxf(sf[nf][0], sf[nf][1]));
                mx1 = fmaxf(mx1, fmaxf(sf[nf][2], sf[nf][3]));
            }
            mx0 = fmaxf(mx0, __shfl_xor_sync(0xffffffffu, mx0, 1));
            mx0 = fmaxf(mx0, __shfl_xor_sync(0xffffffffu, mx0, 2));
            mx1 = fmaxf(mx1, __shfl_xor_sync(0xffffffffu, mx1, 1));
            mx1 = fmaxf(mx1, __shfl_xor_sync(0xffffffffu, mx1, 2));
            float mn0 = fmaxf(m0, mx0), mn1 = fmaxf(m1, mx1);
            float cf0 = exp2f(m0 - mn0), cf1 = exp2f(m1 - mn1);
            m0 = mn0; m1 = mn1;

            float s0 = 0.f, s1 = 0.f;
            uint32_t pf[4][4];
#pragma unroll
            for (int nf = 0; nf < 8; ++nf) {
                float p0 = exp2f(sf[nf][0] - m0);
                float p1 = exp2f(sf[nf][1] - m0);
                float p2 = exp2f(sf[nf][2] - m1);
                float p3 = exp2f(sf[nf][3] - m1);
                s0 += p0 + p1; s1 += p2 + p3;
                __half2 h01 = __floats2half2_rn(p0, p1);
                __half2 h23 = __floats2half2_rn(p2, p3);
                pf[nf >> 1][(nf & 1) * 2 + 0] = *(uint32_t*)&h01;
                pf[nf >> 1][(nf & 1) * 2 + 1] = *(uint32_t*)&h23;
            }
            l0 = l0 * cf0 + s0; l1 = l1 * cf1 + s1;
#pragma unroll
            for (int nf = 0; nf < 8; ++nf) {
                of[nf][0] *= cf0; of[nf][1] *= cf0;
                of[nf][2] *= cf1; of[nf][3] *= cf1;
            }

#pragma unroll
            for (int ks = 0; ks < 4; ++ks) {
                uint32_t vf[8][2];
#pragma unroll
                for (int nfp = 0; nfp < 4; ++nfp)
                    ldsm4t(vf[2 * nfp][0], vf[2 * nfp][1], vf[2 * nfp + 1][0], vf[2 * nfp + 1][1],
                           Vst + (uint32_t)((ks * 16 + (lane & 15)) * ASTR + (nfp * 2 + (lane >> 4)) * 16));
#pragma unroll
                for (int nf = 0; nf < 8; ++nf)
                    mma_f16(of[nf], pf[ks], vf[nf]);
            }
        }
    }

    l0 += __shfl_xor_sync(0xffffffffu, l0, 1);
    l0 += __shfl_xor_sync(0xffffffffu, l0, 2);
    l1 += __shfl_xor_sync(0xffffffffu, l1, 1);
    l1 += __shfl_xor_sync(0xffffffffu, l1, 2);
    const float i0v = 1.f / l0, i1v = 1.f / l1;
    const size_t row0 = (size_t)(b * TLEN + np * 128 + r0);
    const size_t row1 = row0 + 8;
#pragma unroll
    for (int nf = 0; nf < 8; ++nf) {
        const int col = h * HD + nf * 8 + ec;
        __half2 h01 = __floats2half2_rn(of[nf][0] * i0v, of[nf][1] * i0v);
        __half2 h23 = __floats2half2_rn(of[nf][2] * i1v, of[nf][3] * i1v);
        *(uint32_t*)&aout[row0 * DIM + col] = *(uint32_t*)&h01;
        *(uint32_t*)&aout[row1 * DIM + col] = *(uint32_t*)&h23;
    }
}

// ---------------- launch ----------------
extern "C" void kernel_launch(void* const* d_in, const int* in_sizes, int n_in,
                              void* d_out, int out_size)
{
    const float* x  = (const float*)d_in[0];
    const float* Wq = (const float*)d_in[1];
    const float* Wk = (const float*)d_in[2];
    const float* Wv = (const float*)d_in[3];
    const float* Wo = (const float*)d_in[4];
    float* out = (float*)d_out;

    unsigned short *qkv, *x16, *a16, *w16;
    cudaGetSymbolAddress((void**)&qkv, g_qkv);
    cudaGetSymbolAddress((void**)&x16, g_x16);
    cudaGetSymbolAddress((void**)&a16, g_a16);
    cudaGetSymbolAddress((void**)&w16, g_w16);

    const int SM256 = 3 * (256 * T_STRIDE + B_TILE_BYTES);   // 92160
    const int SM128 = 3 * (128 * T_STRIDE + B_TILE_BYTES);   // 61440
    cudaFuncSetAttribute(gemm_f16_kernel<256, 512>, cudaFuncAttributeMaxDynamicSharedMemorySize, SM256);
    cudaFuncSetAttribute(gemm_f16_kernel<128, 256>, cudaFuncAttributeMaxDynamicSharedMemorySize, SM128);
    cudaFuncSetAttribute(attn_hmma_kernel, cudaFuncAttributeMaxDynamicSharedMemorySize, ATTN_SMEM);

    // fused converts: x + Wq/Wk/Wv/Wo
    const int total4 = N4X + 4 * N4W;    // 3145728
    cvt_all_kernel<<<total4 / 256, 256>>>(
        (const float4*)x, (const float4*)Wq, (const float4*)Wk,
        (const float4*)Wv, (const float4*)Wo, (uint2*)x16, (uint2*)w16);

    // fused QKV projection: C[8192,3072] = x @ [Wq|Wk|Wv]^T (q cols scaled by (1/8)log2e)
    dim3 qkvgrid(QSTR / 128, MTOT / 256);   // (24, 32)
    gemm_f16_kernel<256, 512><<<qkvgrid, 512, SM256>>>(x16, w16, nullptr, (__half*)qkv, QSTR, 1024);

    dim3 agrid(TLEN / 128, NHEAD, BATCH);   // (32, 16, 2)
    attn_hmma_kernel<<<agrid, 256, ATTN_SMEM>>>((const __half*)qkv, (__half*)a16);

    // output projection with 128-row CTA tile (512 CTAs -> finer wave granularity)
    dim3 ogrid(DIM / 128, MTOT / 128);      // (8, 64)
    gemm_f16_kernel<128, 256><<<ogrid, 256, SM128>>>(a16, w16 + 3 * DIM * DIM, out, nullptr, DIM, 0);
}